// round 7
// baseline (speedup 1.0000x reference)
#include <cuda_runtime.h>
#include <cuda_fp16.h>
#include <math.h>

typedef unsigned long long ull;

#define Ntot 8192
#define KC   32
#define PC   64
#define FEATC 455
#define FSC   457
#define THREADS 512

// ---- shared memory layout (float offsets) ----
#define OFF_WD    0                        // 455*64 = 29120 (fp32 weights)
#define OFF_W1    29120                    // 64*128 = 8192
#define OFF_R     37312                    // reused: features half2[32][457] = 14624 fl  OR  W2(8192)+H(4128)
#define OFF_W2    (OFF_R)                  // 128*64 = 8192
#define OFF_H     (OFF_R + 8192)           // 32*129 half2 = 4128 fl-words
#define OFF_P0    (OFF_R + 14624)          // 32*66 = 2112 (n0 partials; later pairH half2[32][65])
#define OFF_P1    (OFF_P0 + 2112)          // 32*66 = 2112 (n1 partials)
#define OFF_PJ    (OFF_P1 + 2112)          // [b][32][16] = 1024
#define OFF_POSN  (OFF_PJ + 1024)          // [b][16] = 32
#define OFF_RN    (OFF_POSN + 32)          // [b][12] = 24
#define OFF_SJ    (OFF_RN + 24)            // [b][32] ints = 64
#define OFF_SREL  (OFF_SJ + 64)            // 64
#define OFF_SSAME (OFF_SREL + 64)          // 64
#define OFF_SPM   (OFF_SSAME + 64)         // 64
#define SMEMF     (OFF_SPM + 64)           // 57496 floats = 229984 B

// ---- packed f32x2 helpers ----
#define FMA2(d, a, b, c) asm("fma.rn.f32x2 %0, %1, %2, %3;" : "=l"(d) : "l"(a), "l"(b), "l"(c))
#define ADD2(d, a, b)    asm("add.rn.f32x2 %0, %1, %2;"     : "=l"(d) : "l"(a), "l"(b))
#define PK2(r, x)        asm("mov.b64 %0, {%1, %1};"        : "=l"(r) : "f"(x))
#define PK2D(r, x, y)    asm("mov.b64 %0, {%1, %2};"        : "=l"(r) : "f"(x), "f"(y))
#define UPK2(lo, hi, v)  asm("mov.b64 {%0, %1}, %2;"        : "=f"(lo), "=f"(hi) : "l"(v))

// ---------------- RBF: 16 bins, 3 exps, fp16 output at stride-2 halfs ----------------
__device__ __forceinline__ void rbf16h(float d, __half* out2) {
    const float SI = 0.72727272727f;   // 16/22
    const float G  = 1.06666666667f;   // 16/15
    const float Q  = 0.10273954f;      // exp(-2*G*G)
    float g = d * SI;
    int m = __float2int_rn(g * 0.9375f);
    m = m < 0 ? 0 : (m > 15 ? 15 : m);
    float u = g - (float)m * G;
    float peak = __expf(-u * u);
    float r = __expf(G * (2.0f * u - G));
    float s = __expf(-G * (2.0f * u + G));
    out2[2 * m] = __float2half(peak);
    float v = peak;
#pragma unroll
    for (int st = 1; st <= 15; ++st) {
        v *= r; r *= Q;
        int i = m + st;
        if (i <= 15) out2[2 * i] = __float2half(v);
    }
    v = peak;
#pragma unroll
    for (int st = 1; st <= 15; ++st) {
        v *= s; s *= Q;
        int i = m - st;
        if (i >= 0) out2[2 * i] = __float2half(v);
    }
}

__device__ __forceinline__ void frames_from(const float* p,
                                            float e1[3], float e2[3], float e3[3], float t[3]) {
    t[0] = p[3]; t[1] = p[4]; t[2] = p[5];
    float v1x = p[6] - t[0], v1y = p[7] - t[1], v1z = p[8] - t[2];
    float v2x = p[0] - t[0], v2y = p[1] - t[1], v2z = p[2] - t[2];
    float n1 = sqrtf(v1x * v1x + v1y * v1y + v1z * v1z) + 1e-6f;
    e1[0] = v1x / n1; e1[1] = v1y / n1; e1[2] = v1z / n1;
    float dt = v2x * e1[0] + v2y * e1[1] + v2z * e1[2];
    float ux = v2x - dt * e1[0], uy = v2y - dt * e1[1], uz = v2z - dt * e1[2];
    float n2 = sqrtf(ux * ux + uy * uy + uz * uz) + 1e-6f;
    e2[0] = ux / n2; e2[1] = uy / n2; e2[2] = uz / n2;
    e3[0] = e1[1] * e2[2] - e1[2] * e2[1];
    e3[1] = e1[2] * e2[0] - e1[0] * e2[2];
    e3[2] = e1[0] * e2[1] - e1[1] * e2[0];
}

__device__ __forceinline__ float gelu_f(float x) {
    float c = 0.7978845608028654f * (x + 0.044715f * x * x * x);
    float t;
    asm("tanh.approx.f32 %0, %1;" : "=f"(t) : "f"(c));
    return 0.5f * x * (1.0f + t);
}

__global__ void __launch_bounds__(THREADS, 1)
dsd_kernel(const float* __restrict__ pos, const float* __restrict__ dmap,
           const int* __restrict__ nbrs, const int* __restrict__ resi,
           const int* __restrict__ chain, const int* __restrict__ batch,
           const float* __restrict__ maskp,
           const float* __restrict__ Wrel, const float* __restrict__ Wdmap,
           const float* __restrict__ Wdist, const float* __restrict__ Wdir,
           const float* __restrict__ Wrot, const float* __restrict__ Wvec,
           const float* __restrict__ lng, const float* __restrict__ lnb,
           const float* __restrict__ W1, const float* __restrict__ b1,
           const float* __restrict__ W2, const float* __restrict__ b2,
           float* __restrict__ outPair, float* __restrict__ outMask)
{
    extern __shared__ float sm[];
    const int tid = threadIdx.x;
    const int k   = tid & 31;         // lane = neighbor slot
    const int wid = tid >> 5;         // warp id (0..15)
    const int pg  = wid & 7;          // p-group (8 cols each)
    const int fh  = wid >> 3;         // feature half (0..1)
    const int lkk = tid >> 4;         // LN: k
    const int ls  = tid & 15;         // LN: col quad
    const int g   = wid;              // MLP group

    // ---- stage constant weights once ----
    for (int i = tid; i < 400 * 64; i += THREADS) sm[OFF_WD + i] = Wdist[i];
    for (int i = tid; i < 16 * 64; i += THREADS) sm[OFF_WD + 400 * 64 + i] = Wdmap[i];
    for (int i = tid; i < 15 * 64; i += THREADS) sm[OFF_WD + 416 * 64 + i] = Wdir[i];
    for (int i = tid; i < 15 * 64; i += THREADS) sm[OFF_WD + 431 * 64 + i] = Wvec[i];
    for (int i = tid; i < 9 * 64; i += THREADS) sm[OFF_WD + 446 * 64 + i] = Wrot[i];
    for (int i = tid; i < 64 * 128; i += THREADS) sm[OFF_W1 + i] = W1[i];

    float lgr[4], lbr[4];
    ull b1p[4], b2p[2];
#pragma unroll
    for (int i = 0; i < 4; ++i) {
        lgr[i] = lng[ls * 4 + i];
        lbr[i] = lnb[ls * 4 + i];
    }
#pragma unroll
    for (int i = 0; i < 4; ++i) { float a = b1[g * 8 + 2 * i], b = b1[g * 8 + 2 * i + 1]; PK2D(b1p[i], a, b); }
#pragma unroll
    for (int i = 0; i < 2; ++i) { float a = b2[g * 4 + 2 * i], b = b2[g * 4 + 2 * i + 1]; PK2D(b2p[i], a, b); }

    const int fbeg = fh ? 228 : 0;
    const int fend = fh ? 455 : 228;

    __syncthreads();

    int* smi = (int*)sm;
    __half* F = (__half*)(sm + OFF_R);

    for (int n0 = blockIdx.x * 2; n0 < Ntot; n0 += gridDim.x * 2) {
        // ---------- stage 1: meta + frames + pos for both n ----------
        if (tid < 64) {
            int b = tid >> 5, kk = tid & 31;
            int n = n0 + b;
            int nb = nbrs[n * KC + kk];
            int j = nb < 0 ? 0 : nb;
            float valid = (nb != -1) ? 1.0f : 0.0f;
            smi[OFF_SJ + b * 32 + kk] = j;
            int dr = resi[j] - resi[n];
            dr = dr < -32 ? -32 : (dr > 32 ? 32 : dr);
            smi[OFF_SREL + b * 32 + kk] = dr + 32;
            float same = (chain[j] == chain[n] && batch[j] == batch[n]) ? 1.0f : 0.0f;
            sm[OFF_SSAME + b * 32 + kk] = same;
            float pm = maskp[n] * maskp[j] * valid;
            sm[OFF_SPM + b * 32 + kk] = pm;
            outMask[n * KC + kk] = pm;
        } else if (tid < 66) {
            int b = tid - 64;
            float e1[3], e2[3], e3[3], t[3], prow[9];
#pragma unroll
            for (int i = 0; i < 9; ++i) prow[i] = pos[(n0 + b) * 15 + i];
            frames_from(prow, e1, e2, e3, t);
#pragma unroll
            for (int r = 0; r < 3; ++r) {
                sm[OFF_RN + b * 12 + r * 3 + 0] = e1[r];
                sm[OFF_RN + b * 12 + r * 3 + 1] = e2[r];
                sm[OFF_RN + b * 12 + r * 3 + 2] = e3[r];
            }
            sm[OFF_RN + b * 12 + 9 + 0] = t[0];
            sm[OFF_RN + b * 12 + 9 + 1] = t[1];
            sm[OFF_RN + b * 12 + 9 + 2] = t[2];
        } else if (tid >= 96 && tid < 126) {
            int b = (tid - 96) / 15, e = (tid - 96) % 15;
            sm[OFF_POSN + b * 16 + e] = pos[(n0 + b) * 15 + e];
        }
        __syncthreads();

        // ---------- stage 2: gather neighbor positions (both n) ----------
        for (int i = tid; i < 960; i += THREADS) {
            int b = i / 480, r2 = i - b * 480;
            int kk = r2 / 15, e = r2 - kk * 15;
            int j = smi[OFF_SJ + b * 32 + kk];
            sm[OFF_PJ + b * 512 + kk * 16 + e] = pos[j * 15 + e];
        }
        __syncthreads();

        // ---------- stage 3: build features (fp16, interleaved by b) ----------
        for (int b = 0; b < 2; ++b) {
            __half* fk = F + (k * FSC) * 2 + b;   // element f at fk[2*f]
            const float* pn = sm + OFF_POSN + b * 16;
            const float* pj = sm + OFF_PJ + b * 512 + k * 16;
            const float* rn = sm + OFF_RN + b * 12;
            {   // distance pair dp = wid (0..15)
                int a = wid / 5, bb = wid - a * 5;
                float dx = pn[a * 3 + 0] - pj[bb * 3 + 0];
                float dy = pn[a * 3 + 1] - pj[bb * 3 + 1];
                float dz = pn[a * 3 + 2] - pj[bb * 3 + 2];
                float d = sqrtf(dx * dx + dy * dy + dz * dz);
                rbf16h(d, fk + wid * 32);
            }
            if (wid < 9) {   // dp = 16 + wid
                int dp = 16 + wid;
                int a = dp / 5, bb = dp - a * 5;
                float dx = pn[a * 3 + 0] - pj[bb * 3 + 0];
                float dy = pn[a * 3 + 1] - pj[bb * 3 + 1];
                float dz = pn[a * 3 + 2] - pj[bb * 3 + 2];
                float d = sqrtf(dx * dx + dy * dy + dz * dz);
                rbf16h(d, fk + dp * 32);
            } else if (wid == 9) {   // dmap rbf, masked
                int j = smi[OFF_SJ + b * 32 + k];
                float pm = sm[OFF_SPM + b * 32 + k];
                float dval = __ldg(&dmap[(long)(n0 + b) * Ntot + j]);
                if (pm > 0.0f) {
                    rbf16h(dval, fk + 400 * 2);
                } else {
                    __half z = __float2half(0.0f);
#pragma unroll
                    for (int i = 0; i < 16; ++i) fk[(400 + i) * 2] = z;
                }
            } else if (wid < 15) {   // rel_vec + dirs, atom a = wid-10
                int a = wid - 10;
                float v0 = pj[a * 3 + 0] - rn[9 + 0];
                float v1 = pj[a * 3 + 1] - rn[9 + 1];
                float v2 = pj[a * 3 + 2] - rn[9 + 2];
                float rv[3];
#pragma unroll
                for (int i = 0; i < 3; ++i)
                    rv[i] = rn[0 + i] * v0 + rn[3 + i] * v1 + rn[6 + i] * v2;
                float nr = sqrtf(rv[0] * rv[0] + rv[1] * rv[1] + rv[2] * rv[2]);
                float inv = 1.0f / (nr + 1e-6f);
#pragma unroll
                for (int i = 0; i < 3; ++i) {
                    fk[(416 + a * 3 + i) * 2] = __float2half(rv[i] * inv);
                    fk[(431 + a * 3 + i) * 2] = __float2half(rv[i] * 0.1f);
                }
            } else {   // wid == 15: rotation features
                float e1j[3], e2j[3], e3j[3], tj[3];
                frames_from(pj, e1j, e2j, e3j, tj);
#pragma unroll
                for (int i = 0; i < 3; ++i) {
                    float r0 = rn[0 + i], r1 = rn[3 + i], r2 = rn[6 + i];
                    fk[(446 + i * 3 + 0) * 2] = __float2half(r0 * e1j[0] + r1 * e1j[1] + r2 * e1j[2]);
                    fk[(446 + i * 3 + 1) * 2] = __float2half(r0 * e2j[0] + r1 * e2j[1] + r2 * e2j[2]);
                    fk[(446 + i * 3 + 2) * 2] = __float2half(r0 * e3j[0] + r1 * e3j[1] + r2 * e3j[2]);
                }
            }
        }
        __syncthreads();

        // ---------- stage 4: projection for BOTH n, 8 p-groups x 2 f-halves ----------
        ull acc[8];   // [0..3] n0 cols pg*8..+7, [4..7] n1
#pragma unroll
        for (int j = 0; j < 8; ++j) acc[j] = 0ull;
        {
            const __half2* xh = (const __half2*)(sm + OFF_R) + k * FSC;
            const ulonglong2* w = reinterpret_cast<const ulonglong2*>(sm + OFF_WD) + pg * 2;
#pragma unroll 2
            for (int f = fbeg; f < fend; ++f) {
                float2 x2 = __half22float2(xh[f]);
                ull xa, xb;
                PK2(xa, x2.x);
                PK2(xb, x2.y);
                ulonglong2 u0 = w[f * 16];
                ulonglong2 u1 = w[f * 16 + 1];
                FMA2(acc[0], xa, u0.x, acc[0]); FMA2(acc[1], xa, u0.y, acc[1]);
                FMA2(acc[2], xa, u1.x, acc[2]); FMA2(acc[3], xa, u1.y, acc[3]);
                FMA2(acc[4], xb, u0.x, acc[4]); FMA2(acc[5], xb, u0.y, acc[5]);
                FMA2(acc[6], xb, u1.x, acc[6]); FMA2(acc[7], xb, u1.y, acc[7]);
            }
        }
        if (fh == 0) {
            ull* p0 = (ull*)(sm + OFF_P0) + k * 33 + pg * 4;
            ull* p1 = (ull*)(sm + OFF_P1) + k * 33 + pg * 4;
#pragma unroll
            for (int j = 0; j < 4; ++j) { p0[j] = acc[j]; p1[j] = acc[4 + j]; }
        }
        __syncthreads();   // all feature reads done; fh0 stores visible
        if (fh == 1) {
            ull* p0 = (ull*)(sm + OFF_P0) + k * 33 + pg * 4;
            ull* p1 = (ull*)(sm + OFF_P1) + k * 33 + pg * 4;
#pragma unroll
            for (int j = 0; j < 4; ++j) {
                ull t0 = p0[j]; ADD2(t0, t0, acc[j]);     p0[j] = t0;
                ull t1 = p1[j]; ADD2(t1, t1, acc[4 + j]); p1[j] = t1;
            }
        }
        // restage W2 into the (now dead) feature region
        for (int i = tid; i < 128 * 64; i += THREADS) sm[OFF_W2 + i] = W2[i];
        __syncthreads();

        // ---------- stage 5: + Wrel, LayerNorm for both n -> pairH (half2 interleaved) ----------
        {
            float a0 = sm[OFF_P0 + lkk * 66 + ls * 4 + 0];
            float a1 = sm[OFF_P0 + lkk * 66 + ls * 4 + 1];
            float a2 = sm[OFF_P0 + lkk * 66 + ls * 4 + 2];
            float a3 = sm[OFF_P0 + lkk * 66 + ls * 4 + 3];
            float c0 = sm[OFF_P1 + lkk * 66 + ls * 4 + 0];
            float c1 = sm[OFF_P1 + lkk * 66 + ls * 4 + 1];
            float c2 = sm[OFF_P1 + lkk * 66 + ls * 4 + 2];
            float c3 = sm[OFF_P1 + lkk * 66 + ls * 4 + 3];
            {
                int rel = smi[OFF_SREL + lkk];
                float same = sm[OFF_SSAME + lkk];
                float4 wr = __ldg(reinterpret_cast<const float4*>(Wrel) + rel * 16 + ls);
                a0 = fmaf(same, wr.x, a0); a1 = fmaf(same, wr.y, a1);
                a2 = fmaf(same, wr.z, a2); a3 = fmaf(same, wr.w, a3);
            }
            {
                int rel = smi[OFF_SREL + 32 + lkk];
                float same = sm[OFF_SSAME + 32 + lkk];
                float4 wr = __ldg(reinterpret_cast<const float4*>(Wrel) + rel * 16 + ls);
                c0 = fmaf(same, wr.x, c0); c1 = fmaf(same, wr.y, c1);
                c2 = fmaf(same, wr.z, c2); c3 = fmaf(same, wr.w, c3);
            }
            __syncthreads();   // partial reads done before pairH overwrite of P0

            // LN n0
            float y0, y1, y2, y3;
            {
                float ssum = a0 + a1 + a2 + a3;
                ssum += __shfl_xor_sync(0xffffffffu, ssum, 8);
                ssum += __shfl_xor_sync(0xffffffffu, ssum, 4);
                ssum += __shfl_xor_sync(0xffffffffu, ssum, 2);
                ssum += __shfl_xor_sync(0xffffffffu, ssum, 1);
                float mu = ssum * 0.015625f;
                float d0 = a0 - mu, d1 = a1 - mu, d2 = a2 - mu, d3 = a3 - mu;
                float sq = d0 * d0 + d1 * d1 + d2 * d2 + d3 * d3;
                sq += __shfl_xor_sync(0xffffffffu, sq, 8);
                sq += __shfl_xor_sync(0xffffffffu, sq, 4);
                sq += __shfl_xor_sync(0xffffffffu, sq, 2);
                sq += __shfl_xor_sync(0xffffffffu, sq, 1);
                float inv = rsqrtf(sq * 0.015625f + 1e-5f);
                y0 = lgr[0] * d0 * inv + lbr[0];
                y1 = lgr[1] * d1 * inv + lbr[1];
                y2 = lgr[2] * d2 * inv + lbr[2];
                y3 = lgr[3] * d3 * inv + lbr[3];
            }
            // LN n1
            float z0, z1, z2, z3;
            {
                float ssum = c0 + c1 + c2 + c3;
                ssum += __shfl_xor_sync(0xffffffffu, ssum, 8);
                ssum += __shfl_xor_sync(0xffffffffu, ssum, 4);
                ssum += __shfl_xor_sync(0xffffffffu, ssum, 2);
                ssum += __shfl_xor_sync(0xffffffffu, ssum, 1);
                float mu = ssum * 0.015625f;
                float d0 = c0 - mu, d1 = c1 - mu, d2 = c2 - mu, d3 = c3 - mu;
                float sq = d0 * d0 + d1 * d1 + d2 * d2 + d3 * d3;
                sq += __shfl_xor_sync(0xffffffffu, sq, 8);
                sq += __shfl_xor_sync(0xffffffffu, sq, 4);
                sq += __shfl_xor_sync(0xffffffffu, sq, 2);
                sq += __shfl_xor_sync(0xffffffffu, sq, 1);
                float inv = rsqrtf(sq * 0.015625f + 1e-5f);
                z0 = lgr[0] * d0 * inv + lbr[0];
                z1 = lgr[1] * d1 * inv + lbr[1];
                z2 = lgr[2] * d2 * inv + lbr[2];
                z3 = lgr[3] * d3 * inv + lbr[3];
            }
            __half2* ph = (__half2*)(sm + OFF_P0) + lkk * 65 + ls * 4;
            ph[0] = __floats2half2_rn(y0, z0);
            ph[1] = __floats2half2_rn(y1, z1);
            ph[2] = __floats2half2_rn(y2, z2);
            ph[3] = __floats2half2_rn(y3, z3);
        }
        __syncthreads();

        // ---------- stage 6: MLP layer 1 (64 -> 128), both n fused, fp16 x ----------
        {
            ull hacc[8];
#pragma unroll
            for (int j = 0; j < 4; ++j) { hacc[j] = b1p[j]; hacc[4 + j] = b1p[j]; }
            const __half2* pb = (const __half2*)(sm + OFF_P0) + k * 65;
            const ulonglong2* w1v = reinterpret_cast<const ulonglong2*>(sm + OFF_W1) + g * 2;
#pragma unroll 4
            for (int p = 0; p < 64; ++p) {
                float2 x2 = __half22float2(pb[p]);
                ull xa, xb;
                PK2(xa, x2.x);
                PK2(xb, x2.y);
                ulonglong2 wa = w1v[p * 32];
                ulonglong2 wb = w1v[p * 32 + 1];
                FMA2(hacc[0], xa, wa.x, hacc[0]);
                FMA2(hacc[1], xa, wa.y, hacc[1]);
                FMA2(hacc[2], xa, wb.x, hacc[2]);
                FMA2(hacc[3], xa, wb.y, hacc[3]);
                FMA2(hacc[4], xb, wa.x, hacc[4]);
                FMA2(hacc[5], xb, wa.y, hacc[5]);
                FMA2(hacc[6], xb, wb.x, hacc[6]);
                FMA2(hacc[7], xb, wb.y, hacc[7]);
            }
            __half2* hb = (__half2*)(sm + OFF_H) + k * 129 + g * 8;
#pragma unroll
            for (int j = 0; j < 4; ++j) {
                float lo0, hi0, lo1, hi1;
                UPK2(lo0, hi0, hacc[j]);
                UPK2(lo1, hi1, hacc[4 + j]);
                hb[2 * j + 0] = __floats2half2_rn(gelu_f(lo0), gelu_f(lo1));
                hb[2 * j + 1] = __floats2half2_rn(gelu_f(hi0), gelu_f(hi1));
            }
        }
        __syncthreads();

        // ---------- stage 7: MLP layer 2 (128 -> 64), both n fused, fp16 x ----------
        {
            ull o2[4];
            o2[0] = b2p[0]; o2[1] = b2p[1];
            o2[2] = b2p[0]; o2[3] = b2p[1];
            const __half2* hr = (const __half2*)(sm + OFF_H) + k * 129;
            const ulonglong2* w2v = reinterpret_cast<const ulonglong2*>(sm + OFF_W2) + g;
#pragma unroll 8
            for (int j = 0; j < 128; ++j) {
                float2 x2 = __half22float2(hr[j]);
                ull xa, xb;
                PK2(xa, x2.x);
                PK2(xb, x2.y);
                ulonglong2 w = w2v[j * 16];
                FMA2(o2[0], xa, w.x, o2[0]);
                FMA2(o2[1], xa, w.y, o2[1]);
                FMA2(o2[2], xb, w.x, o2[2]);
                FMA2(o2[3], xb, w.y, o2[3]);
            }
            float4 o;
            UPK2(o.x, o.y, o2[0]);
            UPK2(o.z, o.w, o2[1]);
            reinterpret_cast<float4*>(outPair)[(n0 * KC + k) * 16 + g] = o;
            UPK2(o.x, o.y, o2[2]);
            UPK2(o.z, o.w, o2[3]);
            reinterpret_cast<float4*>(outPair)[((n0 + 1) * KC + k) * 16 + g] = o;
        }
        __syncthreads();
        // loop-top stage-1 follows the final barrier
    }
}

extern "C" void kernel_launch(void* const* d_in, const int* in_sizes, int n_in,
                              void* d_out, int out_size) {
    const float* pos   = (const float*)d_in[0];
    const float* dmap  = (const float*)d_in[1];
    const int*   nbrs  = (const int*)d_in[2];
    const int*   resi  = (const int*)d_in[3];
    const int*   chain = (const int*)d_in[4];
    const int*   batch = (const int*)d_in[5];
    const float* maskp = (const float*)d_in[6];
    const float* Wrel  = (const float*)d_in[7];
    const float* Wdmap = (const float*)d_in[8];
    const float* Wdist = (const float*)d_in[9];
    const float* Wdir  = (const float*)d_in[10];
    const float* Wrot  = (const float*)d_in[11];
    const float* Wvec  = (const float*)d_in[12];
    const float* lng   = (const float*)d_in[13];
    const float* lnb   = (const float*)d_in[14];
    const float* W1    = (const float*)d_in[15];
    const float* b1    = (const float*)d_in[16];
    const float* W2    = (const float*)d_in[17];
    const float* b2    = (const float*)d_in[18];

    float* outPair = (float*)d_out;
    float* outMask = outPair + (long)Ntot * KC * PC;

    cudaFuncSetAttribute(dsd_kernel, cudaFuncAttributeMaxDynamicSharedMemorySize, SMEMF * 4);
    int sms = 148;
    cudaDeviceGetAttribute(&sms, cudaDevAttrMultiProcessorCount, 0);

    dsd_kernel<<<sms, THREADS, SMEMF * 4>>>(
        pos, dmap, nbrs, resi, chain, batch, maskp,
        Wrel, Wdmap, Wdist, Wdir, Wrot, Wvec, lng, lnb, W1, b1, W2, b2,
        outPair, outMask);
}

// round 10
// speedup vs baseline: 1.9847x; 1.9847x over previous
#include <cuda_runtime.h>
#include <cuda_fp16.h>
#include <cstdint>
#include <math.h>

typedef unsigned long long ull;
typedef unsigned int u32;

#define Ntot 8192
#define KC   32
#define PC   64
#define FEATC 455
#define KPAD  464            // 29 * 16
#define FS2   472            // feature row stride in halfs (944B; ldsm conflict-free)
#define WS2   72             // weight row stride in halfs (144B; ldsm.trans conflict-free)
#define THREADS 512

// ---- shared memory layout (float offsets) ----
#define OFF_WDH   0                        // half[464][72] = 33408 h = 16704 fl
#define OFF_W1    16704                    // fp32 64*128 = 8192
#define OFF_R     24896                    // F half[64][472] = 15104 fl ; later H fp32 32*129=4128
#define OFF_P0    40000                    // 32*66 = 2112 (n0 proj; later pair fp32 stride 65)
#define OFF_P1    42112                    // 32*66 = 2112 (n1 proj)
#define OFF_PJ    44224                    // [b][32][16] = 1024
#define OFF_POSN  45248                    // 32
#define OFF_RN    45280                    // 24
#define OFF_SJ    45304                    // 64 ints
#define OFF_SREL  45368                    // 64
#define OFF_SSAME 45432                    // 64
#define OFF_SPM   45496                    // 64
#define OFF_W2P   45560                    // fp32 128*64 = 8192 (PERMANENT)
#define SMEMF     53752                    // 215008 bytes

// ---- packed f32x2 helpers ----
#define FMA2(d, a, b, c) asm("fma.rn.f32x2 %0, %1, %2, %3;" : "=l"(d) : "l"(a), "l"(b), "l"(c))
#define PK2(r, x)        asm("mov.b64 %0, {%1, %1};"        : "=l"(r) : "f"(x))
#define PK2D(r, x, y)    asm("mov.b64 %0, {%1, %2};"        : "=l"(r) : "f"(x), "f"(y))
#define UPK2(lo, hi, v)  asm("mov.b64 {%0, %1}, %2;"        : "=f"(lo), "=f"(hi) : "l"(v))

// ---- tensor-core helpers ----
#define LDSM4(q0, q1, q2, q3, addr) \
    asm volatile("ldmatrix.sync.aligned.m8n8.x4.shared.b16 {%0,%1,%2,%3}, [%4];" \
                 : "=r"(q0), "=r"(q1), "=r"(q2), "=r"(q3) : "r"(addr))
#define LDSM4T(q0, q1, q2, q3, addr) \
    asm volatile("ldmatrix.sync.aligned.m8n8.x4.trans.shared.b16 {%0,%1,%2,%3}, [%4];" \
                 : "=r"(q0), "=r"(q1), "=r"(q2), "=r"(q3) : "r"(addr))
#define MMA16816(d0, d1, d2, d3, q0, q1, q2, q3, p0, p1) \
    asm volatile("mma.sync.aligned.m16n8k16.row.col.f32.f16.f16.f32 " \
                 "{%0,%1,%2,%3}, {%4,%5,%6,%7}, {%8,%9}, {%0,%1,%2,%3};" \
                 : "+f"(d0), "+f"(d1), "+f"(d2), "+f"(d3) \
                 : "r"(q0), "r"(q1), "r"(q2), "r"(q3), "r"(p0), "r"(p1))

// ---------------- RBF: 16 bins, 3 exps, fp16 out stride 1 ----------------
__device__ __forceinline__ void rbf16h(float d, __half* out) {
    const float SI = 0.72727272727f;   // 16/22
    const float G  = 1.06666666667f;   // 16/15
    const float Q  = 0.10273954f;      // exp(-2*G*G)
    float g = d * SI;
    int m = __float2int_rn(g * 0.9375f);
    m = m < 0 ? 0 : (m > 15 ? 15 : m);
    float u = g - (float)m * G;
    float peak = __expf(-u * u);
    float r = __expf(G * (2.0f * u - G));
    float s = __expf(-G * (2.0f * u + G));
    out[m] = __float2half(peak);
    float v = peak;
#pragma unroll
    for (int st = 1; st <= 15; ++st) {
        v *= r; r *= Q;
        int i = m + st;
        if (i <= 15) out[i] = __float2half(v);
    }
    v = peak;
#pragma unroll
    for (int st = 1; st <= 15; ++st) {
        v *= s; s *= Q;
        int i = m - st;
        if (i >= 0) out[i] = __float2half(v);
    }
}

__device__ __forceinline__ void frames_from(const float* p,
                                            float e1[3], float e2[3], float e3[3], float t[3]) {
    t[0] = p[3]; t[1] = p[4]; t[2] = p[5];
    float v1x = p[6] - t[0], v1y = p[7] - t[1], v1z = p[8] - t[2];
    float v2x = p[0] - t[0], v2y = p[1] - t[1], v2z = p[2] - t[2];
    float n1 = sqrtf(v1x * v1x + v1y * v1y + v1z * v1z) + 1e-6f;
    e1[0] = v1x / n1; e1[1] = v1y / n1; e1[2] = v1z / n1;
    float dt = v2x * e1[0] + v2y * e1[1] + v2z * e1[2];
    float ux = v2x - dt * e1[0], uy = v2y - dt * e1[1], uz = v2z - dt * e1[2];
    float n2 = sqrtf(ux * ux + uy * uy + uz * uz) + 1e-6f;
    e2[0] = ux / n2; e2[1] = uy / n2; e2[2] = uz / n2;
    e3[0] = e1[1] * e2[2] - e1[2] * e2[1];
    e3[1] = e1[2] * e2[0] - e1[0] * e2[2];
    e3[2] = e1[0] * e2[1] - e1[1] * e2[0];
}

__device__ __forceinline__ float gelu_f(float x) {
    float c = 0.7978845608028654f * (x + 0.044715f * x * x * x);
    float t;
    asm("tanh.approx.f32 %0, %1;" : "=f"(t) : "f"(c));
    return 0.5f * x * (1.0f + t);
}

__global__ void __launch_bounds__(THREADS, 1)
dsd_kernel(const float* __restrict__ pos, const float* __restrict__ dmap,
           const int* __restrict__ nbrs, const int* __restrict__ resi,
           const int* __restrict__ chain, const int* __restrict__ batch,
           const float* __restrict__ maskp,
           const float* __restrict__ Wrel, const float* __restrict__ Wdmap,
           const float* __restrict__ Wdist, const float* __restrict__ Wdir,
           const float* __restrict__ Wrot, const float* __restrict__ Wvec,
           const float* __restrict__ lng, const float* __restrict__ lnb,
           const float* __restrict__ W1, const float* __restrict__ bias1,
           const float* __restrict__ W2, const float* __restrict__ bias2,
           float* __restrict__ outPair, float* __restrict__ outMask)
{
    extern __shared__ float sm[];
    const int tid = threadIdx.x;
    const int k   = tid & 31;         // lane
    const int wid = tid >> 5;         // warp id (0..15)
    const int mt  = wid & 3;          // mma row tile (16 rows)
    const int nt  = wid >> 2;         // mma col tile (16 cols)
    const int lkk = tid >> 4;         // LN: k
    const int ls  = tid & 15;         // LN: col quad
    const int g   = wid;              // MLP group

    __half* WDh = (__half*)(sm + OFF_WDH);
    __half* Fh  = (__half*)(sm + OFF_R);

    // ---- stage constant weights once: fp16 projection matrix [464][72] ----
    for (int i = tid; i < KPAD * 64; i += THREADS) {
        int f = i >> 6, c = i & 63;
        float v;
        if (f < 400)      v = Wdist[f * 64 + c];
        else if (f < 416) v = Wdmap[(f - 400) * 64 + c];
        else if (f < 431) v = Wdir[(f - 416) * 64 + c];
        else if (f < 446) v = Wvec[(f - 431) * 64 + c];
        else if (f < 455) v = Wrot[(f - 446) * 64 + c];
        else              v = 0.0f;
        WDh[f * WS2 + c] = __float2half(v);
    }
    for (int i = tid; i < 64 * 128; i += THREADS) sm[OFF_W1 + i] = W1[i];
    for (int i = tid; i < 128 * 64; i += THREADS) sm[OFF_W2P + i] = W2[i];

    float lgr[4], lbr[4];
    ull b1p[4], b2p[2];
#pragma unroll
    for (int i = 0; i < 4; ++i) {
        lgr[i] = lng[ls * 4 + i];
        lbr[i] = lnb[ls * 4 + i];
    }
#pragma unroll
    for (int i = 0; i < 4; ++i) { float va = bias1[g * 8 + 2 * i], vb = bias1[g * 8 + 2 * i + 1]; PK2D(b1p[i], va, vb); }
#pragma unroll
    for (int i = 0; i < 2; ++i) { float va = bias2[g * 4 + 2 * i], vb = bias2[g * 4 + 2 * i + 1]; PK2D(b2p[i], va, vb); }

    // mma lane-addresses (constant across iterations)
    const u32 FhS = (u32)__cvta_generic_to_shared(Fh);
    const u32 WhS = (u32)__cvta_generic_to_shared(WDh);
    const int arow = mt * 16 + (k & 7) + ((k >> 3) & 1) * 8;
    const u32 aAddr0 = FhS + arow * (FS2 * 2) + ((k >> 4) & 1) * 16;
    const int brow = (k & 7) + ((k >> 3) & 1) * 8;
    const u32 bAddr0 = WhS + brow * (WS2 * 2) + (nt * 16 + ((k >> 4) & 1) * 8) * 2;

    __syncthreads();

    int* smi = (int*)sm;

    for (int n0 = blockIdx.x * 2; n0 < Ntot; n0 += gridDim.x * 2) {
        // ---------- stage 1: meta + frames + pos for both n ----------
        if (tid < 64) {
            int bb = tid >> 5, kk = tid & 31;
            int n = n0 + bb;
            int nb = nbrs[n * KC + kk];
            int j = nb < 0 ? 0 : nb;
            float valid = (nb != -1) ? 1.0f : 0.0f;
            smi[OFF_SJ + bb * 32 + kk] = j;
            int dr = resi[j] - resi[n];
            dr = dr < -32 ? -32 : (dr > 32 ? 32 : dr);
            smi[OFF_SREL + bb * 32 + kk] = dr + 32;
            float same = (chain[j] == chain[n] && batch[j] == batch[n]) ? 1.0f : 0.0f;
            sm[OFF_SSAME + bb * 32 + kk] = same;
            float pm = maskp[n] * maskp[j] * valid;
            sm[OFF_SPM + bb * 32 + kk] = pm;
            outMask[n * KC + kk] = pm;
        } else if (tid < 66) {
            int bb = tid - 64;
            float e1[3], e2[3], e3[3], t[3], prow[9];
#pragma unroll
            for (int i = 0; i < 9; ++i) prow[i] = pos[(n0 + bb) * 15 + i];
            frames_from(prow, e1, e2, e3, t);
#pragma unroll
            for (int r = 0; r < 3; ++r) {
                sm[OFF_RN + bb * 12 + r * 3 + 0] = e1[r];
                sm[OFF_RN + bb * 12 + r * 3 + 1] = e2[r];
                sm[OFF_RN + bb * 12 + r * 3 + 2] = e3[r];
            }
            sm[OFF_RN + bb * 12 + 9 + 0] = t[0];
            sm[OFF_RN + bb * 12 + 9 + 1] = t[1];
            sm[OFF_RN + bb * 12 + 9 + 2] = t[2];
        } else if (tid >= 96 && tid < 126) {
            int bb = (tid - 96) / 15, e = (tid - 96) % 15;
            sm[OFF_POSN + bb * 16 + e] = pos[(n0 + bb) * 15 + e];
        }
        __syncthreads();

        // ---------- stage 2: gather neighbor positions ----------
        for (int i = tid; i < 960; i += THREADS) {
            int bb = i / 480, r2 = i - bb * 480;
            int kk = r2 / 15, e = r2 - kk * 15;
            int j = smi[OFF_SJ + bb * 32 + kk];
            sm[OFF_PJ + bb * 512 + kk * 16 + e] = pos[j * 15 + e];
        }
        __syncthreads();

        // ---------- stage 3: build features (fp16 rows, stride FS2) ----------
        for (int bb = 0; bb < 2; ++bb) {
            __half* fk = Fh + (bb * 32 + k) * FS2;
            const float* pn = sm + OFF_POSN + bb * 16;
            const float* pj = sm + OFF_PJ + bb * 512 + k * 16;
            const float* rn = sm + OFF_RN + bb * 12;
            {   // distance pair dp = wid (0..15)
                int a = wid / 5, c5 = wid - a * 5;
                float dx = pn[a * 3 + 0] - pj[c5 * 3 + 0];
                float dy = pn[a * 3 + 1] - pj[c5 * 3 + 1];
                float dz = pn[a * 3 + 2] - pj[c5 * 3 + 2];
                float d = sqrtf(dx * dx + dy * dy + dz * dz);
                rbf16h(d, fk + wid * 16);
            }
            if (wid < 9) {   // dp = 16 + wid
                int dp = 16 + wid;
                int a = dp / 5, c5 = dp - a * 5;
                float dx = pn[a * 3 + 0] - pj[c5 * 3 + 0];
                float dy = pn[a * 3 + 1] - pj[c5 * 3 + 1];
                float dz = pn[a * 3 + 2] - pj[c5 * 3 + 2];
                float d = sqrtf(dx * dx + dy * dy + dz * dz);
                rbf16h(d, fk + dp * 16);
            } else if (wid == 9) {   // dmap rbf, masked
                int j = smi[OFF_SJ + bb * 32 + k];
                float pm = sm[OFF_SPM + bb * 32 + k];
                float dval = __ldg(&dmap[(long)(n0 + bb) * Ntot + j]);
                if (pm > 0.0f) {
                    rbf16h(dval, fk + 400);
                } else {
                    __half z = __float2half(0.0f);
#pragma unroll
                    for (int i = 0; i < 16; ++i) fk[400 + i] = z;
                }
            } else if (wid < 15) {   // rel_vec + dirs, atom a = wid-10
                int a = wid - 10;
                float v0 = pj[a * 3 + 0] - rn[9 + 0];
                float v1 = pj[a * 3 + 1] - rn[9 + 1];
                float v2 = pj[a * 3 + 2] - rn[9 + 2];
                float rv[3];
#pragma unroll
                for (int i = 0; i < 3; ++i)
                    rv[i] = rn[0 + i] * v0 + rn[3 + i] * v1 + rn[6 + i] * v2;
                float nr = sqrtf(rv[0] * rv[0] + rv[1] * rv[1] + rv[2] * rv[2]);
                float inv = 1.0f / (nr + 1e-6f);
#pragma unroll
                for (int i = 0; i < 3; ++i) {
                    fk[416 + a * 3 + i] = __float2half(rv[i] * inv);
                    fk[431 + a * 3 + i] = __float2half(rv[i] * 0.1f);
                }
            } else {   // wid == 15: rotation features
                float e1j[3], e2j[3], e3j[3], tj[3];
                frames_from(pj, e1j, e2j, e3j, tj);
#pragma unroll
                for (int i = 0; i < 3; ++i) {
                    float r0 = rn[0 + i], r1 = rn[3 + i], r2 = rn[6 + i];
                    fk[446 + i * 3 + 0] = __float2half(r0 * e1j[0] + r1 * e1j[1] + r2 * e1j[2]);
                    fk[446 + i * 3 + 1] = __float2half(r0 * e2j[0] + r1 * e2j[1] + r2 * e2j[2]);
                    fk[446 + i * 3 + 2] = __float2half(r0 * e3j[0] + r1 * e3j[1] + r2 * e3j[2]);
                }
            }
        }
        // zero K-pad cols 455..463 (feature region is reused, may hold garbage)
        {
            __half z = __float2half(0.0f);
            for (int i = tid; i < 64 * 9; i += THREADS) {
                int r = i / 9, c = i - r * 9;
                Fh[r * FS2 + 455 + c] = z;
            }
        }
        __syncthreads();

        // ---------- stage 4: projection GEMM via mma.sync (m16n8k16 f16) ----------
        {
            float d0 = 0.f, d1 = 0.f, d2 = 0.f, d3 = 0.f;   // n8 low
            float d4 = 0.f, d5 = 0.f, d6 = 0.f, d7 = 0.f;   // n8 high
            u32 aA = aAddr0, bA = bAddr0;
#pragma unroll 1
            for (int s = 0; s < 29; ++s) {
                u32 ra0, ra1, ra2, ra3, rb0, rb1, rb2, rb3;
                LDSM4(ra0, ra1, ra2, ra3, aA);
                LDSM4T(rb0, rb1, rb2, rb3, bA);
                aA += 32;                 // 16 halfs
                bA += 16 * WS2 * 2;       // 16 k-rows
                MMA16816(d0, d1, d2, d3, ra0, ra1, ra2, ra3, rb0, rb1);
                MMA16816(d4, d5, d6, d7, ra0, ra1, ra2, ra3, rb2, rb3);
            }
            // epilogue: scatter into P0/P1 (stride 66, same layout stage 5 expects)
            float* P = sm + ((mt >> 1) ? OFF_P1 : OFF_P0);
            int kk1 = (mt & 1) * 16 + (k >> 2);
            int kk2 = kk1 + 8;
            int col = nt * 16 + (k & 3) * 2;
            *reinterpret_cast<float2*>(P + kk1 * 66 + col)     = make_float2(d0, d1);
            *reinterpret_cast<float2*>(P + kk2 * 66 + col)     = make_float2(d2, d3);
            *reinterpret_cast<float2*>(P + kk1 * 66 + col + 8) = make_float2(d4, d5);
            *reinterpret_cast<float2*>(P + kk2 * 66 + col + 8) = make_float2(d6, d7);
        }
        __syncthreads();

        // ---------- stage 5: + Wrel, LayerNorm for both n ----------
        {
            float a0 = sm[OFF_P0 + lkk * 66 + ls * 4 + 0];
            float a1 = sm[OFF_P0 + lkk * 66 + ls * 4 + 1];
            float a2 = sm[OFF_P0 + lkk * 66 + ls * 4 + 2];
            float a3 = sm[OFF_P0 + lkk * 66 + ls * 4 + 3];
            float c0 = sm[OFF_P1 + lkk * 66 + ls * 4 + 0];
            float c1 = sm[OFF_P1 + lkk * 66 + ls * 4 + 1];
            float c2 = sm[OFF_P1 + lkk * 66 + ls * 4 + 2];
            float c3 = sm[OFF_P1 + lkk * 66 + ls * 4 + 3];
            {
                int rel = smi[OFF_SREL + lkk];
                float same = sm[OFF_SSAME + lkk];
                float4 wr = __ldg(reinterpret_cast<const float4*>(Wrel) + rel * 16 + ls);
                a0 = fmaf(same, wr.x, a0); a1 = fmaf(same, wr.y, a1);
                a2 = fmaf(same, wr.z, a2); a3 = fmaf(same, wr.w, a3);
            }
            {
                int rel = smi[OFF_SREL + 32 + lkk];
                float same = sm[OFF_SSAME + 32 + lkk];
                float4 wr = __ldg(reinterpret_cast<const float4*>(Wrel) + rel * 16 + ls);
                c0 = fmaf(same, wr.x, c0); c1 = fmaf(same, wr.y, c1);
                c2 = fmaf(same, wr.z, c2); c3 = fmaf(same, wr.w, c3);
            }
            __syncthreads();   // all P0/P1 reads done before pair overwrite

            // LN n0 -> pair at OFF_P0 stride 65
            {
                float ssum = a0 + a1 + a2 + a3;
                ssum += __shfl_xor_sync(0xffffffffu, ssum, 8);
                ssum += __shfl_xor_sync(0xffffffffu, ssum, 4);
                ssum += __shfl_xor_sync(0xffffffffu, ssum, 2);
                ssum += __shfl_xor_sync(0xffffffffu, ssum, 1);
                float mu = ssum * 0.015625f;
                float e0 = a0 - mu, e1 = a1 - mu, e2 = a2 - mu, e3 = a3 - mu;
                float sq = e0 * e0 + e1 * e1 + e2 * e2 + e3 * e3;
                sq += __shfl_xor_sync(0xffffffffu, sq, 8);
                sq += __shfl_xor_sync(0xffffffffu, sq, 4);
                sq += __shfl_xor_sync(0xffffffffu, sq, 2);
                sq += __shfl_xor_sync(0xffffffffu, sq, 1);
                float inv = rsqrtf(sq * 0.015625f + 1e-5f);
                sm[OFF_P0 + lkk * 65 + ls * 4 + 0] = lgr[0] * e0 * inv + lbr[0];
                sm[OFF_P0 + lkk * 65 + ls * 4 + 1] = lgr[1] * e1 * inv + lbr[1];
                sm[OFF_P0 + lkk * 65 + ls * 4 + 2] = lgr[2] * e2 * inv + lbr[2];
                sm[OFF_P0 + lkk * 65 + ls * 4 + 3] = lgr[3] * e3 * inv + lbr[3];
            }
            // LN n1 -> pair at OFF_P1 stride 65
            {
                float ssum = c0 + c1 + c2 + c3;
                ssum += __shfl_xor_sync(0xffffffffu, ssum, 8);
                ssum += __shfl_xor_sync(0xffffffffu, ssum, 4);
                ssum += __shfl_xor_sync(0xffffffffu, ssum, 2);
                ssum += __shfl_xor_sync(0xffffffffu, ssum, 1);
                float mu = ssum * 0.015625f;
                float e0 = c0 - mu, e1 = c1 - mu, e2 = c2 - mu, e3 = c3 - mu;
                float sq = e0 * e0 + e1 * e1 + e2 * e2 + e3 * e3;
                sq += __shfl_xor_sync(0xffffffffu, sq, 8);
                sq += __shfl_xor_sync(0xffffffffu, sq, 4);
                sq += __shfl_xor_sync(0xffffffffu, sq, 2);
                sq += __shfl_xor_sync(0xffffffffu, sq, 1);
                float inv = rsqrtf(sq * 0.015625f + 1e-5f);
                sm[OFF_P1 + lkk * 65 + ls * 4 + 0] = lgr[0] * e0 * inv + lbr[0];
                sm[OFF_P1 + lkk * 65 + ls * 4 + 1] = lgr[1] * e1 * inv + lbr[1];
                sm[OFF_P1 + lkk * 65 + ls * 4 + 2] = lgr[2] * e2 * inv + lbr[2];
                sm[OFF_P1 + lkk * 65 + ls * 4 + 3] = lgr[3] * e3 * inv + lbr[3];
            }
        }
        __syncthreads();

        // ---------- stages 6-7: MLP per n (exact R6 structure) ----------
#pragma unroll 1
        for (int bb = 0; bb < 2; ++bb) {
            const int pairOff = bb ? OFF_P1 : OFF_P0;
            // MLP layer 1: 64 -> 128
            {
                ull hacc[4];
#pragma unroll
                for (int j = 0; j < 4; ++j) hacc[j] = b1p[j];
                const float* pb = sm + pairOff + k * 65;
                const ulonglong2* w1v = reinterpret_cast<const ulonglong2*>(sm + OFF_W1) + g * 2;
#pragma unroll 4
                for (int p = 0; p < 64; ++p) {
                    float xv = pb[p];
                    ull xx; PK2(xx, xv);
                    ulonglong2 wa = w1v[p * 32];
                    ulonglong2 wb = w1v[p * 32 + 1];
                    FMA2(hacc[0], xx, wa.x, hacc[0]);
                    FMA2(hacc[1], xx, wa.y, hacc[1]);
                    FMA2(hacc[2], xx, wb.x, hacc[2]);
                    FMA2(hacc[3], xx, wb.y, hacc[3]);
                }
                float* hb = sm + OFF_R + k * 129 + g * 8;   // H lives in dead F region
#pragma unroll
                for (int j = 0; j < 4; ++j) {
                    float lo, hi;
                    UPK2(lo, hi, hacc[j]);
                    hb[2 * j + 0] = gelu_f(lo);
                    hb[2 * j + 1] = gelu_f(hi);
                }
            }
            __syncthreads();
            // MLP layer 2: 128 -> 64
            {
                ull o2[2];
                o2[0] = b2p[0]; o2[1] = b2p[1];
                const float* hr = sm + OFF_R + k * 129;
                const ulonglong2* w2v = reinterpret_cast<const ulonglong2*>(sm + OFF_W2P) + g;
#pragma unroll 8
                for (int j = 0; j < 128; ++j) {
                    float xv = hr[j];
                    ull xx; PK2(xx, xv);
                    ulonglong2 w = w2v[j * 16];
                    FMA2(o2[0], xx, w.x, o2[0]);
                    FMA2(o2[1], xx, w.y, o2[1]);
                }
                float4 o;
                UPK2(o.x, o.y, o2[0]);
                UPK2(o.z, o.w, o2[1]);
                reinterpret_cast<float4*>(outPair)[((n0 + bb) * KC + k) * 16 + g] = o;
            }
            __syncthreads();
        }
        // loop-top stage-1 follows the final barrier
    }
}

extern "C" void kernel_launch(void* const* d_in, const int* in_sizes, int n_in,
                              void* d_out, int out_size) {
    const float* pos   = (const float*)d_in[0];
    const float* dmap  = (const float*)d_in[1];
    const int*   nbrs  = (const int*)d_in[2];
    const int*   resi  = (const int*)d_in[3];
    const int*   chain = (const int*)d_in[4];
    const int*   batch = (const int*)d_in[5];
    const float* maskp = (const float*)d_in[6];
    const float* Wrel  = (const float*)d_in[7];
    const float* Wdmap = (const float*)d_in[8];
    const float* Wdist = (const float*)d_in[9];
    const float* Wdir  = (const float*)d_in[10];
    const float* Wrot  = (const float*)d_in[11];
    const float* Wvec  = (const float*)d_in[12];
    const float* lng   = (const float*)d_in[13];
    const float* lnb   = (const float*)d_in[14];
    const float* W1    = (const float*)d_in[15];
    const float* b1    = (const float*)d_in[16];
    const float* W2    = (const float*)d_in[17];
    const float* b2    = (const float*)d_in[18];

    float* outPair = (float*)d_out;
    float* outMask = outPair + (long)Ntot * KC * PC;

    cudaFuncSetAttribute(dsd_kernel, cudaFuncAttributeMaxDynamicSharedMemorySize, SMEMF * 4);
    int sms = 148;
    cudaDeviceGetAttribute(&sms, cudaDevAttrMultiProcessorCount, 0);

    dsd_kernel<<<sms, THREADS, SMEMF * 4>>>(
        pos, dmap, nbrs, resi, chain, batch, maskp,
        Wrel, Wdmap, Wdist, Wdir, Wrot, Wvec, lng, lnb, W1, b1, W2, b2,
        outPair, outMask);
}

// round 11
// speedup vs baseline: 3.9922x; 2.0115x over previous
#include <cuda_runtime.h>
#include <cuda_fp16.h>
#include <cstdint>
#include <math.h>

typedef unsigned long long ull;
typedef unsigned int u32;

#define Ntot 8192
#define KC   32
#define PC   64
#define KPAD  464            // 29 * 16
#define THREADS 512

// strides (in halfs)
#define S72   72             // 144B rows: F^T, WD, W2, Ph  (ldsm phase step 4 -> distinct)
#define S136  136            // 272B rows: W1, Hh

// ---- shared memory layout (float offsets) ----
#define OFF_WDH   0                        // half[464][72]  = 16704 fl
#define OFF_W1H   16704                    // half[64][136]  = 4352 fl
#define OFF_W2H   21056                    // half[128][72]  = 4608 fl
#define OFF_FT    25664                    // F^T half[464][72] = 16704 fl ; reused as Hh half[64][136]
#define OFF_P0    42368                    // fp32 [32][66] = 2112 (n0 proj)
#define OFF_P1    44480                    // fp32 [32][66] = 2112 (n1 proj)
#define OFF_PH    46592                    // pair half[64][72] = 2304 fl
#define OFF_PJ    48896                    // [2][32][17] = 1088
#define OFF_POSN  49984                    // 32
#define OFF_RN    50016                    // 24
#define OFF_SJ    50040                    // 64 ints
#define OFF_SREL  50104                    // 64
#define OFF_SSAME 50168                    // 64
#define OFF_SPM   50232                    // 64
#define SMEMF     50296                    // 201184 bytes

// ---- tensor-core helpers ----
#define LDSM4(q0, q1, q2, q3, addr) \
    asm volatile("ldmatrix.sync.aligned.m8n8.x4.shared.b16 {%0,%1,%2,%3}, [%4];" \
                 : "=r"(q0), "=r"(q1), "=r"(q2), "=r"(q3) : "r"(addr))
#define LDSM4T(q0, q1, q2, q3, addr) \
    asm volatile("ldmatrix.sync.aligned.m8n8.x4.trans.shared.b16 {%0,%1,%2,%3}, [%4];" \
                 : "=r"(q0), "=r"(q1), "=r"(q2), "=r"(q3) : "r"(addr))
#define MMA16816(d0, d1, d2, d3, q0, q1, q2, q3, p0, p1) \
    asm volatile("mma.sync.aligned.m16n8k16.row.col.f32.f16.f16.f32 " \
                 "{%0,%1,%2,%3}, {%4,%5,%6,%7}, {%8,%9}, {%0,%1,%2,%3};" \
                 : "+f"(d0), "+f"(d1), "+f"(d2), "+f"(d3) \
                 : "r"(q0), "r"(q1), "r"(q2), "r"(q3), "r"(p0), "r"(p1))

// ---------------- RBF: 16 bins, 3 exps, fp16 out at stride S72 ----------------
__device__ __forceinline__ void rbf16s(float d, __half* out) {
    const float SI = 0.72727272727f;   // 16/22
    const float G  = 1.06666666667f;   // 16/15
    const float Q  = 0.10273954f;      // exp(-2*G*G)
    float g = d * SI;
    int m = __float2int_rn(g * 0.9375f);
    m = m < 0 ? 0 : (m > 15 ? 15 : m);
    float u = g - (float)m * G;
    float peak = __expf(-u * u);
    float r = __expf(G * (2.0f * u - G));
    float s = __expf(-G * (2.0f * u + G));
    out[m * S72] = __float2half(peak);
    float v = peak;
#pragma unroll
    for (int st = 1; st <= 15; ++st) {
        v *= r; r *= Q;
        int i = m + st;
        if (i <= 15) out[i * S72] = __float2half(v);
    }
    v = peak;
#pragma unroll
    for (int st = 1; st <= 15; ++st) {
        v *= s; s *= Q;
        int i = m - st;
        if (i >= 0) out[i * S72] = __float2half(v);
    }
}

__device__ __forceinline__ void frames_from(const float* p,
                                            float e1[3], float e2[3], float e3[3], float t[3]) {
    t[0] = p[3]; t[1] = p[4]; t[2] = p[5];
    float v1x = p[6] - t[0], v1y = p[7] - t[1], v1z = p[8] - t[2];
    float v2x = p[0] - t[0], v2y = p[1] - t[1], v2z = p[2] - t[2];
    float n1 = sqrtf(v1x * v1x + v1y * v1y + v1z * v1z) + 1e-6f;
    e1[0] = v1x / n1; e1[1] = v1y / n1; e1[2] = v1z / n1;
    float dt = v2x * e1[0] + v2y * e1[1] + v2z * e1[2];
    float ux = v2x - dt * e1[0], uy = v2y - dt * e1[1], uz = v2z - dt * e1[2];
    float n2 = sqrtf(ux * ux + uy * uy + uz * uz) + 1e-6f;
    e2[0] = ux / n2; e2[1] = uy / n2; e2[2] = uz / n2;
    e3[0] = e1[1] * e2[2] - e1[2] * e2[1];
    e3[1] = e1[2] * e2[0] - e1[0] * e2[2];
    e3[2] = e1[0] * e2[1] - e1[1] * e2[0];
}

__device__ __forceinline__ float gelu_f(float x) {
    float c = 0.7978845608028654f * (x + 0.044715f * x * x * x);
    float t;
    asm("tanh.approx.f32 %0, %1;" : "=f"(t) : "f"(c));
    return 0.5f * x * (1.0f + t);
}

__global__ void __launch_bounds__(THREADS, 1)
dsd_kernel(const float* __restrict__ pos, const float* __restrict__ dmap,
           const int* __restrict__ nbrs, const int* __restrict__ resi,
           const int* __restrict__ chain, const int* __restrict__ batch,
           const float* __restrict__ maskp,
           const float* __restrict__ Wrel, const float* __restrict__ Wdmap,
           const float* __restrict__ Wdist, const float* __restrict__ Wdir,
           const float* __restrict__ Wrot, const float* __restrict__ Wvec,
           const float* __restrict__ lng, const float* __restrict__ lnb,
           const float* __restrict__ W1, const float* __restrict__ bias1,
           const float* __restrict__ W2, const float* __restrict__ bias2,
           float* __restrict__ outPair, float* __restrict__ outMask)
{
    extern __shared__ float sm[];
    const int tid = threadIdx.x;
    const int k   = tid & 31;         // lane
    const int wid = tid >> 5;         // warp id (0..15)
    const int mt  = wid & 3;          // mma m-tile (16 rows)
    const int nt  = wid >> 2;         // mma n-tile
    const int lkk = tid >> 4;         // LN: k
    const int ls  = tid & 15;         // LN: col quad

    __half* WDh = (__half*)(sm + OFF_WDH);
    __half* W1h = (__half*)(sm + OFF_W1H);
    __half* W2h = (__half*)(sm + OFF_W2H);
    __half* FT  = (__half*)(sm + OFF_FT);

    // ---- stage constant weights once (all fp16) ----
    for (int i = tid; i < KPAD * 64; i += THREADS) {
        int f = i >> 6, c = i & 63;
        float v;
        if (f < 400)      v = Wdist[f * 64 + c];
        else if (f < 416) v = Wdmap[(f - 400) * 64 + c];
        else if (f < 431) v = Wdir[(f - 416) * 64 + c];
        else if (f < 446) v = Wvec[(f - 431) * 64 + c];
        else if (f < 455) v = Wrot[(f - 446) * 64 + c];
        else              v = 0.0f;
        WDh[f * S72 + c] = __float2half(v);
    }
    for (int i = tid; i < 64 * 128; i += THREADS) {
        int p = i >> 7, h = i & 127;
        W1h[p * S136 + h] = __float2half(W1[i]);
    }
    for (int i = tid; i < 128 * 64; i += THREADS) {
        int j = i >> 6, c = i & 63;
        W2h[j * S72 + c] = __float2half(W2[i]);
    }

    float lgr[4], lbr[4], b1r[8], b2r[4];
#pragma unroll
    for (int i = 0; i < 4; ++i) {
        lgr[i] = lng[ls * 4 + i];
        lbr[i] = lnb[ls * 4 + i];
    }
#pragma unroll
    for (int t = 0; t < 4; ++t) {
        b1r[2 * t + 0] = bias1[nt * 32 + t * 8 + (k & 3) * 2 + 0];
        b1r[2 * t + 1] = bias1[nt * 32 + t * 8 + (k & 3) * 2 + 1];
    }
#pragma unroll
    for (int t = 0; t < 2; ++t) {
        b2r[2 * t + 0] = bias2[nt * 16 + t * 8 + (k & 3) * 2 + 0];
        b2r[2 * t + 1] = bias2[nt * 16 + t * 8 + (k & 3) * 2 + 1];
    }

    // mma base addresses (constant across iterations)
    const u32 FTS = (u32)__cvta_generic_to_shared(FT);
    const u32 WDS = (u32)__cvta_generic_to_shared(WDh);
    const u32 W1S_ = (u32)__cvta_generic_to_shared(W1h);
    const u32 W2S_ = (u32)__cvta_generic_to_shared(W2h);
    const u32 PhS = (u32)__cvta_generic_to_shared(sm + OFF_PH);
    // stage 4: A = F^T[K][M] trans-load; groups: bit4 -> k+8 rows, bit3 -> m+8 cols
    const u32 aAddr0 = FTS + ((k & 7) + ((k >> 4) & 1) * 8) * 144 + (mt * 16 + ((k >> 3) & 1) * 8) * 2;
    // B = W[K][N] trans-load (validated): bit3 -> k+8 rows, bit4 -> n+8 cols
    const u32 bAddr0 = WDS + ((k & 7) + ((k >> 3) & 1) * 8) * 144 + (nt * 16 + ((k >> 4) & 1) * 8) * 2;
    // MLP1: A = Ph[M][K] non-trans (validated pattern), B = W1h[K][N] trans
    const u32 aP0 = PhS + (mt * 16 + (k & 7) + ((k >> 3) & 1) * 8) * 144 + ((k >> 4) & 1) * 16;
    const u32 bW1 = W1S_ + ((k & 7) + ((k >> 3) & 1) * 8) * 272 + (nt * 32 + ((k >> 4) & 1) * 8) * 2;
    // MLP2: A = Hh[M][K] non-trans (Hh lives at OFF_FT, stride 136), B = W2h trans
    const u32 aH0 = FTS + (mt * 16 + (k & 7) + ((k >> 3) & 1) * 8) * 272 + ((k >> 4) & 1) * 16;
    const u32 bW2 = W2S_ + ((k & 7) + ((k >> 3) & 1) * 8) * 144 + (nt * 16 + ((k >> 4) & 1) * 8) * 2;

    __syncthreads();

    int* smi = (int*)sm;

    for (int n0 = blockIdx.x * 2; n0 < Ntot; n0 += gridDim.x * 2) {
        // ---------- stage 1: meta + frames + pos for both n ----------
        if (tid < 64) {
            int bb = tid >> 5, kk = tid & 31;
            int n = n0 + bb;
            int nb = nbrs[n * KC + kk];
            int j = nb < 0 ? 0 : nb;
            float valid = (nb != -1) ? 1.0f : 0.0f;
            smi[OFF_SJ + bb * 32 + kk] = j;
            int dr = resi[j] - resi[n];
            dr = dr < -32 ? -32 : (dr > 32 ? 32 : dr);
            smi[OFF_SREL + bb * 32 + kk] = dr + 32;
            float same = (chain[j] == chain[n] && batch[j] == batch[n]) ? 1.0f : 0.0f;
            sm[OFF_SSAME + bb * 32 + kk] = same;
            float pm = maskp[n] * maskp[j] * valid;
            sm[OFF_SPM + bb * 32 + kk] = pm;
            outMask[n * KC + kk] = pm;
        } else if (tid < 66) {
            int bb = tid - 64;
            float e1[3], e2[3], e3[3], t[3], prow[9];
#pragma unroll
            for (int i = 0; i < 9; ++i) prow[i] = pos[(n0 + bb) * 15 + i];
            frames_from(prow, e1, e2, e3, t);
#pragma unroll
            for (int r = 0; r < 3; ++r) {
                sm[OFF_RN + bb * 12 + r * 3 + 0] = e1[r];
                sm[OFF_RN + bb * 12 + r * 3 + 1] = e2[r];
                sm[OFF_RN + bb * 12 + r * 3 + 2] = e3[r];
            }
            sm[OFF_RN + bb * 12 + 9 + 0] = t[0];
            sm[OFF_RN + bb * 12 + 9 + 1] = t[1];
            sm[OFF_RN + bb * 12 + 9 + 2] = t[2];
        } else if (tid >= 96 && tid < 126) {
            int bb = (tid - 96) / 15, e = (tid - 96) % 15;
            sm[OFF_POSN + bb * 16 + e] = pos[(n0 + bb) * 15 + e];
        }
        __syncthreads();

        // ---------- stage 2: gather neighbor positions (stride 17 -> conflict-free reads) ----------
        for (int i = tid; i < 960; i += THREADS) {
            int bb = i / 480, r2 = i - bb * 480;
            int kk = r2 / 15, e = r2 - kk * 15;
            int j = smi[OFF_SJ + bb * 32 + kk];
            sm[OFF_PJ + bb * 544 + kk * 17 + e] = pos[j * 15 + e];
        }
        __syncthreads();

        // ---------- stage 3: build features TRANSPOSED (F^T[f][row], conflict-free stores) ----------
        for (int bb = 0; bb < 2; ++bb) {
            __half* fT = FT + (bb * 32 + k);      // element f at fT[f*S72]
            const float* pn = sm + OFF_POSN + bb * 16;
            const float* pj = sm + OFF_PJ + bb * 544 + k * 17;
            const float* rn = sm + OFF_RN + bb * 12;
            {   // distance pair dp = wid (0..15)
                int a = wid / 5, c5 = wid - a * 5;
                float dx = pn[a * 3 + 0] - pj[c5 * 3 + 0];
                float dy = pn[a * 3 + 1] - pj[c5 * 3 + 1];
                float dz = pn[a * 3 + 2] - pj[c5 * 3 + 2];
                float d = sqrtf(dx * dx + dy * dy + dz * dz);
                rbf16s(d, fT + (wid * 16) * S72);
            }
            if (wid < 9) {   // dp = 16 + wid
                int dp = 16 + wid;
                int a = dp / 5, c5 = dp - a * 5;
                float dx = pn[a * 3 + 0] - pj[c5 * 3 + 0];
                float dy = pn[a * 3 + 1] - pj[c5 * 3 + 1];
                float dz = pn[a * 3 + 2] - pj[c5 * 3 + 2];
                float d = sqrtf(dx * dx + dy * dy + dz * dz);
                rbf16s(d, fT + (dp * 16) * S72);
            } else if (wid == 9) {   // dmap rbf, masked
                int j = smi[OFF_SJ + bb * 32 + k];
                float pm = sm[OFF_SPM + bb * 32 + k];
                float dval = __ldg(&dmap[(long)(n0 + bb) * Ntot + j]);
                if (pm > 0.0f) {
                    rbf16s(dval, fT + 400 * S72);
                } else {
                    __half z = __float2half(0.0f);
#pragma unroll
                    for (int i = 0; i < 16; ++i) fT[(400 + i) * S72] = z;
                }
            } else if (wid < 15) {   // rel_vec + dirs, atom a = wid-10
                int a = wid - 10;
                float v0 = pj[a * 3 + 0] - rn[9 + 0];
                float v1 = pj[a * 3 + 1] - rn[9 + 1];
                float v2 = pj[a * 3 + 2] - rn[9 + 2];
                float rv[3];
#pragma unroll
                for (int i = 0; i < 3; ++i)
                    rv[i] = rn[0 + i] * v0 + rn[3 + i] * v1 + rn[6 + i] * v2;
                float nr = sqrtf(rv[0] * rv[0] + rv[1] * rv[1] + rv[2] * rv[2]);
                float inv = 1.0f / (nr + 1e-6f);
#pragma unroll
                for (int i = 0; i < 3; ++i) {
                    fT[(416 + a * 3 + i) * S72] = __float2half(rv[i] * inv);
                    fT[(431 + a * 3 + i) * S72] = __float2half(rv[i] * 0.1f);
                }
            } else {   // wid == 15: rotation features
                float e1j[3], e2j[3], e3j[3], tj[3];
                frames_from(pj, e1j, e2j, e3j, tj);
#pragma unroll
                for (int i = 0; i < 3; ++i) {
                    float r0 = rn[0 + i], r1 = rn[3 + i], r2 = rn[6 + i];
                    fT[(446 + i * 3 + 0) * S72] = __float2half(r0 * e1j[0] + r1 * e1j[1] + r2 * e1j[2]);
                    fT[(446 + i * 3 + 1) * S72] = __float2half(r0 * e2j[0] + r1 * e2j[1] + r2 * e2j[2]);
                    fT[(446 + i * 3 + 2) * S72] = __float2half(r0 * e3j[0] + r1 * e3j[1] + r2 * e3j[2]);
                }
            }
        }
        // zero K-pad rows 455..463 (cols 0..63)
        {
            __half z = __float2half(0.0f);
            for (int i = tid; i < 9 * 64; i += THREADS) {
                int r = 455 + i / 64, c = i - (i / 64) * 64;
                FT[r * S72 + c] = z;
            }
        }
        __syncthreads();

        // ---------- stage 4: projection GEMM (A = F^T trans-loaded) ----------
        {
            float d0 = 0.f, d1 = 0.f, d2 = 0.f, d3 = 0.f;
            float d4 = 0.f, d5 = 0.f, d6 = 0.f, d7 = 0.f;
            u32 aA = aAddr0, bA = bAddr0;
#pragma unroll 1
            for (int s = 0; s < 29; ++s) {
                u32 ra0, ra1, ra2, ra3, rb0, rb1, rb2, rb3;
                LDSM4T(ra0, ra1, ra2, ra3, aA);
                LDSM4T(rb0, rb1, rb2, rb3, bA);
                aA += 2304;               // 16 k-rows * 144B
                bA += 2304;
                MMA16816(d0, d1, d2, d3, ra0, ra1, ra2, ra3, rb0, rb1);
                MMA16816(d4, d5, d6, d7, ra0, ra1, ra2, ra3, rb2, rb3);
            }
            float* P = sm + ((mt >> 1) ? OFF_P1 : OFF_P0);
            int kk1 = (mt & 1) * 16 + (k >> 2);
            int kk2 = kk1 + 8;
            int col = nt * 16 + (k & 3) * 2;
            *reinterpret_cast<float2*>(P + kk1 * 66 + col)     = make_float2(d0, d1);
            *reinterpret_cast<float2*>(P + kk2 * 66 + col)     = make_float2(d2, d3);
            *reinterpret_cast<float2*>(P + kk1 * 66 + col + 8) = make_float2(d4, d5);
            *reinterpret_cast<float2*>(P + kk2 * 66 + col + 8) = make_float2(d6, d7);
        }
        __syncthreads();

        // ---------- stage 5: + Wrel, LayerNorm -> Ph (fp16 [64][72]) ----------
        {
            float a0 = sm[OFF_P0 + lkk * 66 + ls * 4 + 0];
            float a1 = sm[OFF_P0 + lkk * 66 + ls * 4 + 1];
            float a2 = sm[OFF_P0 + lkk * 66 + ls * 4 + 2];
            float a3 = sm[OFF_P0 + lkk * 66 + ls * 4 + 3];
            float c0 = sm[OFF_P1 + lkk * 66 + ls * 4 + 0];
            float c1 = sm[OFF_P1 + lkk * 66 + ls * 4 + 1];
            float c2 = sm[OFF_P1 + lkk * 66 + ls * 4 + 2];
            float c3 = sm[OFF_P1 + lkk * 66 + ls * 4 + 3];
            {
                int rel = smi[OFF_SREL + lkk];
                float same = sm[OFF_SSAME + lkk];
                float4 wr = __ldg(reinterpret_cast<const float4*>(Wrel) + rel * 16 + ls);
                a0 = fmaf(same, wr.x, a0); a1 = fmaf(same, wr.y, a1);
                a2 = fmaf(same, wr.z, a2); a3 = fmaf(same, wr.w, a3);
            }
            {
                int rel = smi[OFF_SREL + 32 + lkk];
                float same = sm[OFF_SSAME + 32 + lkk];
                float4 wr = __ldg(reinterpret_cast<const float4*>(Wrel) + rel * 16 + ls);
                c0 = fmaf(same, wr.x, c0); c1 = fmaf(same, wr.y, c1);
                c2 = fmaf(same, wr.z, c2); c3 = fmaf(same, wr.w, c3);
            }
            __half2* ph2 = (__half2*)(sm + OFF_PH);
            // LN n0 -> Ph row lkk
            {
                float ssum = a0 + a1 + a2 + a3;
                ssum += __shfl_xor_sync(0xffffffffu, ssum, 8);
                ssum += __shfl_xor_sync(0xffffffffu, ssum, 4);
                ssum += __shfl_xor_sync(0xffffffffu, ssum, 2);
                ssum += __shfl_xor_sync(0xffffffffu, ssum, 1);
                float mu = ssum * 0.015625f;
                float e0 = a0 - mu, e1 = a1 - mu, e2 = a2 - mu, e3 = a3 - mu;
                float sq = e0 * e0 + e1 * e1 + e2 * e2 + e3 * e3;
                sq += __shfl_xor_sync(0xffffffffu, sq, 8);
                sq += __shfl_xor_sync(0xffffffffu, sq, 4);
                sq += __shfl_xor_sync(0xffffffffu, sq, 2);
                sq += __shfl_xor_sync(0xffffffffu, sq, 1);
                float inv = rsqrtf(sq * 0.015625f + 1e-5f);
                ph2[lkk * 36 + ls * 2 + 0] = __floats2half2_rn(lgr[0] * e0 * inv + lbr[0],
                                                               lgr[1] * e1 * inv + lbr[1]);
                ph2[lkk * 36 + ls * 2 + 1] = __floats2half2_rn(lgr[2] * e2 * inv + lbr[2],
                                                               lgr[3] * e3 * inv + lbr[3]);
            }
            // LN n1 -> Ph row 32+lkk
            {
                float ssum = c0 + c1 + c2 + c3;
                ssum += __shfl_xor_sync(0xffffffffu, ssum, 8);
                ssum += __shfl_xor_sync(0xffffffffu, ssum, 4);
                ssum += __shfl_xor_sync(0xffffffffu, ssum, 2);
                ssum += __shfl_xor_sync(0xffffffffu, ssum, 1);
                float mu = ssum * 0.015625f;
                float e0 = c0 - mu, e1 = c1 - mu, e2 = c2 - mu, e3 = c3 - mu;
                float sq = e0 * e0 + e1 * e1 + e2 * e2 + e3 * e3;
                sq += __shfl_xor_sync(0xffffffffu, sq, 8);
                sq += __shfl_xor_sync(0xffffffffu, sq, 4);
                sq += __shfl_xor_sync(0xffffffffu, sq, 2);
                sq += __shfl_xor_sync(0xffffffffu, sq, 1);
                float inv = rsqrtf(sq * 0.015625f + 1e-5f);
                ph2[(32 + lkk) * 36 + ls * 2 + 0] = __floats2half2_rn(lgr[0] * e0 * inv + lbr[0],
                                                                      lgr[1] * e1 * inv + lbr[1]);
                ph2[(32 + lkk) * 36 + ls * 2 + 1] = __floats2half2_rn(lgr[2] * e2 * inv + lbr[2],
                                                                      lgr[3] * e3 * inv + lbr[3]);
            }
        }
        __syncthreads();

        // ---------- stage 6: MLP1 (64x64x128) via mma; gelu; Hh fp16 into FT region ----------
        {
            float c[16];
#pragma unroll
            for (int j = 0; j < 16; ++j) c[j] = 0.0f;
            u32 aA = aP0, bA = bW1;
#pragma unroll
            for (int s = 0; s < 4; ++s) {
                u32 ra0, ra1, ra2, ra3, rb0, rb1, rb2, rb3, rc0, rc1, rc2, rc3;
                LDSM4(ra0, ra1, ra2, ra3, aA);
                LDSM4T(rb0, rb1, rb2, rb3, bA);
                LDSM4T(rc0, rc1, rc2, rc3, bA + 32);
                aA += 32;                 // 16 halfs along K
                bA += 4352;               // 16 k-rows * 272B
                MMA16816(c[0],  c[1],  c[2],  c[3],  ra0, ra1, ra2, ra3, rb0, rb1);
                MMA16816(c[4],  c[5],  c[6],  c[7],  ra0, ra1, ra2, ra3, rb2, rb3);
                MMA16816(c[8],  c[9],  c[10], c[11], ra0, ra1, ra2, ra3, rc0, rc1);
                MMA16816(c[12], c[13], c[14], c[15], ra0, ra1, ra2, ra3, rc2, rc3);
            }
            __half2* hh2 = (__half2*)(sm + OFF_FT);
            int r1 = mt * 16 + (k >> 2), r2 = r1 + 8;
#pragma unroll
            for (int t = 0; t < 4; ++t) {
                float g0 = gelu_f(c[4 * t + 0] + b1r[2 * t + 0]);
                float g1 = gelu_f(c[4 * t + 1] + b1r[2 * t + 1]);
                float g2 = gelu_f(c[4 * t + 2] + b1r[2 * t + 0]);
                float g3 = gelu_f(c[4 * t + 3] + b1r[2 * t + 1]);
                int cw = nt * 16 + t * 4 + (k & 3);
                hh2[r1 * 68 + cw] = __floats2half2_rn(g0, g1);
                hh2[r2 * 68 + cw] = __floats2half2_rn(g2, g3);
            }
        }
        __syncthreads();

        // ---------- stage 7: MLP2 (64x128x64) via mma; bias; write gmem ----------
        {
            float d0 = 0.f, d1 = 0.f, d2 = 0.f, d3 = 0.f;
            float d4 = 0.f, d5 = 0.f, d6 = 0.f, d7 = 0.f;
            u32 aA = aH0, bA = bW2;
#pragma unroll
            for (int s = 0; s < 8; ++s) {
                u32 ra0, ra1, ra2, ra3, rb0, rb1, rb2, rb3;
                LDSM4(ra0, ra1, ra2, ra3, aA);
                LDSM4T(rb0, rb1, rb2, rb3, bA);
                aA += 32;
                bA += 2304;
                MMA16816(d0, d1, d2, d3, ra0, ra1, ra2, ra3, rb0, rb1);
                MMA16816(d4, d5, d6, d7, ra0, ra1, ra2, ra3, rb2, rb3);
            }
            d0 += b2r[0]; d1 += b2r[1]; d2 += b2r[0]; d3 += b2r[1];
            d4 += b2r[2]; d5 += b2r[3]; d6 += b2r[2]; d7 += b2r[3];
            int r1 = mt * 16 + (k >> 2), r2 = r1 + 8;
            int col = nt * 16 + (k & 3) * 2;
            long i1 = ((long)(n0 + (r1 >> 5)) * 32 + (r1 & 31)) * 64;
            long i2 = ((long)(n0 + (r2 >> 5)) * 32 + (r2 & 31)) * 64;
            *reinterpret_cast<float2*>(outPair + i1 + col)     = make_float2(d0, d1);
            *reinterpret_cast<float2*>(outPair + i2 + col)     = make_float2(d2, d3);
            *reinterpret_cast<float2*>(outPair + i1 + col + 8) = make_float2(d4, d5);
            *reinterpret_cast<float2*>(outPair + i2 + col + 8) = make_float2(d6, d7);
        }
        __syncthreads();   // Hh / Ph / P0/P1 reuse next iteration
    }
}

extern "C" void kernel_launch(void* const* d_in, const int* in_sizes, int n_in,
                              void* d_out, int out_size) {
    const float* pos   = (const float*)d_in[0];
    const float* dmap  = (const float*)d_in[1];
    const int*   nbrs  = (const int*)d_in[2];
    const int*   resi  = (const int*)d_in[3];
    const int*   chain = (const int*)d_in[4];
    const int*   batch = (const int*)d_in[5];
    const float* maskp = (const float*)d_in[6];
    const float* Wrel  = (const float*)d_in[7];
    const float* Wdmap = (const float*)d_in[8];
    const float* Wdist = (const float*)d_in[9];
    const float* Wdir  = (const float*)d_in[10];
    const float* Wrot  = (const float*)d_in[11];
    const float* Wvec  = (const float*)d_in[12];
    const float* lng   = (const float*)d_in[13];
    const float* lnb   = (const float*)d_in[14];
    const float* W1    = (const float*)d_in[15];
    const float* b1    = (const float*)d_in[16];
    const float* W2    = (const float*)d_in[17];
    const float* b2    = (const float*)d_in[18];

    float* outPair = (float*)d_out;
    float* outMask = outPair + (long)Ntot * KC * PC;

    cudaFuncSetAttribute(dsd_kernel, cudaFuncAttributeMaxDynamicSharedMemorySize, SMEMF * 4);
    int sms = 148;
    cudaDeviceGetAttribute(&sms, cudaDevAttrMultiProcessorCount, 0);

    dsd_kernel<<<sms, THREADS, SMEMF * 4>>>(
        pos, dmap, nbrs, resi, chain, batch, maskp,
        Wrel, Wdmap, Wdist, Wdir, Wrot, Wvec, lng, lnb, W1, b1, W2, b2,
        outPair, outMask);
}

// round 12
// speedup vs baseline: 4.7334x; 1.1856x over previous
#include <cuda_runtime.h>
#include <cuda_fp16.h>
#include <cstdint>
#include <math.h>

typedef unsigned long long ull;
typedef unsigned int u32;

#define Ntot 8192
#define KC   32
#define PC   64
#define KPAD  464            // 29 * 16
#define THREADS 512

// strides (in halfs)
#define S72   72
#define S136  136

// ---- shared memory layout (float offsets) ----
#define OFF_WDH   0                        // half[464][72]  = 16704 fl
#define OFF_W1H   16704                    // half[64][136]  = 4352 fl
#define OFF_W2H   21056                    // half[128][72]  = 4608 fl
#define OFF_FT    25664                    // F^T half[464][72] = 16704 fl ; reused as Hh half[64][136]
#define OFF_P0    42368                    // fp32 [32][66]
#define OFF_P1    44480                    // fp32 [32][66]
#define OFF_PH    46592                    // pair half[64][72] = 2304 fl
#define OFF_PJ    48896                    // [par][2][32][17] = 2176
#define OFF_POSN  51072                    // [par][2][16] = 64
#define OFF_RN    51136                    // [par][2][12] = 48
#define OFF_SJ    51184                    // [par][64] ints = 128
#define OFF_SREL  51312                    // 128
#define OFF_SSAME 51440                    // 128
#define OFF_SPM   51568                    // 128
#define OFF_DM    51696                    // 128  (prefetched dmap values)
#define SMEMF     51824                    // 207296 bytes

// ---- tensor-core helpers ----
#define LDSM4(q0, q1, q2, q3, addr) \
    asm volatile("ldmatrix.sync.aligned.m8n8.x4.shared.b16 {%0,%1,%2,%3}, [%4];" \
                 : "=r"(q0), "=r"(q1), "=r"(q2), "=r"(q3) : "r"(addr))
#define LDSM4T(q0, q1, q2, q3, addr) \
    asm volatile("ldmatrix.sync.aligned.m8n8.x4.trans.shared.b16 {%0,%1,%2,%3}, [%4];" \
                 : "=r"(q0), "=r"(q1), "=r"(q2), "=r"(q3) : "r"(addr))
#define MMA16816(d0, d1, d2, d3, q0, q1, q2, q3, p0, p1) \
    asm volatile("mma.sync.aligned.m16n8k16.row.col.f32.f16.f16.f32 " \
                 "{%0,%1,%2,%3}, {%4,%5,%6,%7}, {%8,%9}, {%0,%1,%2,%3};" \
                 : "+f"(d0), "+f"(d1), "+f"(d2), "+f"(d3) \
                 : "r"(q0), "r"(q1), "r"(q2), "r"(q3), "r"(p0), "r"(p1))

// ---------------- RBF: 16 bins, 3 exps, fp16 out at stride S72 ----------------
__device__ __forceinline__ void rbf16s(float d, __half* out) {
    const float SI = 0.72727272727f;
    const float G  = 1.06666666667f;
    const float Q  = 0.10273954f;
    float g = d * SI;
    int m = __float2int_rn(g * 0.9375f);
    m = m < 0 ? 0 : (m > 15 ? 15 : m);
    float u = g - (float)m * G;
    float peak = __expf(-u * u);
    float r = __expf(G * (2.0f * u - G));
    float s = __expf(-G * (2.0f * u + G));
    out[m * S72] = __float2half(peak);
    float v = peak;
#pragma unroll
    for (int st = 1; st <= 15; ++st) {
        v *= r; r *= Q;
        int i = m + st;
        if (i <= 15) out[i * S72] = __float2half(v);
    }
    v = peak;
#pragma unroll
    for (int st = 1; st <= 15; ++st) {
        v *= s; s *= Q;
        int i = m - st;
        if (i >= 0) out[i * S72] = __float2half(v);
    }
}

__device__ __forceinline__ void frames_from(const float* p,
                                            float e1[3], float e2[3], float e3[3], float t[3]) {
    t[0] = p[3]; t[1] = p[4]; t[2] = p[5];
    float v1x = p[6] - t[0], v1y = p[7] - t[1], v1z = p[8] - t[2];
    float v2x = p[0] - t[0], v2y = p[1] - t[1], v2z = p[2] - t[2];
    float n1 = sqrtf(v1x * v1x + v1y * v1y + v1z * v1z) + 1e-6f;
    e1[0] = v1x / n1; e1[1] = v1y / n1; e1[2] = v1z / n1;
    float dt = v2x * e1[0] + v2y * e1[1] + v2z * e1[2];
    float ux = v2x - dt * e1[0], uy = v2y - dt * e1[1], uz = v2z - dt * e1[2];
    float n2 = sqrtf(ux * ux + uy * uy + uz * uz) + 1e-6f;
    e2[0] = ux / n2; e2[1] = uy / n2; e2[2] = uz / n2;
    e3[0] = e1[1] * e2[2] - e1[2] * e2[1];
    e3[1] = e1[2] * e2[0] - e1[0] * e2[2];
    e3[2] = e1[0] * e2[1] - e1[1] * e2[0];
}

__device__ __forceinline__ float gelu_f(float x) {
    float c = 0.7978845608028654f * (x + 0.044715f * x * x * x);
    float t;
    asm("tanh.approx.f32 %0, %1;" : "=f"(t) : "f"(c));
    return 0.5f * x * (1.0f + t);
}

__global__ void __launch_bounds__(THREADS, 1)
dsd_kernel(const float* __restrict__ pos, const float* __restrict__ dmap,
           const int* __restrict__ nbrs, const int* __restrict__ resi,
           const int* __restrict__ chain, const int* __restrict__ batch,
           const float* __restrict__ maskp,
           const float* __restrict__ Wrel, const float* __restrict__ Wdmap,
           const float* __restrict__ Wdist, const float* __restrict__ Wdir,
           const float* __restrict__ Wrot, const float* __restrict__ Wvec,
           const float* __restrict__ lng, const float* __restrict__ lnb,
           const float* __restrict__ W1, const float* __restrict__ bias1,
           const float* __restrict__ W2, const float* __restrict__ bias2,
           float* __restrict__ outPair, float* __restrict__ outMask)
{
    extern __shared__ float sm[];
    const int tid = threadIdx.x;
    const int k   = tid & 31;
    const int wid = tid >> 5;
    const int mt  = wid & 3;
    const int nt  = wid >> 2;
    const int lkk = tid >> 4;
    const int ls  = tid & 15;

    __half* WDh = (__half*)(sm + OFF_WDH);
    __half* W1h = (__half*)(sm + OFF_W1H);
    __half* W2h = (__half*)(sm + OFF_W2H);
    __half* FT  = (__half*)(sm + OFF_FT);

    // ---- stage constant weights once (all fp16) ----
    for (int i = tid; i < KPAD * 64; i += THREADS) {
        int f = i >> 6, c = i & 63;
        float v;
        if (f < 400)      v = Wdist[f * 64 + c];
        else if (f < 416) v = Wdmap[(f - 400) * 64 + c];
        else if (f < 431) v = Wdir[(f - 416) * 64 + c];
        else if (f < 446) v = Wvec[(f - 431) * 64 + c];
        else if (f < 455) v = Wrot[(f - 446) * 64 + c];
        else              v = 0.0f;
        WDh[f * S72 + c] = __float2half(v);
    }
    for (int i = tid; i < 64 * 128; i += THREADS) {
        int p = i >> 7, h = i & 127;
        W1h[p * S136 + h] = __float2half(W1[i]);
    }
    for (int i = tid; i < 128 * 64; i += THREADS) {
        int j = i >> 6, c = i & 63;
        W2h[j * S72 + c] = __float2half(W2[i]);
    }
    // K-pad rows 455..463 zeroed ONCE (Hh reuse never touches halfs >= 64*136=8704 < 455*72)
    {
        __half z = __float2half(0.0f);
        for (int i = tid; i < 9 * 64; i += THREADS) {
            int r = 455 + i / 64, c = i - (i / 64) * 64;
            FT[r * S72 + c] = z;
        }
    }

    float lgr[4], lbr[4], b1r[8], b2r[4];
#pragma unroll
    for (int i = 0; i < 4; ++i) {
        lgr[i] = lng[ls * 4 + i];
        lbr[i] = lnb[ls * 4 + i];
    }
#pragma unroll
    for (int t = 0; t < 4; ++t) {
        b1r[2 * t + 0] = bias1[nt * 32 + t * 8 + (k & 3) * 2 + 0];
        b1r[2 * t + 1] = bias1[nt * 32 + t * 8 + (k & 3) * 2 + 1];
    }
#pragma unroll
    for (int t = 0; t < 2; ++t) {
        b2r[2 * t + 0] = bias2[nt * 16 + t * 8 + (k & 3) * 2 + 0];
        b2r[2 * t + 1] = bias2[nt * 16 + t * 8 + (k & 3) * 2 + 1];
    }

    // validated mma base addresses
    const u32 FTS = (u32)__cvta_generic_to_shared(FT);
    const u32 WDS = (u32)__cvta_generic_to_shared(WDh);
    const u32 W1S_ = (u32)__cvta_generic_to_shared(W1h);
    const u32 W2S_ = (u32)__cvta_generic_to_shared(W2h);
    const u32 PhS = (u32)__cvta_generic_to_shared(sm + OFF_PH);
    const u32 aAddr0 = FTS + ((k & 7) + ((k >> 4) & 1) * 8) * 144 + (mt * 16 + ((k >> 3) & 1) * 8) * 2;
    const u32 bAddr0 = WDS + ((k & 7) + ((k >> 3) & 1) * 8) * 144 + (nt * 16 + ((k >> 4) & 1) * 8) * 2;
    const u32 aP0 = PhS + (mt * 16 + (k & 7) + ((k >> 3) & 1) * 8) * 144 + ((k >> 4) & 1) * 16;
    const u32 bW1 = W1S_ + ((k & 7) + ((k >> 3) & 1) * 8) * 272 + (nt * 32 + ((k >> 4) & 1) * 8) * 2;
    const u32 aH0 = FTS + (mt * 16 + (k & 7) + ((k >> 3) & 1) * 8) * 272 + ((k >> 4) & 1) * 16;
    const u32 bW2 = W2S_ + ((k & 7) + ((k >> 3) & 1) * 8) * 144 + (nt * 16 + ((k >> 4) & 1) * 8) * 2;

    int* smi = (int*)sm;
    const int stride2 = gridDim.x * 2;

    __syncthreads();

    // ================= PROLOGUE: fill par=0 buffers for n0 = bid*2 =================
    {
        int nb0 = blockIdx.x * 2;
        if (tid < 64) {
            int bb = tid >> 5, kk = tid & 31;
            int n = nb0 + bb;
            int nb = nbrs[n * KC + kk];
            int j = nb < 0 ? 0 : nb;
            float valid = (nb != -1) ? 1.0f : 0.0f;
            smi[OFF_SJ + bb * 32 + kk] = j;
            int dr = resi[j] - resi[n];
            dr = dr < -32 ? -32 : (dr > 32 ? 32 : dr);
            smi[OFF_SREL + bb * 32 + kk] = dr + 32;
            float same = (chain[j] == chain[n] && batch[j] == batch[n]) ? 1.0f : 0.0f;
            sm[OFF_SSAME + bb * 32 + kk] = same;
            float pm = maskp[n] * maskp[j] * valid;
            sm[OFF_SPM + bb * 32 + kk] = pm;
            outMask[n * KC + kk] = pm;
        } else if (tid < 66) {
            int bb = tid - 64;
            float e1[3], e2[3], e3[3], t[3], prow[9];
#pragma unroll
            for (int i = 0; i < 9; ++i) prow[i] = pos[(nb0 + bb) * 15 + i];
            frames_from(prow, e1, e2, e3, t);
#pragma unroll
            for (int r = 0; r < 3; ++r) {
                sm[OFF_RN + bb * 12 + r * 3 + 0] = e1[r];
                sm[OFF_RN + bb * 12 + r * 3 + 1] = e2[r];
                sm[OFF_RN + bb * 12 + r * 3 + 2] = e3[r];
            }
            sm[OFF_RN + bb * 12 + 9 + 0] = t[0];
            sm[OFF_RN + bb * 12 + 9 + 1] = t[1];
            sm[OFF_RN + bb * 12 + 9 + 2] = t[2];
        } else if (tid >= 96 && tid < 126) {
            int bb = (tid - 96) / 15, e = (tid - 96) % 15;
            sm[OFF_POSN + bb * 16 + e] = pos[(nb0 + bb) * 15 + e];
        }
        __syncthreads();
        for (int i = tid; i < 960; i += THREADS) {
            int bb = i / 480, r2 = i - bb * 480;
            int kk = r2 / 15, e = r2 - kk * 15;
            int j = smi[OFF_SJ + bb * 32 + kk];
            sm[OFF_PJ + bb * 544 + kk * 17 + e] = pos[j * 15 + e];
        }
        if (tid < 64) {
            int bb = tid >> 5;
            int j = smi[OFF_SJ + tid];
            sm[OFF_DM + tid] = __ldg(&dmap[(long)(nb0 + bb) * Ntot + j]);
        }
        __syncthreads();
    }

    int iter = 0;
    for (int n0 = blockIdx.x * 2; n0 < Ntot; n0 += stride2, ++iter) {
        const int par  = iter & 1;
        const int parn = par ^ 1;
        const int nN   = n0 + stride2;       // next iteration's base
        const bool hasNext = (nN < Ntot);

        // ---------- P3: build features into F^T from buffers[par] ----------
        for (int bb = 0; bb < 2; ++bb) {
            __half* fT = FT + (bb * 32 + k);
            const float* pn = sm + OFF_POSN + par * 32 + bb * 16;
            const float* pj = sm + OFF_PJ + par * 1088 + bb * 544 + k * 17;
            const float* rn = sm + OFF_RN + par * 24 + bb * 12;
            {
                int a = wid / 5, c5 = wid - a * 5;
                float dx = pn[a * 3 + 0] - pj[c5 * 3 + 0];
                float dy = pn[a * 3 + 1] - pj[c5 * 3 + 1];
                float dz = pn[a * 3 + 2] - pj[c5 * 3 + 2];
                float d = sqrtf(dx * dx + dy * dy + dz * dz);
                rbf16s(d, fT + (wid * 16) * S72);
            }
            if (wid < 9) {
                int dp = 16 + wid;
                int a = dp / 5, c5 = dp - a * 5;
                float dx = pn[a * 3 + 0] - pj[c5 * 3 + 0];
                float dy = pn[a * 3 + 1] - pj[c5 * 3 + 1];
                float dz = pn[a * 3 + 2] - pj[c5 * 3 + 2];
                float d = sqrtf(dx * dx + dy * dy + dz * dz);
                rbf16s(d, fT + (dp * 16) * S72);
            } else if (wid == 9) {
                float pm = sm[OFF_SPM + par * 64 + bb * 32 + k];
                float dval = sm[OFF_DM + par * 64 + bb * 32 + k];
                if (pm > 0.0f) {
                    rbf16s(dval, fT + 400 * S72);
                } else {
                    __half z = __float2half(0.0f);
#pragma unroll
                    for (int i = 0; i < 16; ++i) fT[(400 + i) * S72] = z;
                }
            } else if (wid < 15) {
                int a = wid - 10;
                float v0 = pj[a * 3 + 0] - rn[9 + 0];
                float v1 = pj[a * 3 + 1] - rn[9 + 1];
                float v2 = pj[a * 3 + 2] - rn[9 + 2];
                float rv[3];
#pragma unroll
                for (int i = 0; i < 3; ++i)
                    rv[i] = rn[0 + i] * v0 + rn[3 + i] * v1 + rn[6 + i] * v2;
                float nr = sqrtf(rv[0] * rv[0] + rv[1] * rv[1] + rv[2] * rv[2]);
                float inv = 1.0f / (nr + 1e-6f);
#pragma unroll
                for (int i = 0; i < 3; ++i) {
                    fT[(416 + a * 3 + i) * S72] = __float2half(rv[i] * inv);
                    fT[(431 + a * 3 + i) * S72] = __float2half(rv[i] * 0.1f);
                }
            } else {
                float e1j[3], e2j[3], e3j[3], tj[3];
                frames_from(pj, e1j, e2j, e3j, tj);
#pragma unroll
                for (int i = 0; i < 3; ++i) {
                    float r0 = rn[0 + i], r1 = rn[3 + i], r2 = rn[6 + i];
                    fT[(446 + i * 3 + 0) * S72] = __float2half(r0 * e1j[0] + r1 * e1j[1] + r2 * e1j[2]);
                    fT[(446 + i * 3 + 1) * S72] = __float2half(r0 * e2j[0] + r1 * e2j[1] + r2 * e2j[2]);
                    fT[(446 + i * 3 + 2) * S72] = __float2half(r0 * e3j[0] + r1 * e3j[1] + r2 * e3j[2]);
                }
            }
        }
        __syncthreads();

        // ---------- P4: projection GEMM + first-level prefetch for nN ----------
        int nbv = -1;
        float prowv[9];
        float posnv = 0.0f;
        if (hasNext) {
            if (tid < 64) {
                int bb = tid >> 5, kk = tid & 31;
                nbv = nbrs[(nN + bb) * KC + kk];
            } else if (tid < 66) {
                int bb = tid - 64;
#pragma unroll
                for (int i = 0; i < 9; ++i) prowv[i] = pos[(nN + bb) * 15 + i];
            } else if (tid >= 96 && tid < 126) {
                int bb = (tid - 96) / 15, e = (tid - 96) % 15;
                posnv = pos[(nN + bb) * 15 + e];
            }
        }
        {
            float d0 = 0.f, d1 = 0.f, d2 = 0.f, d3 = 0.f;
            float d4 = 0.f, d5 = 0.f, d6 = 0.f, d7 = 0.f;
            u32 aA = aAddr0, bA = bAddr0;
#pragma unroll 1
            for (int s = 0; s < 29; ++s) {
                u32 ra0, ra1, ra2, ra3, rb0, rb1, rb2, rb3;
                LDSM4T(ra0, ra1, ra2, ra3, aA);
                LDSM4T(rb0, rb1, rb2, rb3, bA);
                aA += 2304;
                bA += 2304;
                MMA16816(d0, d1, d2, d3, ra0, ra1, ra2, ra3, rb0, rb1);
                MMA16816(d4, d5, d6, d7, ra0, ra1, ra2, ra3, rb2, rb3);
            }
            float* P = sm + ((mt >> 1) ? OFF_P1 : OFF_P0);
            int kk1 = (mt & 1) * 16 + (k >> 2);
            int kk2 = kk1 + 8;
            int col = nt * 16 + (k & 3) * 2;
            *reinterpret_cast<float2*>(P + kk1 * 66 + col)     = make_float2(d0, d1);
            *reinterpret_cast<float2*>(P + kk2 * 66 + col)     = make_float2(d2, d3);
            *reinterpret_cast<float2*>(P + kk1 * 66 + col + 8) = make_float2(d4, d5);
            *reinterpret_cast<float2*>(P + kk2 * 66 + col + 8) = make_float2(d6, d7);
        }
        if (hasNext) {
            if (tid < 64) {
                int bb = tid >> 5, kk = tid & 31;
                int j = nbv < 0 ? 0 : nbv;
                smi[OFF_SJ + parn * 64 + bb * 32 + kk] = j;
            } else if (tid < 66) {
                int bb = tid - 64;
                float e1[3], e2[3], e3[3], t[3];
                frames_from(prowv, e1, e2, e3, t);
#pragma unroll
                for (int r = 0; r < 3; ++r) {
                    sm[OFF_RN + parn * 24 + bb * 12 + r * 3 + 0] = e1[r];
                    sm[OFF_RN + parn * 24 + bb * 12 + r * 3 + 1] = e2[r];
                    sm[OFF_RN + parn * 24 + bb * 12 + r * 3 + 2] = e3[r];
                }
                sm[OFF_RN + parn * 24 + bb * 12 + 9 + 0] = t[0];
                sm[OFF_RN + parn * 24 + bb * 12 + 9 + 1] = t[1];
                sm[OFF_RN + parn * 24 + bb * 12 + 9 + 2] = t[2];
            } else if (tid >= 96 && tid < 126) {
                int bb = (tid - 96) / 15, e = (tid - 96) % 15;
                sm[OFF_POSN + parn * 32 + bb * 16 + e] = posnv;
            }
        }
        __syncthreads();

        // ---------- P5: + Wrel, LayerNorm -> Ph ----------
        {
            float a0 = sm[OFF_P0 + lkk * 66 + ls * 4 + 0];
            float a1 = sm[OFF_P0 + lkk * 66 + ls * 4 + 1];
            float a2 = sm[OFF_P0 + lkk * 66 + ls * 4 + 2];
            float a3 = sm[OFF_P0 + lkk * 66 + ls * 4 + 3];
            float c0 = sm[OFF_P1 + lkk * 66 + ls * 4 + 0];
            float c1 = sm[OFF_P1 + lkk * 66 + ls * 4 + 1];
            float c2 = sm[OFF_P1 + lkk * 66 + ls * 4 + 2];
            float c3 = sm[OFF_P1 + lkk * 66 + ls * 4 + 3];
            {
                int rel = smi[OFF_SREL + par * 64 + lkk];
                float same = sm[OFF_SSAME + par * 64 + lkk];
                float4 wr = __ldg(reinterpret_cast<const float4*>(Wrel) + rel * 16 + ls);
                a0 = fmaf(same, wr.x, a0); a1 = fmaf(same, wr.y, a1);
                a2 = fmaf(same, wr.z, a2); a3 = fmaf(same, wr.w, a3);
            }
            {
                int rel = smi[OFF_SREL + par * 64 + 32 + lkk];
                float same = sm[OFF_SSAME + par * 64 + 32 + lkk];
                float4 wr = __ldg(reinterpret_cast<const float4*>(Wrel) + rel * 16 + ls);
                c0 = fmaf(same, wr.x, c0); c1 = fmaf(same, wr.y, c1);
                c2 = fmaf(same, wr.z, c2); c3 = fmaf(same, wr.w, c3);
            }
            __half2* ph2 = (__half2*)(sm + OFF_PH);
            {
                float ssum = a0 + a1 + a2 + a3;
                ssum += __shfl_xor_sync(0xffffffffu, ssum, 8);
                ssum += __shfl_xor_sync(0xffffffffu, ssum, 4);
                ssum += __shfl_xor_sync(0xffffffffu, ssum, 2);
                ssum += __shfl_xor_sync(0xffffffffu, ssum, 1);
                float mu = ssum * 0.015625f;
                float e0 = a0 - mu, e1 = a1 - mu, e2 = a2 - mu, e3 = a3 - mu;
                float sq = e0 * e0 + e1 * e1 + e2 * e2 + e3 * e3;
                sq += __shfl_xor_sync(0xffffffffu, sq, 8);
                sq += __shfl_xor_sync(0xffffffffu, sq, 4);
                sq += __shfl_xor_sync(0xffffffffu, sq, 2);
                sq += __shfl_xor_sync(0xffffffffu, sq, 1);
                float inv = rsqrtf(sq * 0.015625f + 1e-5f);
                ph2[lkk * 36 + ls * 2 + 0] = __floats2half2_rn(lgr[0] * e0 * inv + lbr[0],
                                                               lgr[1] * e1 * inv + lbr[1]);
                ph2[lkk * 36 + ls * 2 + 1] = __floats2half2_rn(lgr[2] * e2 * inv + lbr[2],
                                                               lgr[3] * e3 * inv + lbr[3]);
            }
            {
                float ssum = c0 + c1 + c2 + c3;
                ssum += __shfl_xor_sync(0xffffffffu, ssum, 8);
                ssum += __shfl_xor_sync(0xffffffffu, ssum, 4);
                ssum += __shfl_xor_sync(0xffffffffu, ssum, 2);
                ssum += __shfl_xor_sync(0xffffffffu, ssum, 1);
                float mu = ssum * 0.015625f;
                float e0 = c0 - mu, e1 = c1 - mu, e2 = c2 - mu, e3 = c3 - mu;
                float sq = e0 * e0 + e1 * e1 + e2 * e2 + e3 * e3;
                sq += __shfl_xor_sync(0xffffffffu, sq, 8);
                sq += __shfl_xor_sync(0xffffffffu, sq, 4);
                sq += __shfl_xor_sync(0xffffffffu, sq, 2);
                sq += __shfl_xor_sync(0xffffffffu, sq, 1);
                float inv = rsqrtf(sq * 0.015625f + 1e-5f);
                ph2[(32 + lkk) * 36 + ls * 2 + 0] = __floats2half2_rn(lgr[0] * e0 * inv + lbr[0],
                                                                      lgr[1] * e1 * inv + lbr[1]);
                ph2[(32 + lkk) * 36 + ls * 2 + 1] = __floats2half2_rn(lgr[2] * e2 * inv + lbr[2],
                                                                      lgr[3] * e3 * inv + lbr[3]);
            }
        }
        __syncthreads();

        // ---------- P6: MLP1 mma + second-level prefetch for nN ----------
        float gv0 = 0.0f, gv1 = 0.0f;
        int rjv = 0, rnv = 0, cjv = 0, cnv = 0, bjv = 0, bnv = 0;
        float mjv = 0.0f, mnv = 0.0f, dmv = 0.0f;
        if (hasNext) {
            {   // gather item 0: i = tid
                int bb = tid / 480, r2 = tid - bb * 480;
                int kk = r2 / 15, e = r2 - kk * 15;
                int j = smi[OFF_SJ + parn * 64 + bb * 32 + kk];
                gv0 = pos[j * 15 + e];
            }
            if (tid < 448) {   // gather item 1: i = tid + 512
                int i1 = tid + 512;
                int bb = i1 / 480, r2 = i1 - bb * 480;
                int kk = r2 / 15, e = r2 - kk * 15;
                int j = smi[OFF_SJ + parn * 64 + bb * 32 + kk];
                gv1 = pos[j * 15 + e];
            }
            if (tid < 64) {
                int bb = tid >> 5;
                int nn = nN + bb;
                int j = smi[OFF_SJ + parn * 64 + tid];
                rjv = resi[j]; rnv = resi[nn];
                cjv = chain[j]; cnv = chain[nn];
                bjv = batch[j]; bnv = batch[nn];
                mjv = maskp[j]; mnv = maskp[nn];
                dmv = __ldg(&dmap[(long)nn * Ntot + j]);
            }
        }
        {
            float c[16];
#pragma unroll
            for (int j = 0; j < 16; ++j) c[j] = 0.0f;
            u32 aA = aP0, bA = bW1;
#pragma unroll
            for (int s = 0; s < 4; ++s) {
                u32 ra0, ra1, ra2, ra3, rb0, rb1, rb2, rb3, rc0, rc1, rc2, rc3;
                LDSM4(ra0, ra1, ra2, ra3, aA);
                LDSM4T(rb0, rb1, rb2, rb3, bA);
                LDSM4T(rc0, rc1, rc2, rc3, bA + 32);
                aA += 32;
                bA += 4352;
                MMA16816(c[0],  c[1],  c[2],  c[3],  ra0, ra1, ra2, ra3, rb0, rb1);
                MMA16816(c[4],  c[5],  c[6],  c[7],  ra0, ra1, ra2, ra3, rb2, rb3);
                MMA16816(c[8],  c[9],  c[10], c[11], ra0, ra1, ra2, ra3, rc0, rc1);
                MMA16816(c[12], c[13], c[14], c[15], ra0, ra1, ra2, ra3, rc2, rc3);
            }
            __half2* hh2 = (__half2*)(sm + OFF_FT);
            int r1 = mt * 16 + (k >> 2), r2 = r1 + 8;
#pragma unroll
            for (int t = 0; t < 4; ++t) {
                float g0 = gelu_f(c[4 * t + 0] + b1r[2 * t + 0]);
                float g1 = gelu_f(c[4 * t + 1] + b1r[2 * t + 1]);
                float g2 = gelu_f(c[4 * t + 2] + b1r[2 * t + 0]);
                float g3 = gelu_f(c[4 * t + 3] + b1r[2 * t + 1]);
                int cw = nt * 16 + t * 4 + (k & 3);
                hh2[r1 * 68 + cw] = __floats2half2_rn(g0, g1);
                hh2[r2 * 68 + cw] = __floats2half2_rn(g2, g3);
            }
        }
        if (hasNext) {
            {
                int bb = tid / 480, r2 = tid - bb * 480;
                int kk = r2 / 15, e = r2 - kk * 15;
                sm[OFF_PJ + parn * 1088 + bb * 544 + kk * 17 + e] = gv0;
            }
            if (tid < 448) {
                int i1 = tid + 512;
                int bb = i1 / 480, r2 = i1 - bb * 480;
                int kk = r2 / 15, e = r2 - kk * 15;
                sm[OFF_PJ + parn * 1088 + bb * 544 + kk * 17 + e] = gv1;
            }
            if (tid < 64) {
                int bb = tid >> 5, kk = tid & 31;
                int dr = rjv - rnv;
                dr = dr < -32 ? -32 : (dr > 32 ? 32 : dr);
                smi[OFF_SREL + parn * 64 + tid] = dr + 32;
                float same = (cjv == cnv && bjv == bnv) ? 1.0f : 0.0f;
                sm[OFF_SSAME + parn * 64 + tid] = same;
                float valid = (nbv != -1) ? 1.0f : 0.0f;
                float pm = mnv * mjv * valid;
                sm[OFF_SPM + parn * 64 + tid] = pm;
                sm[OFF_DM + parn * 64 + tid] = dmv;
                outMask[(nN + bb) * KC + kk] = pm;
            }
        }
        __syncthreads();

        // ---------- P7: MLP2 mma + gmem write ----------
        {
            float d0 = 0.f, d1 = 0.f, d2 = 0.f, d3 = 0.f;
            float d4 = 0.f, d5 = 0.f, d6 = 0.f, d7 = 0.f;
            u32 aA = aH0, bA = bW2;
#pragma unroll
            for (int s = 0; s < 8; ++s) {
                u32 ra0, ra1, ra2, ra3, rb0, rb1, rb2, rb3;
                LDSM4(ra0, ra1, ra2, ra3, aA);
                LDSM4T(rb0, rb1, rb2, rb3, bA);
                aA += 32;
                bA += 2304;
                MMA16816(d0, d1, d2, d3, ra0, ra1, ra2, ra3, rb0, rb1);
                MMA16816(d4, d5, d6, d7, ra0, ra1, ra2, ra3, rb2, rb3);
            }
            d0 += b2r[0]; d1 += b2r[1]; d2 += b2r[0]; d3 += b2r[1];
            d4 += b2r[2]; d5 += b2r[3]; d6 += b2r[2]; d7 += b2r[3];
            int r1 = mt * 16 + (k >> 2), r2 = r1 + 8;
            int col = nt * 16 + (k & 3) * 2;
            long i1 = ((long)(n0 + (r1 >> 5)) * 32 + (r1 & 31)) * 64;
            long i2 = ((long)(n0 + (r2 >> 5)) * 32 + (r2 & 31)) * 64;
            *reinterpret_cast<float2*>(outPair + i1 + col)     = make_float2(d0, d1);
            *reinterpret_cast<float2*>(outPair + i2 + col)     = make_float2(d2, d3);
            *reinterpret_cast<float2*>(outPair + i1 + col + 8) = make_float2(d4, d5);
            *reinterpret_cast<float2*>(outPair + i2 + col + 8) = make_float2(d6, d7);
        }
        __syncthreads();
    }
}

extern "C" void kernel_launch(void* const* d_in, const int* in_sizes, int n_in,
                              void* d_out, int out_size) {
    const float* pos   = (const float*)d_in[0];
    const float* dmap  = (const float*)d_in[1];
    const int*   nbrs  = (const int*)d_in[2];
    const int*   resi  = (const int*)d_in[3];
    const int*   chain = (const int*)d_in[4];
    const int*   batch = (const int*)d_in[5];
    const float* maskp = (const float*)d_in[6];
    const float* Wrel  = (const float*)d_in[7];
    const float* Wdmap = (const float*)d_in[8];
    const float* Wdist = (const float*)d_in[9];
    const float* Wdir  = (const float*)d_in[10];
    const float* Wrot  = (const float*)d_in[11];
    const float* Wvec  = (const float*)d_in[12];
    const float* lng   = (const float*)d_in[13];
    const float* lnb   = (const float*)d_in[14];
    const float* W1    = (const float*)d_in[15];
    const float* b1    = (const float*)d_in[16];
    const float* W2    = (const float*)d_in[17];
    const float* b2    = (const float*)d_in[18];

    float* outPair = (float*)d_out;
    float* outMask = outPair + (long)Ntot * KC * PC;

    cudaFuncSetAttribute(dsd_kernel, cudaFuncAttributeMaxDynamicSharedMemorySize, SMEMF * 4);
    int sms = 148;
    cudaDeviceGetAttribute(&sms, cudaDevAttrMultiProcessorCount, 0);

    dsd_kernel<<<sms, THREADS, SMEMF * 4>>>(
        pos, dmap, nbrs, resi, chain, batch, maskp,
        Wrel, Wdmap, Wdist, Wdir, Wrot, Wvec, lng, lnb, W1, b1, W2, b2,
        outPair, outMask);
}

// round 13
// speedup vs baseline: 4.8651x; 1.0278x over previous
#include <cuda_runtime.h>
#include <cuda_fp16.h>
#include <cstdint>
#include <math.h>

typedef unsigned long long ull;
typedef unsigned int u32;

#define Ntot 8192
#define KC   32
#define PC   64
#define KPAD  464            // 29 * 16
#define THREADS 512

// strides (in halfs)
#define S72   72
#define S136  136

// ---- shared memory layout (float offsets) ----
#define OFF_WDH   0                        // half[464][72]  = 16704 fl
#define OFF_W1H   16704                    // half[64][136]  = 4352 fl
#define OFF_W2H   21056                    // half[128][72]  = 4608 fl
#define OFF_FT    25664                    // F^T half[464][72] = 16704 fl ; reused as Hh half[64][136]
#define OFF_P0    42368                    // fp32 [32][66]
#define OFF_P1    44480                    // fp32 [32][66]
#define OFF_PH    46592                    // pair half[64][72] = 2304 fl
#define OFF_PJ    48896                    // [par][2][32][17] = 2176
#define OFF_POSN  51072                    // [par][2][16] = 64
#define OFF_RN    51136                    // [par][2][12] = 48
#define OFF_SJ    51184                    // [par][64] ints = 128
#define OFF_SREL  51312                    // 128
#define OFF_SSAME 51440                    // 128
#define OFF_SPM   51568                    // 128
#define OFF_DM    51696                    // 128
#define SMEMF     51824                    // 207296 bytes

// ---- tensor-core helpers ----
#define LDSM4(q0, q1, q2, q3, addr) \
    asm volatile("ldmatrix.sync.aligned.m8n8.x4.shared.b16 {%0,%1,%2,%3}, [%4];" \
                 : "=r"(q0), "=r"(q1), "=r"(q2), "=r"(q3) : "r"(addr))
#define LDSM4T(q0, q1, q2, q3, addr) \
    asm volatile("ldmatrix.sync.aligned.m8n8.x4.trans.shared.b16 {%0,%1,%2,%3}, [%4];" \
                 : "=r"(q0), "=r"(q1), "=r"(q2), "=r"(q3) : "r"(addr))
#define MMA16816(d0, d1, d2, d3, q0, q1, q2, q3, p0, p1) \
    asm volatile("mma.sync.aligned.m16n8k16.row.col.f32.f16.f16.f32 " \
                 "{%0,%1,%2,%3}, {%4,%5,%6,%7}, {%8,%9}, {%0,%1,%2,%3};" \
                 : "+f"(d0), "+f"(d1), "+f"(d2), "+f"(d3) \
                 : "r"(q0), "r"(q1), "r"(q2), "r"(q3), "r"(p0), "r"(p1))

// ---------------- RBF: 16 bins, 3 exps, fp16 out at stride S72 ----------------
__device__ __forceinline__ void rbf16s(float d, __half* out) {
    const float SI = 0.72727272727f;
    const float G  = 1.06666666667f;
    const float Q  = 0.10273954f;
    float g = d * SI;
    int m = __float2int_rn(g * 0.9375f);
    m = m < 0 ? 0 : (m > 15 ? 15 : m);
    float u = g - (float)m * G;
    float peak = __expf(-u * u);
    float r = __expf(G * (2.0f * u - G));
    float s = __expf(-G * (2.0f * u + G));
    out[m * S72] = __float2half(peak);
    float v = peak;
#pragma unroll
    for (int st = 1; st <= 15; ++st) {
        v *= r; r *= Q;
        int i = m + st;
        if (i <= 15) out[i * S72] = __float2half(v);
    }
    v = peak;
#pragma unroll
    for (int st = 1; st <= 15; ++st) {
        v *= s; s *= Q;
        int i = m - st;
        if (i >= 0) out[i * S72] = __float2half(v);
    }
}

__device__ __forceinline__ void frames_from(const float* p,
                                            float e1[3], float e2[3], float e3[3], float t[3]) {
    t[0] = p[3]; t[1] = p[4]; t[2] = p[5];
    float v1x = p[6] - t[0], v1y = p[7] - t[1], v1z = p[8] - t[2];
    float v2x = p[0] - t[0], v2y = p[1] - t[1], v2z = p[2] - t[2];
    float n1 = sqrtf(v1x * v1x + v1y * v1y + v1z * v1z) + 1e-6f;
    e1[0] = v1x / n1; e1[1] = v1y / n1; e1[2] = v1z / n1;
    float dt = v2x * e1[0] + v2y * e1[1] + v2z * e1[2];
    float ux = v2x - dt * e1[0], uy = v2y - dt * e1[1], uz = v2z - dt * e1[2];
    float n2 = sqrtf(ux * ux + uy * uy + uz * uz) + 1e-6f;
    e2[0] = ux / n2; e2[1] = uy / n2; e2[2] = uz / n2;
    e3[0] = e1[1] * e2[2] - e1[2] * e2[1];
    e3[1] = e1[2] * e2[0] - e1[0] * e2[2];
    e3[2] = e1[0] * e2[1] - e1[1] * e2[0];
}

__device__ __forceinline__ float gelu_f(float x) {
    float c = 0.7978845608028654f * (x + 0.044715f * x * x * x);
    float t;
    asm("tanh.approx.f32 %0, %1;" : "=f"(t) : "f"(c));
    return 0.5f * x * (1.0f + t);
}

__global__ void __launch_bounds__(THREADS, 1)
dsd_kernel(const float* __restrict__ pos, const float* __restrict__ dmap,
           const int* __restrict__ nbrs, const int* __restrict__ resi,
           const int* __restrict__ chain, const int* __restrict__ batch,
           const float* __restrict__ maskp,
           const float* __restrict__ Wrel, const float* __restrict__ Wdmap,
           const float* __restrict__ Wdist, const float* __restrict__ Wdir,
           const float* __restrict__ Wrot, const float* __restrict__ Wvec,
           const float* __restrict__ lng, const float* __restrict__ lnb,
           const float* __restrict__ W1, const float* __restrict__ bias1,
           const float* __restrict__ W2, const float* __restrict__ bias2,
           float* __restrict__ outPair, float* __restrict__ outMask)
{
    extern __shared__ float sm[];
    const int tid = threadIdx.x;
    const int k   = tid & 31;
    const int wid = tid >> 5;
    const int mt  = wid & 3;
    const int nt  = wid >> 2;
    const int lkk = tid >> 4;
    const int ls  = tid & 15;

    __half* WDh = (__half*)(sm + OFF_WDH);
    __half* W1h = (__half*)(sm + OFF_W1H);
    __half* W2h = (__half*)(sm + OFF_W2H);
    __half* FT  = (__half*)(sm + OFF_FT);

    // ---- stage constant weights once (all fp16) ----
    for (int i = tid; i < KPAD * 64; i += THREADS) {
        int f = i >> 6, c = i & 63;
        float v;
        if (f < 400)      v = Wdist[f * 64 + c];
        else if (f < 416) v = Wdmap[(f - 400) * 64 + c];
        else if (f < 431) v = Wdir[(f - 416) * 64 + c];
        else if (f < 446) v = Wvec[(f - 431) * 64 + c];
        else if (f < 455) v = Wrot[(f - 446) * 64 + c];
        else              v = 0.0f;
        WDh[f * S72 + c] = __float2half(v);
    }
    for (int i = tid; i < 64 * 128; i += THREADS) {
        int p = i >> 7, h = i & 127;
        W1h[p * S136 + h] = __float2half(W1[i]);
    }
    for (int i = tid; i < 128 * 64; i += THREADS) {
        int j = i >> 6, c = i & 63;
        W2h[j * S72 + c] = __float2half(W2[i]);
    }
    {
        __half z = __float2half(0.0f);
        for (int i = tid; i < 9 * 64; i += THREADS) {
            int r = 455 + i / 64, c = i - (i / 64) * 64;
            FT[r * S72 + c] = z;
        }
    }

    float lgr[4], lbr[4], b1r[8], b2r[4];
#pragma unroll
    for (int i = 0; i < 4; ++i) {
        lgr[i] = lng[ls * 4 + i];
        lbr[i] = lnb[ls * 4 + i];
    }
#pragma unroll
    for (int t = 0; t < 4; ++t) {
        b1r[2 * t + 0] = bias1[nt * 32 + t * 8 + (k & 3) * 2 + 0];
        b1r[2 * t + 1] = bias1[nt * 32 + t * 8 + (k & 3) * 2 + 1];
    }
#pragma unroll
    for (int t = 0; t < 2; ++t) {
        b2r[2 * t + 0] = bias2[nt * 16 + t * 8 + (k & 3) * 2 + 0];
        b2r[2 * t + 1] = bias2[nt * 16 + t * 8 + (k & 3) * 2 + 1];
    }

    // validated mma base addresses
    const u32 FTS = (u32)__cvta_generic_to_shared(FT);
    const u32 WDS = (u32)__cvta_generic_to_shared(WDh);
    const u32 W1S_ = (u32)__cvta_generic_to_shared(W1h);
    const u32 W2S_ = (u32)__cvta_generic_to_shared(W2h);
    const u32 PhS = (u32)__cvta_generic_to_shared(sm + OFF_PH);
    const u32 aAddr0 = FTS + ((k & 7) + ((k >> 4) & 1) * 8) * 144 + (mt * 16 + ((k >> 3) & 1) * 8) * 2;
    const u32 bAddr0 = WDS + ((k & 7) + ((k >> 3) & 1) * 8) * 144 + (nt * 16 + ((k >> 4) & 1) * 8) * 2;
    const u32 aP0 = PhS + (mt * 16 + (k & 7) + ((k >> 3) & 1) * 8) * 144 + ((k >> 4) & 1) * 16;
    const u32 bW1 = W1S_ + ((k & 7) + ((k >> 3) & 1) * 8) * 272 + (nt * 32 + ((k >> 4) & 1) * 8) * 2;
    const u32 aH0 = FTS + (mt * 16 + (k & 7) + ((k >> 3) & 1) * 8) * 272 + ((k >> 4) & 1) * 16;
    const u32 bW2 = W2S_ + ((k & 7) + ((k >> 3) & 1) * 8) * 144 + (nt * 16 + ((k >> 4) & 1) * 8) * 2;

    int* smi = (int*)sm;
    const int stride2 = gridDim.x * 2;

    __syncthreads();

    // ================= PROLOGUE: fill par=0 buffers =================
    {
        int nb0 = blockIdx.x * 2;
        if (tid < 64) {
            int bb = tid >> 5, kk = tid & 31;
            int n = nb0 + bb;
            int nb = nbrs[n * KC + kk];
            int j = nb < 0 ? 0 : nb;
            float valid = (nb != -1) ? 1.0f : 0.0f;
            smi[OFF_SJ + bb * 32 + kk] = j;
            int dr = resi[j] - resi[n];
            dr = dr < -32 ? -32 : (dr > 32 ? 32 : dr);
            smi[OFF_SREL + bb * 32 + kk] = dr + 32;
            float same = (chain[j] == chain[n] && batch[j] == batch[n]) ? 1.0f : 0.0f;
            sm[OFF_SSAME + bb * 32 + kk] = same;
            float pm = maskp[n] * maskp[j] * valid;
            sm[OFF_SPM + bb * 32 + kk] = pm;
            outMask[n * KC + kk] = pm;
        } else if (tid < 66) {
            int bb = tid - 64;
            float e1[3], e2[3], e3[3], t[3], prow[9];
#pragma unroll
            for (int i = 0; i < 9; ++i) prow[i] = pos[(nb0 + bb) * 15 + i];
            frames_from(prow, e1, e2, e3, t);
#pragma unroll
            for (int r = 0; r < 3; ++r) {
                sm[OFF_RN + bb * 12 + r * 3 + 0] = e1[r];
                sm[OFF_RN + bb * 12 + r * 3 + 1] = e2[r];
                sm[OFF_RN + bb * 12 + r * 3 + 2] = e3[r];
            }
            sm[OFF_RN + bb * 12 + 9 + 0] = t[0];
            sm[OFF_RN + bb * 12 + 9 + 1] = t[1];
            sm[OFF_RN + bb * 12 + 9 + 2] = t[2];
        } else if (tid >= 96 && tid < 126) {
            int bb = (tid - 96) / 15, e = (tid - 96) % 15;
            sm[OFF_POSN + bb * 16 + e] = pos[(nb0 + bb) * 15 + e];
        }
        __syncthreads();
        for (int i = tid; i < 960; i += THREADS) {
            int bb = i / 480, r2 = i - bb * 480;
            int kk = r2 / 15, e = r2 - kk * 15;
            int j = smi[OFF_SJ + bb * 32 + kk];
            sm[OFF_PJ + bb * 544 + kk * 17 + e] = pos[j * 15 + e];
        }
        if (tid < 64) {
            int bb = tid >> 5;
            int j = smi[OFF_SJ + tid];
            sm[OFF_DM + tid] = __ldg(&dmap[(long)(nb0 + bb) * Ntot + j]);
        }
        __syncthreads();
    }

    int iter = 0;
    for (int n0 = blockIdx.x * 2; n0 < Ntot; n0 += stride2, ++iter) {
        const int par  = iter & 1;
        const int parn = par ^ 1;
        const int nN   = n0 + stride2;
        const bool hasNext = (nN < Ntot);

        // ---------- P3: build features into F^T from buffers[par] ----------
        for (int bb = 0; bb < 2; ++bb) {
            __half* fT = FT + (bb * 32 + k);
            const float* pn = sm + OFF_POSN + par * 32 + bb * 16;
            const float* pj = sm + OFF_PJ + par * 1088 + bb * 544 + k * 17;
            const float* rn = sm + OFF_RN + par * 24 + bb * 12;
            {
                int a = wid / 5, c5 = wid - a * 5;
                float dx = pn[a * 3 + 0] - pj[c5 * 3 + 0];
                float dy = pn[a * 3 + 1] - pj[c5 * 3 + 1];
                float dz = pn[a * 3 + 2] - pj[c5 * 3 + 2];
                float d = sqrtf(dx * dx + dy * dy + dz * dz);
                rbf16s(d, fT + (wid * 16) * S72);
            }
            if (wid < 9) {
                int dp = 16 + wid;
                int a = dp / 5, c5 = dp - a * 5;
                float dx = pn[a * 3 + 0] - pj[c5 * 3 + 0];
                float dy = pn[a * 3 + 1] - pj[c5 * 3 + 1];
                float dz = pn[a * 3 + 2] - pj[c5 * 3 + 2];
                float d = sqrtf(dx * dx + dy * dy + dz * dz);
                rbf16s(d, fT + (dp * 16) * S72);
            } else if (wid == 9) {
                float pm = sm[OFF_SPM + par * 64 + bb * 32 + k];
                float dval = sm[OFF_DM + par * 64 + bb * 32 + k];
                if (pm > 0.0f) {
                    rbf16s(dval, fT + 400 * S72);
                } else {
                    __half z = __float2half(0.0f);
#pragma unroll
                    for (int i = 0; i < 16; ++i) fT[(400 + i) * S72] = z;
                }
            } else if (wid < 15) {
                int a = wid - 10;
                float v0 = pj[a * 3 + 0] - rn[9 + 0];
                float v1 = pj[a * 3 + 1] - rn[9 + 1];
                float v2 = pj[a * 3 + 2] - rn[9 + 2];
                float rv[3];
#pragma unroll
                for (int i = 0; i < 3; ++i)
                    rv[i] = rn[0 + i] * v0 + rn[3 + i] * v1 + rn[6 + i] * v2;
                float nr = sqrtf(rv[0] * rv[0] + rv[1] * rv[1] + rv[2] * rv[2]);
                float inv = 1.0f / (nr + 1e-6f);
#pragma unroll
                for (int i = 0; i < 3; ++i) {
                    fT[(416 + a * 3 + i) * S72] = __float2half(rv[i] * inv);
                    fT[(431 + a * 3 + i) * S72] = __float2half(rv[i] * 0.1f);
                }
            } else {
                float e1j[3], e2j[3], e3j[3], tj[3];
                frames_from(pj, e1j, e2j, e3j, tj);
#pragma unroll
                for (int i = 0; i < 3; ++i) {
                    float r0 = rn[0 + i], r1 = rn[3 + i], r2 = rn[6 + i];
                    fT[(446 + i * 3 + 0) * S72] = __float2half(r0 * e1j[0] + r1 * e1j[1] + r2 * e1j[2]);
                    fT[(446 + i * 3 + 1) * S72] = __float2half(r0 * e2j[0] + r1 * e2j[1] + r2 * e2j[2]);
                    fT[(446 + i * 3 + 2) * S72] = __float2half(r0 * e3j[0] + r1 * e3j[1] + r2 * e3j[2]);
                }
            }
        }
        __syncthreads();

        // ---------- P4: Wrel prefetch + first-level prefetch + pipelined GEMM ----------
        float4 wrA, wrC;
        {
            int relA = smi[OFF_SREL + par * 64 + lkk];
            int relC = smi[OFF_SREL + par * 64 + 32 + lkk];
            wrA = __ldg(reinterpret_cast<const float4*>(Wrel) + relA * 16 + ls);
            wrC = __ldg(reinterpret_cast<const float4*>(Wrel) + relC * 16 + ls);
        }
        int nbv = -1;
        float posnv = 0.0f;
        if (hasNext) {
            if (tid < 64) {
                int bb = tid >> 5, kk = tid & 31;
                nbv = nbrs[(nN + bb) * KC + kk];
            } else if (tid >= 96 && tid < 126) {
                int bb = (tid - 96) / 15, e = (tid - 96) % 15;
                posnv = pos[(nN + bb) * 15 + e];
            }
        }
        {
            float d0 = 0.f, d1 = 0.f, d2 = 0.f, d3 = 0.f;
            float d4 = 0.f, d5 = 0.f, d6 = 0.f, d7 = 0.f;
            u32 aA = aAddr0, bA = bAddr0;
            u32 xa0, xa1, xa2, xa3, xb0, xb1, xb2, xb3;
            u32 ya0, ya1, ya2, ya3, yb0, yb1, yb2, yb3;
            LDSM4T(xa0, xa1, xa2, xa3, aA);
            LDSM4T(xb0, xb1, xb2, xb3, bA);
#pragma unroll 1
            for (int s = 0; s < 14; ++s) {
                aA += 2304; bA += 2304;
                LDSM4T(ya0, ya1, ya2, ya3, aA);
                LDSM4T(yb0, yb1, yb2, yb3, bA);
                MMA16816(d0, d1, d2, d3, xa0, xa1, xa2, xa3, xb0, xb1);
                MMA16816(d4, d5, d6, d7, xa0, xa1, xa2, xa3, xb2, xb3);
                aA += 2304; bA += 2304;
                LDSM4T(xa0, xa1, xa2, xa3, aA);
                LDSM4T(xb0, xb1, xb2, xb3, bA);
                MMA16816(d0, d1, d2, d3, ya0, ya1, ya2, ya3, yb0, yb1);
                MMA16816(d4, d5, d6, d7, ya0, ya1, ya2, ya3, yb2, yb3);
            }
            MMA16816(d0, d1, d2, d3, xa0, xa1, xa2, xa3, xb0, xb1);
            MMA16816(d4, d5, d6, d7, xa0, xa1, xa2, xa3, xb2, xb3);

            float* P = sm + ((mt >> 1) ? OFF_P1 : OFF_P0);
            int kk1 = (mt & 1) * 16 + (k >> 2);
            int kk2 = kk1 + 8;
            int col = nt * 16 + (k & 3) * 2;
            *reinterpret_cast<float2*>(P + kk1 * 66 + col)     = make_float2(d0, d1);
            *reinterpret_cast<float2*>(P + kk2 * 66 + col)     = make_float2(d2, d3);
            *reinterpret_cast<float2*>(P + kk1 * 66 + col + 8) = make_float2(d4, d5);
            *reinterpret_cast<float2*>(P + kk2 * 66 + col + 8) = make_float2(d6, d7);
        }
        if (hasNext) {
            if (tid < 64) {
                int bb = tid >> 5, kk = tid & 31;
                int j = nbv < 0 ? 0 : nbv;
                smi[OFF_SJ + parn * 64 + bb * 32 + kk] = j;
            } else if (tid >= 96 && tid < 126) {
                int bb = (tid - 96) / 15, e = (tid - 96) % 15;
                sm[OFF_POSN + parn * 32 + bb * 16 + e] = posnv;
            }
        }
        __syncthreads();

        // ---------- P5: + Wrel, LayerNorm -> Ph ; frames for nN from POSN[parn] ----------
        if (hasNext && tid < 2) {
            int bb = tid;
            float e1[3], e2[3], e3[3], t[3];
            frames_from(sm + OFF_POSN + parn * 32 + bb * 16, e1, e2, e3, t);
#pragma unroll
            for (int r = 0; r < 3; ++r) {
                sm[OFF_RN + parn * 24 + bb * 12 + r * 3 + 0] = e1[r];
                sm[OFF_RN + parn * 24 + bb * 12 + r * 3 + 1] = e2[r];
                sm[OFF_RN + parn * 24 + bb * 12 + r * 3 + 2] = e3[r];
            }
            sm[OFF_RN + parn * 24 + bb * 12 + 9 + 0] = t[0];
            sm[OFF_RN + parn * 24 + bb * 12 + 9 + 1] = t[1];
            sm[OFF_RN + parn * 24 + bb * 12 + 9 + 2] = t[2];
        }
        {
            float a0 = sm[OFF_P0 + lkk * 66 + ls * 4 + 0];
            float a1 = sm[OFF_P0 + lkk * 66 + ls * 4 + 1];
            float a2 = sm[OFF_P0 + lkk * 66 + ls * 4 + 2];
            float a3 = sm[OFF_P0 + lkk * 66 + ls * 4 + 3];
            float c0 = sm[OFF_P1 + lkk * 66 + ls * 4 + 0];
            float c1 = sm[OFF_P1 + lkk * 66 + ls * 4 + 1];
            float c2 = sm[OFF_P1 + lkk * 66 + ls * 4 + 2];
            float c3 = sm[OFF_P1 + lkk * 66 + ls * 4 + 3];
            {
                float same = sm[OFF_SSAME + par * 64 + lkk];
                a0 = fmaf(same, wrA.x, a0); a1 = fmaf(same, wrA.y, a1);
                a2 = fmaf(same, wrA.z, a2); a3 = fmaf(same, wrA.w, a3);
            }
            {
                float same = sm[OFF_SSAME + par * 64 + 32 + lkk];
                c0 = fmaf(same, wrC.x, c0); c1 = fmaf(same, wrC.y, c1);
                c2 = fmaf(same, wrC.z, c2); c3 = fmaf(same, wrC.w, c3);
            }
            __half2* ph2 = (__half2*)(sm + OFF_PH);
            {
                float ssum = a0 + a1 + a2 + a3;
                ssum += __shfl_xor_sync(0xffffffffu, ssum, 8);
                ssum += __shfl_xor_sync(0xffffffffu, ssum, 4);
                ssum += __shfl_xor_sync(0xffffffffu, ssum, 2);
                ssum += __shfl_xor_sync(0xffffffffu, ssum, 1);
                float mu = ssum * 0.015625f;
                float e0 = a0 - mu, e1 = a1 - mu, e2 = a2 - mu, e3 = a3 - mu;
                float sq = e0 * e0 + e1 * e1 + e2 * e2 + e3 * e3;
                sq += __shfl_xor_sync(0xffffffffu, sq, 8);
                sq += __shfl_xor_sync(0xffffffffu, sq, 4);
                sq += __shfl_xor_sync(0xffffffffu, sq, 2);
                sq += __shfl_xor_sync(0xffffffffu, sq, 1);
                float inv = rsqrtf(sq * 0.015625f + 1e-5f);
                ph2[lkk * 36 + ls * 2 + 0] = __floats2half2_rn(lgr[0] * e0 * inv + lbr[0],
                                                               lgr[1] * e1 * inv + lbr[1]);
                ph2[lkk * 36 + ls * 2 + 1] = __floats2half2_rn(lgr[2] * e2 * inv + lbr[2],
                                                               lgr[3] * e3 * inv + lbr[3]);
            }
            {
                float ssum = c0 + c1 + c2 + c3;
                ssum += __shfl_xor_sync(0xffffffffu, ssum, 8);
                ssum += __shfl_xor_sync(0xffffffffu, ssum, 4);
                ssum += __shfl_xor_sync(0xffffffffu, ssum, 2);
                ssum += __shfl_xor_sync(0xffffffffu, ssum, 1);
                float mu = ssum * 0.015625f;
                float e0 = c0 - mu, e1 = c1 - mu, e2 = c2 - mu, e3 = c3 - mu;
                float sq = e0 * e0 + e1 * e1 + e2 * e2 + e3 * e3;
                sq += __shfl_xor_sync(0xffffffffu, sq, 8);
                sq += __shfl_xor_sync(0xffffffffu, sq, 4);
                sq += __shfl_xor_sync(0xffffffffu, sq, 2);
                sq += __shfl_xor_sync(0xffffffffu, sq, 1);
                float inv = rsqrtf(sq * 0.015625f + 1e-5f);
                ph2[(32 + lkk) * 36 + ls * 2 + 0] = __floats2half2_rn(lgr[0] * e0 * inv + lbr[0],
                                                                      lgr[1] * e1 * inv + lbr[1]);
                ph2[(32 + lkk) * 36 + ls * 2 + 1] = __floats2half2_rn(lgr[2] * e2 * inv + lbr[2],
                                                                      lgr[3] * e3 * inv + lbr[3]);
            }
        }
        __syncthreads();

        // ---------- P6: MLP1 mma + second-level prefetch for nN ----------
        float gv0 = 0.0f, gv1 = 0.0f;
        int rjv = 0, rnv = 0, cjv = 0, cnv = 0, bjv = 0, bnv = 0;
        float mjv = 0.0f, mnv = 0.0f, dmv = 0.0f;
        if (hasNext) {
            {
                int bb = tid / 480, r2 = tid - bb * 480;
                int kk = r2 / 15, e = r2 - kk * 15;
                int j = smi[OFF_SJ + parn * 64 + bb * 32 + kk];
                gv0 = pos[j * 15 + e];
            }
            if (tid < 448) {
                int i1 = tid + 512;
                int bb = i1 / 480, r2 = i1 - bb * 480;
                int kk = r2 / 15, e = r2 - kk * 15;
                int j = smi[OFF_SJ + parn * 64 + bb * 32 + kk];
                gv1 = pos[j * 15 + e];
            }
            if (tid < 64) {
                int bb = tid >> 5;
                int nn = nN + bb;
                int j = smi[OFF_SJ + parn * 64 + tid];
                rjv = resi[j]; rnv = resi[nn];
                cjv = chain[j]; cnv = chain[nn];
                bjv = batch[j]; bnv = batch[nn];
                mjv = maskp[j]; mnv = maskp[nn];
                dmv = __ldg(&dmap[(long)nn * Ntot + j]);
            }
        }
        {
            float c[16];
#pragma unroll
            for (int j = 0; j < 16; ++j) c[j] = 0.0f;
            u32 aA = aP0, bA = bW1;
#pragma unroll
            for (int s = 0; s < 4; ++s) {
                u32 ra0, ra1, ra2, ra3, rb0, rb1, rb2, rb3, rc0, rc1, rc2, rc3;
                LDSM4(ra0, ra1, ra2, ra3, aA);
                LDSM4T(rb0, rb1, rb2, rb3, bA);
                LDSM4T(rc0, rc1, rc2, rc3, bA + 32);
                aA += 32;
                bA += 4352;
                MMA16816(c[0],  c[1],  c[2],  c[3],  ra0, ra1, ra2, ra3, rb0, rb1);
                MMA16816(c[4],  c[5],  c[6],  c[7],  ra0, ra1, ra2, ra3, rb2, rb3);
                MMA16816(c[8],  c[9],  c[10], c[11], ra0, ra1, ra2, ra3, rc0, rc1);
                MMA16816(c[12], c[13], c[14], c[15], ra0, ra1, ra2, ra3, rc2, rc3);
            }
            __half2* hh2 = (__half2*)(sm + OFF_FT);
            int r1 = mt * 16 + (k >> 2), r2 = r1 + 8;
#pragma unroll
            for (int t = 0; t < 4; ++t) {
                float g0 = gelu_f(c[4 * t + 0] + b1r[2 * t + 0]);
                float g1 = gelu_f(c[4 * t + 1] + b1r[2 * t + 1]);
                float g2 = gelu_f(c[4 * t + 2] + b1r[2 * t + 0]);
                float g3 = gelu_f(c[4 * t + 3] + b1r[2 * t + 1]);
                int cw = nt * 16 + t * 4 + (k & 3);
                hh2[r1 * 68 + cw] = __floats2half2_rn(g0, g1);
                hh2[r2 * 68 + cw] = __floats2half2_rn(g2, g3);
            }
        }
        if (hasNext) {
            {
                int bb = tid / 480, r2 = tid - bb * 480;
                int kk = r2 / 15, e = r2 - kk * 15;
                sm[OFF_PJ + parn * 1088 + bb * 544 + kk * 17 + e] = gv0;
            }
            if (tid < 448) {
                int i1 = tid + 512;
                int bb = i1 / 480, r2 = i1 - bb * 480;
                int kk = r2 / 15, e = r2 - kk * 15;
                sm[OFF_PJ + parn * 1088 + bb * 544 + kk * 17 + e] = gv1;
            }
            if (tid < 64) {
                int bb = tid >> 5, kk = tid & 31;
                int dr = rjv - rnv;
                dr = dr < -32 ? -32 : (dr > 32 ? 32 : dr);
                smi[OFF_SREL + parn * 64 + tid] = dr + 32;
                float same = (cjv == cnv && bjv == bnv) ? 1.0f : 0.0f;
                sm[OFF_SSAME + parn * 64 + tid] = same;
                float valid = (nbv != -1) ? 1.0f : 0.0f;
                float pm = mnv * mjv * valid;
                sm[OFF_SPM + parn * 64 + tid] = pm;
                sm[OFF_DM + parn * 64 + tid] = dmv;
                outMask[(nN + bb) * KC + kk] = pm;
            }
        }
        __syncthreads();

        // ---------- P7: MLP2 mma + gmem write ----------
        {
            float d0 = 0.f, d1 = 0.f, d2 = 0.f, d3 = 0.f;
            float d4 = 0.f, d5 = 0.f, d6 = 0.f, d7 = 0.f;
            u32 aA = aH0, bA = bW2;
#pragma unroll
            for (int s = 0; s < 8; ++s) {
                u32 ra0, ra1, ra2, ra3, rb0, rb1, rb2, rb3;
                LDSM4(ra0, ra1, ra2, ra3, aA);
                LDSM4T(rb0, rb1, rb2, rb3, bA);
                aA += 32;
                bA += 2304;
                MMA16816(d0, d1, d2, d3, ra0, ra1, ra2, ra3, rb0, rb1);
                MMA16816(d4, d5, d6, d7, ra0, ra1, ra2, ra3, rb2, rb3);
            }
            d0 += b2r[0]; d1 += b2r[1]; d2 += b2r[0]; d3 += b2r[1];
            d4 += b2r[2]; d5 += b2r[3]; d6 += b2r[2]; d7 += b2r[3];
            int r1 = mt * 16 + (k >> 2), r2 = r1 + 8;
            int col = nt * 16 + (k & 3) * 2;
            long i1 = ((long)(n0 + (r1 >> 5)) * 32 + (r1 & 31)) * 64;
            long i2 = ((long)(n0 + (r2 >> 5)) * 32 + (r2 & 31)) * 64;
            *reinterpret_cast<float2*>(outPair + i1 + col)     = make_float2(d0, d1);
            *reinterpret_cast<float2*>(outPair + i2 + col)     = make_float2(d2, d3);
            *reinterpret_cast<float2*>(outPair + i1 + col + 8) = make_float2(d4, d5);
            *reinterpret_cast<float2*>(outPair + i2 + col + 8) = make_float2(d6, d7);
        }
        __syncthreads();
    }
}

extern "C" void kernel_launch(void* const* d_in, const int* in_sizes, int n_in,
                              void* d_out, int out_size) {
    const float* pos   = (const float*)d_in[0];
    const float* dmap  = (const float*)d_in[1];
    const int*   nbrs  = (const int*)d_in[2];
    const int*   resi  = (const int*)d_in[3];
    const int*   chain = (const int*)d_in[4];
    const int*   batch = (const int*)d_in[5];
    const float* maskp = (const float*)d_in[6];
    const float* Wrel  = (const float*)d_in[7];
    const float* Wdmap = (const float*)d_in[8];
    const float* Wdist = (const float*)d_in[9];
    const float* Wdir  = (const float*)d_in[10];
    const float* Wrot  = (const float*)d_in[11];
    const float* Wvec  = (const float*)d_in[12];
    const float* lng   = (const float*)d_in[13];
    const float* lnb   = (const float*)d_in[14];
    const float* W1    = (const float*)d_in[15];
    const float* b1    = (const float*)d_in[16];
    const float* W2    = (const float*)d_in[17];
    const float* b2    = (const float*)d_in[18];

    float* outPair = (float*)d_out;
    float* outMask = outPair + (long)Ntot * KC * PC;

    cudaFuncSetAttribute(dsd_kernel, cudaFuncAttributeMaxDynamicSharedMemorySize, SMEMF * 4);
    int sms = 148;
    cudaDeviceGetAttribute(&sms, cudaDevAttrMultiProcessorCount, 0);

    dsd_kernel<<<sms, THREADS, SMEMF * 4>>>(
        pos, dmap, nbrs, resi, chain, batch, maskp,
        Wrel, Wdmap, Wdist, Wdir, Wrot, Wvec, lng, lnb, W1, b1, W2, b2,
        outPair, outMask);
}

// round 14
// speedup vs baseline: 4.9882x; 1.0253x over previous
#include <cuda_runtime.h>
#include <cuda_fp16.h>
#include <cstdint>
#include <math.h>

typedef unsigned long long ull;
typedef unsigned int u32;

#define Ntot 8192
#define KC   32
#define PC   64
#define KPAD  464            // 29 * 16
#define THREADS 512

// strides (in halfs)
#define S72   72
#define S136  136

// ---- shared memory layout (float offsets) ----
#define OFF_WDH   0                        // half[464][72]  = 16704 fl
#define OFF_W1H   16704                    // half[64][136]  = 4352 fl
#define OFF_W2H   21056                    // half[128][72]  = 4608 fl
#define OFF_FT    25664                    // F^T half[464][72] = 16704 fl (features ONLY)
#define OFF_HH    42368                    // Hh half[64][136] = 4352 fl (own region)
#define OFF_P0    46720                    // fp32 [32][66] = 2112
#define OFF_P1    48832                    // fp32 [32][66] = 2112
#define OFF_PH    50944                    // pair half[64][72] = 2304 fl
#define OFF_PJ    53248                    // [par][2][32][17] = 2176
#define OFF_POSN  55424                    // [par][2][16] = 64
#define OFF_RN    55488                    // [par][2][12] = 48
#define OFF_SJ    55536                    // [par][64] ints = 128
#define OFF_SREL  55664                    // 128
#define OFF_SSAME 55792                    // 128
#define OFF_SPM   55920                    // 128
#define OFF_DM    56048                    // 128
#define SMEMF     56176                    // 224704 bytes

// ---- tensor-core helpers ----
#define LDSM4(q0, q1, q2, q3, addr) \
    asm volatile("ldmatrix.sync.aligned.m8n8.x4.shared.b16 {%0,%1,%2,%3}, [%4];" \
                 : "=r"(q0), "=r"(q1), "=r"(q2), "=r"(q3) : "r"(addr))
#define LDSM4T(q0, q1, q2, q3, addr) \
    asm volatile("ldmatrix.sync.aligned.m8n8.x4.trans.shared.b16 {%0,%1,%2,%3}, [%4];" \
                 : "=r"(q0), "=r"(q1), "=r"(q2), "=r"(q3) : "r"(addr))
#define MMA16816(d0, d1, d2, d3, q0, q1, q2, q3, p0, p1) \
    asm volatile("mma.sync.aligned.m16n8k16.row.col.f32.f16.f16.f32 " \
                 "{%0,%1,%2,%3}, {%4,%5,%6,%7}, {%8,%9}, {%0,%1,%2,%3};" \
                 : "+f"(d0), "+f"(d1), "+f"(d2), "+f"(d3) \
                 : "r"(q0), "r"(q1), "r"(q2), "r"(q3), "r"(p0), "r"(p1))

// ---------------- RBF: 16 bins. Peak + ±5-step walk (steps >=5 round to 0 in
// fp16, so zero-fill first; bit-identical to the full walk). ----------------
__device__ __forceinline__ void rbf16s(float d, __half* out) {
    const float SI = 0.72727272727f;
    const float G  = 1.06666666667f;
    const float Q  = 0.10273954f;
    float g = d * SI;
    int m = __float2int_rn(g * 0.9375f);
    m = m < 0 ? 0 : (m > 15 ? 15 : m);
    float u = g - (float)m * G;
    float peak = __expf(-u * u);
    float r = __expf(G * (2.0f * u - G));
    float s = __expf(-G * (2.0f * u + G));
    {
        __half z = __float2half(0.0f);
        __half* q = out;
#pragma unroll
        for (int i = 0; i < 16; ++i) { *q = z; q += S72; }
    }
    out[m * S72] = __float2half(peak);
    float v = peak;
#pragma unroll
    for (int st = 1; st <= 5; ++st) {
        v *= r; r *= Q;
        int i = m + st;
        if (i <= 15) out[i * S72] = __float2half(v);
    }
    v = peak;
#pragma unroll
    for (int st = 1; st <= 5; ++st) {
        v *= s; s *= Q;
        int i = m - st;
        if (i >= 0) out[i * S72] = __float2half(v);
    }
}

__device__ __forceinline__ void frames_from(const float* p,
                                            float e1[3], float e2[3], float e3[3], float t[3]) {
    t[0] = p[3]; t[1] = p[4]; t[2] = p[5];
    float v1x = p[6] - t[0], v1y = p[7] - t[1], v1z = p[8] - t[2];
    float v2x = p[0] - t[0], v2y = p[1] - t[1], v2z = p[2] - t[2];
    float n1 = sqrtf(v1x * v1x + v1y * v1y + v1z * v1z) + 1e-6f;
    e1[0] = v1x / n1; e1[1] = v1y / n1; e1[2] = v1z / n1;
    float dt = v2x * e1[0] + v2y * e1[1] + v2z * e1[2];
    float ux = v2x - dt * e1[0], uy = v2y - dt * e1[1], uz = v2z - dt * e1[2];
    float n2 = sqrtf(ux * ux + uy * uy + uz * uz) + 1e-6f;
    e2[0] = ux / n2; e2[1] = uy / n2; e2[2] = uz / n2;
    e3[0] = e1[1] * e2[2] - e1[2] * e2[1];
    e3[1] = e1[2] * e2[0] - e1[0] * e2[2];
    e3[2] = e1[0] * e2[1] - e1[1] * e2[0];
}

__device__ __forceinline__ float gelu_f(float x) {
    float c = 0.7978845608028654f * (x + 0.044715f * x * x * x);
    float t;
    asm("tanh.approx.f32 %0, %1;" : "=f"(t) : "f"(c));
    return 0.5f * x * (1.0f + t);
}

__global__ void __launch_bounds__(THREADS, 1)
dsd_kernel(const float* __restrict__ pos, const float* __restrict__ dmap,
           const int* __restrict__ nbrs, const int* __restrict__ resi,
           const int* __restrict__ chain, const int* __restrict__ batch,
           const float* __restrict__ maskp,
           const float* __restrict__ Wrel, const float* __restrict__ Wdmap,
           const float* __restrict__ Wdist, const float* __restrict__ Wdir,
           const float* __restrict__ Wrot, const float* __restrict__ Wvec,
           const float* __restrict__ lng, const float* __restrict__ lnb,
           const float* __restrict__ W1, const float* __restrict__ bias1,
           const float* __restrict__ W2, const float* __restrict__ bias2,
           float* __restrict__ outPair, float* __restrict__ outMask)
{
    extern __shared__ float sm[];
    const int tid = threadIdx.x;
    const int k   = tid & 31;
    const int wid = tid >> 5;
    const int mt  = wid & 3;
    const int nt  = wid >> 2;
    const int lkk = tid >> 4;
    const int ls  = tid & 15;

    __half* WDh = (__half*)(sm + OFF_WDH);
    __half* W1h = (__half*)(sm + OFF_W1H);
    __half* W2h = (__half*)(sm + OFF_W2H);
    __half* FT  = (__half*)(sm + OFF_FT);

    // ---- stage constant weights once (all fp16) ----
    for (int i = tid; i < KPAD * 64; i += THREADS) {
        int f = i >> 6, c = i & 63;
        float v;
        if (f < 400)      v = Wdist[f * 64 + c];
        else if (f < 416) v = Wdmap[(f - 400) * 64 + c];
        else if (f < 431) v = Wdir[(f - 416) * 64 + c];
        else if (f < 446) v = Wvec[(f - 431) * 64 + c];
        else if (f < 455) v = Wrot[(f - 446) * 64 + c];
        else              v = 0.0f;
        WDh[f * S72 + c] = __float2half(v);
    }
    for (int i = tid; i < 64 * 128; i += THREADS) {
        int p = i >> 7, h = i & 127;
        W1h[p * S136 + h] = __float2half(W1[i]);
    }
    for (int i = tid; i < 128 * 64; i += THREADS) {
        int j = i >> 6, c = i & 63;
        W2h[j * S72 + c] = __float2half(W2[i]);
    }
    // K-pad rows zeroed once (FT now holds features exclusively)
    {
        __half z = __float2half(0.0f);
        for (int i = tid; i < 9 * 64; i += THREADS) {
            int r = 455 + i / 64, c = i - (i / 64) * 64;
            FT[r * S72 + c] = z;
        }
    }

    float lgr[4], lbr[4], b1r[8], b2r[4];
#pragma unroll
    for (int i = 0; i < 4; ++i) {
        lgr[i] = lng[ls * 4 + i];
        lbr[i] = lnb[ls * 4 + i];
    }
#pragma unroll
    for (int t = 0; t < 4; ++t) {
        b1r[2 * t + 0] = bias1[nt * 32 + t * 8 + (k & 3) * 2 + 0];
        b1r[2 * t + 1] = bias1[nt * 32 + t * 8 + (k & 3) * 2 + 1];
    }
#pragma unroll
    for (int t = 0; t < 2; ++t) {
        b2r[2 * t + 0] = bias2[nt * 16 + t * 8 + (k & 3) * 2 + 0];
        b2r[2 * t + 1] = bias2[nt * 16 + t * 8 + (k & 3) * 2 + 1];
    }

    // validated mma base addresses
    const u32 FTS = (u32)__cvta_generic_to_shared(FT);
    const u32 WDS = (u32)__cvta_generic_to_shared(WDh);
    const u32 W1S_ = (u32)__cvta_generic_to_shared(W1h);
    const u32 W2S_ = (u32)__cvta_generic_to_shared(W2h);
    const u32 PhS = (u32)__cvta_generic_to_shared(sm + OFF_PH);
    const u32 HHS = (u32)__cvta_generic_to_shared(sm + OFF_HH);
    const u32 aAddr0 = FTS + ((k & 7) + ((k >> 4) & 1) * 8) * 144 + (mt * 16 + ((k >> 3) & 1) * 8) * 2;
    const u32 bAddr0 = WDS + ((k & 7) + ((k >> 3) & 1) * 8) * 144 + (nt * 16 + ((k >> 4) & 1) * 8) * 2;
    const u32 aP0 = PhS + (mt * 16 + (k & 7) + ((k >> 3) & 1) * 8) * 144 + ((k >> 4) & 1) * 16;
    const u32 bW1 = W1S_ + ((k & 7) + ((k >> 3) & 1) * 8) * 272 + (nt * 32 + ((k >> 4) & 1) * 8) * 2;
    const u32 aH0 = HHS + (mt * 16 + (k & 7) + ((k >> 3) & 1) * 8) * 272 + ((k >> 4) & 1) * 16;
    const u32 bW2 = W2S_ + ((k & 7) + ((k >> 3) & 1) * 8) * 144 + (nt * 16 + ((k >> 4) & 1) * 8) * 2;

    // rebalanced task-B assignment: wid 10..14 -> dp 16..20, wid 0..3 -> dp 21..24
    const int dpB = (wid >= 10 && wid < 15) ? (6 + wid) : ((wid < 4) ? (21 + wid) : -1);

    int* smi = (int*)sm;
    const int stride2 = gridDim.x * 2;

    __syncthreads();

    // ================= PROLOGUE: fill par=0 buffers =================
    {
        int nb0 = blockIdx.x * 2;
        if (tid < 64) {
            int bb = tid >> 5, kk = tid & 31;
            int n = nb0 + bb;
            int nb = nbrs[n * KC + kk];
            int j = nb < 0 ? 0 : nb;
            float valid = (nb != -1) ? 1.0f : 0.0f;
            smi[OFF_SJ + bb * 32 + kk] = j;
            int dr = resi[j] - resi[n];
            dr = dr < -32 ? -32 : (dr > 32 ? 32 : dr);
            smi[OFF_SREL + bb * 32 + kk] = dr + 32;
            float same = (chain[j] == chain[n] && batch[j] == batch[n]) ? 1.0f : 0.0f;
            sm[OFF_SSAME + bb * 32 + kk] = same;
            float pm = maskp[n] * maskp[j] * valid;
            sm[OFF_SPM + bb * 32 + kk] = pm;
            outMask[n * KC + kk] = pm;
        } else if (tid < 66) {
            int bb = tid - 64;
            float e1[3], e2[3], e3[3], t[3], prow[9];
#pragma unroll
            for (int i = 0; i < 9; ++i) prow[i] = pos[(nb0 + bb) * 15 + i];
            frames_from(prow, e1, e2, e3, t);
#pragma unroll
            for (int r = 0; r < 3; ++r) {
                sm[OFF_RN + bb * 12 + r * 3 + 0] = e1[r];
                sm[OFF_RN + bb * 12 + r * 3 + 1] = e2[r];
                sm[OFF_RN + bb * 12 + r * 3 + 2] = e3[r];
            }
            sm[OFF_RN + bb * 12 + 9 + 0] = t[0];
            sm[OFF_RN + bb * 12 + 9 + 1] = t[1];
            sm[OFF_RN + bb * 12 + 9 + 2] = t[2];
        } else if (tid >= 96 && tid < 126) {
            int bb = (tid - 96) / 15, e = (tid - 96) % 15;
            sm[OFF_POSN + bb * 16 + e] = pos[(nb0 + bb) * 15 + e];
        }
        __syncthreads();
        for (int i = tid; i < 960; i += THREADS) {
            int bb = i / 480, r2 = i - bb * 480;
            int kk = r2 / 15, e = r2 - kk * 15;
            int j = smi[OFF_SJ + bb * 32 + kk];
            sm[OFF_PJ + bb * 544 + kk * 17 + e] = pos[j * 15 + e];
        }
        if (tid < 64) {
            int bb = tid >> 5;
            int j = smi[OFF_SJ + tid];
            sm[OFF_DM + tid] = __ldg(&dmap[(long)(nb0 + bb) * Ntot + j]);
        }
        __syncthreads();
    }

    int iter = 0;
    for (int n0 = blockIdx.x * 2; n0 < Ntot; n0 += stride2, ++iter) {
        const int par  = iter & 1;
        const int parn = par ^ 1;
        const int nN   = n0 + stride2;
        const bool hasNext = (nN < Ntot);

        // ---------- P3: build features into F^T (runs right after P7; no conflict) ----------
        for (int bb = 0; bb < 2; ++bb) {
            __half* fT = FT + (bb * 32 + k);
            const float* pn = sm + OFF_POSN + par * 32 + bb * 16;
            const float* pj = sm + OFF_PJ + par * 1088 + bb * 544 + k * 17;
            const float* rn = sm + OFF_RN + par * 24 + bb * 12;
            {   // task A: dp = wid
                int a = wid / 5, c5 = wid - a * 5;
                float dx = pn[a * 3 + 0] - pj[c5 * 3 + 0];
                float dy = pn[a * 3 + 1] - pj[c5 * 3 + 1];
                float dz = pn[a * 3 + 2] - pj[c5 * 3 + 2];
                float d = sqrtf(dx * dx + dy * dy + dz * dz);
                rbf16s(d, fT + (wid * 16) * S72);
            }
            if (dpB >= 0) {   // task B: rebalanced
                int a = dpB / 5, c5 = dpB - a * 5;
                float dx = pn[a * 3 + 0] - pj[c5 * 3 + 0];
                float dy = pn[a * 3 + 1] - pj[c5 * 3 + 1];
                float dz = pn[a * 3 + 2] - pj[c5 * 3 + 2];
                float d = sqrtf(dx * dx + dy * dy + dz * dz);
                rbf16s(d, fT + (dpB * 16) * S72);
            }
            if (wid == 9) {
                float pm = sm[OFF_SPM + par * 64 + bb * 32 + k];
                float dval = sm[OFF_DM + par * 64 + bb * 32 + k];
                if (pm > 0.0f) {
                    rbf16s(dval, fT + 400 * S72);
                } else {
                    __half z = __float2half(0.0f);
#pragma unroll
                    for (int i = 0; i < 16; ++i) fT[(400 + i) * S72] = z;
                }
            } else if (wid >= 10 && wid < 15) {
                int a = wid - 10;
                float v0 = pj[a * 3 + 0] - rn[9 + 0];
                float v1 = pj[a * 3 + 1] - rn[9 + 1];
                float v2 = pj[a * 3 + 2] - rn[9 + 2];
                float rv[3];
#pragma unroll
                for (int i = 0; i < 3; ++i)
                    rv[i] = rn[0 + i] * v0 + rn[3 + i] * v1 + rn[6 + i] * v2;
                float nr = sqrtf(rv[0] * rv[0] + rv[1] * rv[1] + rv[2] * rv[2]);
                float inv = 1.0f / (nr + 1e-6f);
#pragma unroll
                for (int i = 0; i < 3; ++i) {
                    fT[(416 + a * 3 + i) * S72] = __float2half(rv[i] * inv);
                    fT[(431 + a * 3 + i) * S72] = __float2half(rv[i] * 0.1f);
                }
            } else if (wid == 15) {
                float e1j[3], e2j[3], e3j[3], tj[3];
                frames_from(pj, e1j, e2j, e3j, tj);
#pragma unroll
                for (int i = 0; i < 3; ++i) {
                    float r0 = rn[0 + i], r1 = rn[3 + i], r2 = rn[6 + i];
                    fT[(446 + i * 3 + 0) * S72] = __float2half(r0 * e1j[0] + r1 * e1j[1] + r2 * e1j[2]);
                    fT[(446 + i * 3 + 1) * S72] = __float2half(r0 * e2j[0] + r1 * e2j[1] + r2 * e2j[2]);
                    fT[(446 + i * 3 + 2) * S72] = __float2half(r0 * e3j[0] + r1 * e3j[1] + r2 * e3j[2]);
                }
            }
        }
        __syncthreads();

        // ---------- P4: Wrel prefetch + first-level prefetch + pipelined GEMM ----------
        float4 wrA, wrC;
        {
            int relA = smi[OFF_SREL + par * 64 + lkk];
            int relC = smi[OFF_SREL + par * 64 + 32 + lkk];
            wrA = __ldg(reinterpret_cast<const float4*>(Wrel) + relA * 16 + ls);
            wrC = __ldg(reinterpret_cast<const float4*>(Wrel) + relC * 16 + ls);
        }
        int nbv = -1;
        float posnv = 0.0f;
        if (hasNext) {
            if (tid < 64) {
                int bb = tid >> 5, kk = tid & 31;
                nbv = nbrs[(nN + bb) * KC + kk];
            } else if (tid >= 96 && tid < 126) {
                int bb = (tid - 96) / 15, e = (tid - 96) % 15;
                posnv = pos[(nN + bb) * 15 + e];
            }
        }
        {
            float d0 = 0.f, d1 = 0.f, d2 = 0.f, d3 = 0.f;
            float d4 = 0.f, d5 = 0.f, d6 = 0.f, d7 = 0.f;
            u32 aA = aAddr0, bA = bAddr0;
            u32 xa0, xa1, xa2, xa3, xb0, xb1, xb2, xb3;
            u32 ya0, ya1, ya2, ya3, yb0, yb1, yb2, yb3;
            LDSM4T(xa0, xa1, xa2, xa3, aA);
            LDSM4T(xb0, xb1, xb2, xb3, bA);
#pragma unroll 1
            for (int s = 0; s < 14; ++s) {
                aA += 2304; bA += 2304;
                LDSM4T(ya0, ya1, ya2, ya3, aA);
                LDSM4T(yb0, yb1, yb2, yb3, bA);
                MMA16816(d0, d1, d2, d3, xa0, xa1, xa2, xa3, xb0, xb1);
                MMA16816(d4, d5, d6, d7, xa0, xa1, xa2, xa3, xb2, xb3);
                aA += 2304; bA += 2304;
                LDSM4T(xa0, xa1, xa2, xa3, aA);
                LDSM4T(xb0, xb1, xb2, xb3, bA);
                MMA16816(d0, d1, d2, d3, ya0, ya1, ya2, ya3, yb0, yb1);
                MMA16816(d4, d5, d6, d7, ya0, ya1, ya2, ya3, yb2, yb3);
            }
            MMA16816(d0, d1, d2, d3, xa0, xa1, xa2, xa3, xb0, xb1);
            MMA16816(d4, d5, d6, d7, xa0, xa1, xa2, xa3, xb2, xb3);

            float* P = sm + ((mt >> 1) ? OFF_P1 : OFF_P0);
            int kk1 = (mt & 1) * 16 + (k >> 2);
            int kk2 = kk1 + 8;
            int col = nt * 16 + (k & 3) * 2;
            *reinterpret_cast<float2*>(P + kk1 * 66 + col)     = make_float2(d0, d1);
            *reinterpret_cast<float2*>(P + kk2 * 66 + col)     = make_float2(d2, d3);
            *reinterpret_cast<float2*>(P + kk1 * 66 + col + 8) = make_float2(d4, d5);
            *reinterpret_cast<float2*>(P + kk2 * 66 + col + 8) = make_float2(d6, d7);
        }
        if (hasNext) {
            if (tid < 64) {
                int bb = tid >> 5, kk = tid & 31;
                int j = nbv < 0 ? 0 : nbv;
                smi[OFF_SJ + parn * 64 + bb * 32 + kk] = j;
            } else if (tid >= 96 && tid < 126) {
                int bb = (tid - 96) / 15, e = (tid - 96) % 15;
                sm[OFF_POSN + parn * 32 + bb * 16 + e] = posnv;
            }
        }
        __syncthreads();

        // ---------- P5: + Wrel, LayerNorm -> Ph ; frames for nN from POSN[parn] ----------
        if (hasNext && tid < 2) {
            int bb = tid;
            float e1[3], e2[3], e3[3], t[3];
            frames_from(sm + OFF_POSN + parn * 32 + bb * 16, e1, e2, e3, t);
#pragma unroll
            for (int r = 0; r < 3; ++r) {
                sm[OFF_RN + parn * 24 + bb * 12 + r * 3 + 0] = e1[r];
                sm[OFF_RN + parn * 24 + bb * 12 + r * 3 + 1] = e2[r];
                sm[OFF_RN + parn * 24 + bb * 12 + r * 3 + 2] = e3[r];
            }
            sm[OFF_RN + parn * 24 + bb * 12 + 9 + 0] = t[0];
            sm[OFF_RN + parn * 24 + bb * 12 + 9 + 1] = t[1];
            sm[OFF_RN + parn * 24 + bb * 12 + 9 + 2] = t[2];
        }
        {
            float a0 = sm[OFF_P0 + lkk * 66 + ls * 4 + 0];
            float a1 = sm[OFF_P0 + lkk * 66 + ls * 4 + 1];
            float a2 = sm[OFF_P0 + lkk * 66 + ls * 4 + 2];
            float a3 = sm[OFF_P0 + lkk * 66 + ls * 4 + 3];
            float c0 = sm[OFF_P1 + lkk * 66 + ls * 4 + 0];
            float c1 = sm[OFF_P1 + lkk * 66 + ls * 4 + 1];
            float c2 = sm[OFF_P1 + lkk * 66 + ls * 4 + 2];
            float c3 = sm[OFF_P1 + lkk * 66 + ls * 4 + 3];
            {
                float same = sm[OFF_SSAME + par * 64 + lkk];
                a0 = fmaf(same, wrA.x, a0); a1 = fmaf(same, wrA.y, a1);
                a2 = fmaf(same, wrA.z, a2); a3 = fmaf(same, wrA.w, a3);
            }
            {
                float same = sm[OFF_SSAME + par * 64 + 32 + lkk];
                c0 = fmaf(same, wrC.x, c0); c1 = fmaf(same, wrC.y, c1);
                c2 = fmaf(same, wrC.z, c2); c3 = fmaf(same, wrC.w, c3);
            }
            __half2* ph2 = (__half2*)(sm + OFF_PH);
            {
                float ssum = a0 + a1 + a2 + a3;
                ssum += __shfl_xor_sync(0xffffffffu, ssum, 8);
                ssum += __shfl_xor_sync(0xffffffffu, ssum, 4);
                ssum += __shfl_xor_sync(0xffffffffu, ssum, 2);
                ssum += __shfl_xor_sync(0xffffffffu, ssum, 1);
                float mu = ssum * 0.015625f;
                float e0 = a0 - mu, e1 = a1 - mu, e2 = a2 - mu, e3 = a3 - mu;
                float sq = e0 * e0 + e1 * e1 + e2 * e2 + e3 * e3;
                sq += __shfl_xor_sync(0xffffffffu, sq, 8);
                sq += __shfl_xor_sync(0xffffffffu, sq, 4);
                sq += __shfl_xor_sync(0xffffffffu, sq, 2);
                sq += __shfl_xor_sync(0xffffffffu, sq, 1);
                float inv = rsqrtf(sq * 0.015625f + 1e-5f);
                ph2[lkk * 36 + ls * 2 + 0] = __floats2half2_rn(lgr[0] * e0 * inv + lbr[0],
                                                               lgr[1] * e1 * inv + lbr[1]);
                ph2[lkk * 36 + ls * 2 + 1] = __floats2half2_rn(lgr[2] * e2 * inv + lbr[2],
                                                               lgr[3] * e3 * inv + lbr[3]);
            }
            {
                float ssum = c0 + c1 + c2 + c3;
                ssum += __shfl_xor_sync(0xffffffffu, ssum, 8);
                ssum += __shfl_xor_sync(0xffffffffu, ssum, 4);
                ssum += __shfl_xor_sync(0xffffffffu, ssum, 2);
                ssum += __shfl_xor_sync(0xffffffffu, ssum, 1);
                float mu = ssum * 0.015625f;
                float e0 = c0 - mu, e1 = c1 - mu, e2 = c2 - mu, e3 = c3 - mu;
                float sq = e0 * e0 + e1 * e1 + e2 * e2 + e3 * e3;
                sq += __shfl_xor_sync(0xffffffffu, sq, 8);
                sq += __shfl_xor_sync(0xffffffffu, sq, 4);
                sq += __shfl_xor_sync(0xffffffffu, sq, 2);
                sq += __shfl_xor_sync(0xffffffffu, sq, 1);
                float inv = rsqrtf(sq * 0.015625f + 1e-5f);
                ph2[(32 + lkk) * 36 + ls * 2 + 0] = __floats2half2_rn(lgr[0] * e0 * inv + lbr[0],
                                                                      lgr[1] * e1 * inv + lbr[1]);
                ph2[(32 + lkk) * 36 + ls * 2 + 1] = __floats2half2_rn(lgr[2] * e2 * inv + lbr[2],
                                                                      lgr[3] * e3 * inv + lbr[3]);
            }
        }
        __syncthreads();

        // ---------- P6: MLP1 mma + second-level prefetch for nN ----------
        float gv0 = 0.0f, gv1 = 0.0f;
        int rjv = 0, rnv = 0, cjv = 0, cnv = 0, bjv = 0, bnv = 0;
        float mjv = 0.0f, mnv = 0.0f, dmv = 0.0f;
        if (hasNext) {
            {
                int bb = tid / 480, r2 = tid - bb * 480;
                int kk = r2 / 15, e = r2 - kk * 15;
                int j = smi[OFF_SJ + parn * 64 + bb * 32 + kk];
                gv0 = pos[j * 15 + e];
            }
            if (tid < 448) {
                int i1 = tid + 512;
                int bb = i1 / 480, r2 = i1 - bb * 480;
                int kk = r2 / 15, e = r2 - kk * 15;
                int j = smi[OFF_SJ + parn * 64 + bb * 32 + kk];
                gv1 = pos[j * 15 + e];
            }
            if (tid < 64) {
                int bb = tid >> 5;
                int nn = nN + bb;
                int j = smi[OFF_SJ + parn * 64 + tid];
                rjv = resi[j]; rnv = resi[nn];
                cjv = chain[j]; cnv = chain[nn];
                bjv = batch[j]; bnv = batch[nn];
                mjv = maskp[j]; mnv = maskp[nn];
                dmv = __ldg(&dmap[(long)nn * Ntot + j]);
            }
        }
        {
            float c[16];
#pragma unroll
            for (int j = 0; j < 16; ++j) c[j] = 0.0f;
            u32 aA = aP0, bA = bW1;
#pragma unroll
            for (int s = 0; s < 4; ++s) {
                u32 ra0, ra1, ra2, ra3, rb0, rb1, rb2, rb3, rc0, rc1, rc2, rc3;
                LDSM4(ra0, ra1, ra2, ra3, aA);
                LDSM4T(rb0, rb1, rb2, rb3, bA);
                LDSM4T(rc0, rc1, rc2, rc3, bA + 32);
                aA += 32;
                bA += 4352;
                MMA16816(c[0],  c[1],  c[2],  c[3],  ra0, ra1, ra2, ra3, rb0, rb1);
                MMA16816(c[4],  c[5],  c[6],  c[7],  ra0, ra1, ra2, ra3, rb2, rb3);
                MMA16816(c[8],  c[9],  c[10], c[11], ra0, ra1, ra2, ra3, rc0, rc1);
                MMA16816(c[12], c[13], c[14], c[15], ra0, ra1, ra2, ra3, rc2, rc3);
            }
            __half2* hh2 = (__half2*)(sm + OFF_HH);
            int r1 = mt * 16 + (k >> 2), r2 = r1 + 8;
#pragma unroll
            for (int t = 0; t < 4; ++t) {
                float g0 = gelu_f(c[4 * t + 0] + b1r[2 * t + 0]);
                float g1 = gelu_f(c[4 * t + 1] + b1r[2 * t + 1]);
                float g2 = gelu_f(c[4 * t + 2] + b1r[2 * t + 0]);
                float g3 = gelu_f(c[4 * t + 3] + b1r[2 * t + 1]);
                int cw = nt * 16 + t * 4 + (k & 3);
                hh2[r1 * 68 + cw] = __floats2half2_rn(g0, g1);
                hh2[r2 * 68 + cw] = __floats2half2_rn(g2, g3);
            }
        }
        if (hasNext) {
            {
                int bb = tid / 480, r2 = tid - bb * 480;
                int kk = r2 / 15, e = r2 - kk * 15;
                sm[OFF_PJ + parn * 1088 + bb * 544 + kk * 17 + e] = gv0;
            }
            if (tid < 448) {
                int i1 = tid + 512;
                int bb = i1 / 480, r2 = i1 - bb * 480;
                int kk = r2 / 15, e = r2 - kk * 15;
                sm[OFF_PJ + parn * 1088 + bb * 544 + kk * 17 + e] = gv1;
            }
            if (tid < 64) {
                int bb = tid >> 5, kk = tid & 31;
                int dr = rjv - rnv;
                dr = dr < -32 ? -32 : (dr > 32 ? 32 : dr);
                smi[OFF_SREL + parn * 64 + tid] = dr + 32;
                float same = (cjv == cnv && bjv == bnv) ? 1.0f : 0.0f;
                sm[OFF_SSAME + parn * 64 + tid] = same;
                float valid = (nbv != -1) ? 1.0f : 0.0f;
                float pm = mnv * mjv * valid;
                sm[OFF_SPM + parn * 64 + tid] = pm;
                sm[OFF_DM + parn * 64 + tid] = dmv;
                outMask[(nN + bb) * KC + kk] = pm;
            }
        }
        __syncthreads();

        // ---------- P7: MLP2 mma + gmem write (no trailing barrier; next P3 is safe) ----------
        {
            float d0 = 0.f, d1 = 0.f, d2 = 0.f, d3 = 0.f;
            float d4 = 0.f, d5 = 0.f, d6 = 0.f, d7 = 0.f;
            u32 aA = aH0, bA = bW2;
#pragma unroll
            for (int s = 0; s < 8; ++s) {
                u32 ra0, ra1, ra2, ra3, rb0, rb1, rb2, rb3;
                LDSM4(ra0, ra1, ra2, ra3, aA);
                LDSM4T(rb0, rb1, rb2, rb3, bA);
                aA += 32;
                bA += 2304;
                MMA16816(d0, d1, d2, d3, ra0, ra1, ra2, ra3, rb0, rb1);
                MMA16816(d4, d5, d6, d7, ra0, ra1, ra2, ra3, rb2, rb3);
            }
            d0 += b2r[0]; d1 += b2r[1]; d2 += b2r[0]; d3 += b2r[1];
            d4 += b2r[2]; d5 += b2r[3]; d6 += b2r[2]; d7 += b2r[3];
            int r1 = mt * 16 + (k >> 2), r2 = r1 + 8;
            int col = nt * 16 + (k & 3) * 2;
            long i1 = ((long)(n0 + (r1 >> 5)) * 32 + (r1 & 31)) * 64;
            long i2 = ((long)(n0 + (r2 >> 5)) * 32 + (r2 & 31)) * 64;
            *reinterpret_cast<float2*>(outPair + i1 + col)     = make_float2(d0, d1);
            *reinterpret_cast<float2*>(outPair + i2 + col)     = make_float2(d2, d3);
            *reinterpret_cast<float2*>(outPair + i1 + col + 8) = make_float2(d4, d5);
            *reinterpret_cast<float2*>(outPair + i2 + col + 8) = make_float2(d6, d7);
        }
        // no __syncthreads here: P7 touches only Hh/W2h/gmem; next P3 writes FT
        // and reads buffers[parn->par] all sealed by the post-P6 barrier.
    }
}

extern "C" void kernel_launch(void* const* d_in, const int* in_sizes, int n_in,
                              void* d_out, int out_size) {
    const float* pos   = (const float*)d_in[0];
    const float* dmap  = (const float*)d_in[1];
    const int*   nbrs  = (const int*)d_in[2];
    const int*   resi  = (const int*)d_in[3];
    const int*   chain = (const int*)d_in[4];
    const int*   batch = (const int*)d_in[5];
    const float* maskp = (const float*)d_in[6];
    const float* Wrel  = (const float*)d_in[7];
    const float* Wdmap = (const float*)d_in[8];
    const float* Wdist = (const float*)d_in[9];
    const float* Wdir  = (const float*)d_in[10];
    const float* Wrot  = (const float*)d_in[11];
    const float* Wvec  = (const float*)d_in[12];
    const float* lng   = (const float*)d_in[13];
    const float* lnb   = (const float*)d_in[14];
    const float* W1    = (const float*)d_in[15];
    const float* b1    = (const float*)d_in[16];
    const float* W2    = (const float*)d_in[17];
    const float* b2    = (const float*)d_in[18];

    float* outPair = (float*)d_out;
    float* outMask = outPair + (long)Ntot * KC * PC;

    cudaFuncSetAttribute(dsd_kernel, cudaFuncAttributeMaxDynamicSharedMemorySize, SMEMF * 4);
    int sms = 148;
    cudaDeviceGetAttribute(&sms, cudaDevAttrMultiProcessorCount, 0);

    dsd_kernel<<<sms, THREADS, SMEMF * 4>>>(
        pos, dmap, nbrs, resi, chain, batch, maskp,
        Wrel, Wdmap, Wdist, Wdir, Wrot, Wvec, lng, lnb, W1, b1, W2, b2,
        outPair, outMask);
}

// round 15
// speedup vs baseline: 5.1183x; 1.0261x over previous
#include <cuda_runtime.h>
#include <cuda_fp16.h>
#include <cstdint>
#include <math.h>

typedef unsigned long long ull;
typedef unsigned int u32;

#define Ntot 8192
#define KC   32
#define PC   64
#define KPAD  464            // 29 * 16
#define THREADS 512

// strides (in halfs)
#define S72   72
#define S136  136

// ---- shared memory layout (float offsets) ----
#define OFF_WDH   0                        // half[464][72]  = 16704 fl
#define OFF_W1H   16704                    // half[64][136]  = 4352 fl
#define OFF_W2H   21056                    // half[128][72]  = 4608 fl
#define OFF_FT    25664                    // F^T half[464][72] = 16704 fl (features ONLY)
#define OFF_HH    42368                    // Hh half[64][136] = 4352 fl
#define OFF_P0    46720                    // fp32 [32][66] = 2112
#define OFF_P1    48832                    // fp32 [32][66] = 2112
#define OFF_PH    50944                    // pair half[64][72] = 2304 fl
#define OFF_PJ    53248                    // [par][2][32][17] = 2176
#define OFF_POSN  55424                    // [par][2][16] = 64
#define OFF_RN    55488                    // [par][2][12] = 48
#define OFF_SJ    55536                    // [par][64] ints = 128
#define OFF_SREL  55664                    // 128
#define OFF_SSAME 55792                    // 128
#define OFF_SPM   55920                    // 128
#define OFF_DM    56048                    // 128
#define SMEMF     56176                    // 224704 bytes

// ---- tensor-core helpers ----
#define LDSM4(q0, q1, q2, q3, addr) \
    asm volatile("ldmatrix.sync.aligned.m8n8.x4.shared.b16 {%0,%1,%2,%3}, [%4];" \
                 : "=r"(q0), "=r"(q1), "=r"(q2), "=r"(q3) : "r"(addr))
#define LDSM4T(q0, q1, q2, q3, addr) \
    asm volatile("ldmatrix.sync.aligned.m8n8.x4.trans.shared.b16 {%0,%1,%2,%3}, [%4];" \
                 : "=r"(q0), "=r"(q1), "=r"(q2), "=r"(q3) : "r"(addr))
#define MMA16816(d0, d1, d2, d3, q0, q1, q2, q3, p0, p1) \
    asm volatile("mma.sync.aligned.m16n8k16.row.col.f32.f16.f16.f32 " \
                 "{%0,%1,%2,%3}, {%4,%5,%6,%7}, {%8,%9}, {%0,%1,%2,%3};" \
                 : "+f"(d0), "+f"(d1), "+f"(d2), "+f"(d3) \
                 : "r"(q0), "r"(q1), "r"(q2), "r"(q3), "r"(p0), "r"(p1))

// ---- cp.async helpers ----
#define CPA4(dst, src) \
    asm volatile("cp.async.ca.shared.global [%0], [%1], 4;" :: "r"(dst), "l"(src) : "memory")
#define CPA_COMMIT() asm volatile("cp.async.commit_group;" ::: "memory")
#define CPA_WAIT0()  asm volatile("cp.async.wait_group 0;" ::: "memory")

// ---------------- RBF: 16 bins. Peak + ±5-step walk (fp16-exact) ----------------
__device__ __forceinline__ void rbf16s(float d, __half* out) {
    const float SI = 0.72727272727f;
    const float G  = 1.06666666667f;
    const float Q  = 0.10273954f;
    float g = d * SI;
    int m = __float2int_rn(g * 0.9375f);
    m = m < 0 ? 0 : (m > 15 ? 15 : m);
    float u = g - (float)m * G;
    float peak = __expf(-u * u);
    float r = __expf(G * (2.0f * u - G));
    float s = __expf(-G * (2.0f * u + G));
    {
        __half z = __float2half(0.0f);
        __half* q = out;
#pragma unroll
        for (int i = 0; i < 16; ++i) { *q = z; q += S72; }
    }
    out[m * S72] = __float2half(peak);
    float v = peak;
#pragma unroll
    for (int st = 1; st <= 5; ++st) {
        v *= r; r *= Q;
        int i = m + st;
        if (i <= 15) out[i * S72] = __float2half(v);
    }
    v = peak;
#pragma unroll
    for (int st = 1; st <= 5; ++st) {
        v *= s; s *= Q;
        int i = m - st;
        if (i >= 0) out[i * S72] = __float2half(v);
    }
}

__device__ __forceinline__ void frames_from(const float* p,
                                            float e1[3], float e2[3], float e3[3], float t[3]) {
    t[0] = p[3]; t[1] = p[4]; t[2] = p[5];
    float v1x = p[6] - t[0], v1y = p[7] - t[1], v1z = p[8] - t[2];
    float v2x = p[0] - t[0], v2y = p[1] - t[1], v2z = p[2] - t[2];
    float n1 = sqrtf(v1x * v1x + v1y * v1y + v1z * v1z) + 1e-6f;
    e1[0] = v1x / n1; e1[1] = v1y / n1; e1[2] = v1z / n1;
    float dt = v2x * e1[0] + v2y * e1[1] + v2z * e1[2];
    float ux = v2x - dt * e1[0], uy = v2y - dt * e1[1], uz = v2z - dt * e1[2];
    float n2 = sqrtf(ux * ux + uy * uy + uz * uz) + 1e-6f;
    e2[0] = ux / n2; e2[1] = uy / n2; e2[2] = uz / n2;
    e3[0] = e1[1] * e2[2] - e1[2] * e2[1];
    e3[1] = e1[2] * e2[0] - e1[0] * e2[2];
    e3[2] = e1[0] * e2[1] - e1[1] * e2[0];
}

__device__ __forceinline__ float gelu_f(float x) {
    float c = 0.7978845608028654f * (x + 0.044715f * x * x * x);
    float t;
    asm("tanh.approx.f32 %0, %1;" : "=f"(t) : "f"(c));
    return 0.5f * x * (1.0f + t);
}

__global__ void __launch_bounds__(THREADS, 1)
dsd_kernel(const float* __restrict__ pos, const float* __restrict__ dmap,
           const int* __restrict__ nbrs, const int* __restrict__ resi,
           const int* __restrict__ chain, const int* __restrict__ batch,
           const float* __restrict__ maskp,
           const float* __restrict__ Wrel, const float* __restrict__ Wdmap,
           const float* __restrict__ Wdist, const float* __restrict__ Wdir,
           const float* __restrict__ Wrot, const float* __restrict__ Wvec,
           const float* __restrict__ lng, const float* __restrict__ lnb,
           const float* __restrict__ W1, const float* __restrict__ bias1,
           const float* __restrict__ W2, const float* __restrict__ bias2,
           float* __restrict__ outPair, float* __restrict__ outMask)
{
    extern __shared__ float sm[];
    const int tid = threadIdx.x;
    const int k   = tid & 31;
    const int wid = tid >> 5;
    const int mt  = wid & 3;
    const int nt  = wid >> 2;
    const int lkk = tid >> 4;
    const int ls  = tid & 15;

    __half* WDh = (__half*)(sm + OFF_WDH);
    __half* W1h = (__half*)(sm + OFF_W1H);
    __half* W2h = (__half*)(sm + OFF_W2H);
    __half* FT  = (__half*)(sm + OFF_FT);

    // ---- stage constant weights once (all fp16) ----
    for (int i = tid; i < KPAD * 64; i += THREADS) {
        int f = i >> 6, c = i & 63;
        float v;
        if (f < 400)      v = Wdist[f * 64 + c];
        else if (f < 416) v = Wdmap[(f - 400) * 64 + c];
        else if (f < 431) v = Wdir[(f - 416) * 64 + c];
        else if (f < 446) v = Wvec[(f - 431) * 64 + c];
        else if (f < 455) v = Wrot[(f - 446) * 64 + c];
        else              v = 0.0f;
        WDh[f * S72 + c] = __float2half(v);
    }
    for (int i = tid; i < 64 * 128; i += THREADS) {
        int p = i >> 7, h = i & 127;
        W1h[p * S136 + h] = __float2half(W1[i]);
    }
    for (int i = tid; i < 128 * 64; i += THREADS) {
        int j = i >> 6, c = i & 63;
        W2h[j * S72 + c] = __float2half(W2[i]);
    }
    {
        __half z = __float2half(0.0f);
        for (int i = tid; i < 9 * 64; i += THREADS) {
            int r = 455 + i / 64, c = i - (i / 64) * 64;
            FT[r * S72 + c] = z;
        }
    }

    float lgr[4], lbr[4], b1r[8], b2r[4];
#pragma unroll
    for (int i = 0; i < 4; ++i) {
        lgr[i] = lng[ls * 4 + i];
        lbr[i] = lnb[ls * 4 + i];
    }
#pragma unroll
    for (int t = 0; t < 4; ++t) {
        b1r[2 * t + 0] = bias1[nt * 32 + t * 8 + (k & 3) * 2 + 0];
        b1r[2 * t + 1] = bias1[nt * 32 + t * 8 + (k & 3) * 2 + 1];
    }
#pragma unroll
    for (int t = 0; t < 2; ++t) {
        b2r[2 * t + 0] = bias2[nt * 16 + t * 8 + (k & 3) * 2 + 0];
        b2r[2 * t + 1] = bias2[nt * 16 + t * 8 + (k & 3) * 2 + 1];
    }

    // validated mma base addresses
    const u32 FTS = (u32)__cvta_generic_to_shared(FT);
    const u32 WDS = (u32)__cvta_generic_to_shared(WDh);
    const u32 W1S_ = (u32)__cvta_generic_to_shared(W1h);
    const u32 W2S_ = (u32)__cvta_generic_to_shared(W2h);
    const u32 PhS = (u32)__cvta_generic_to_shared(sm + OFF_PH);
    const u32 HHS = (u32)__cvta_generic_to_shared(sm + OFF_HH);
    const u32 SMB = (u32)__cvta_generic_to_shared(sm);      // base for cp.async dsts
    const u32 aAddr0 = FTS + ((k & 7) + ((k >> 4) & 1) * 8) * 144 + (mt * 16 + ((k >> 3) & 1) * 8) * 2;
    const u32 bAddr0 = WDS + ((k & 7) + ((k >> 3) & 1) * 8) * 144 + (nt * 16 + ((k >> 4) & 1) * 8) * 2;
    const u32 aP0 = PhS + (mt * 16 + (k & 7) + ((k >> 3) & 1) * 8) * 144 + ((k >> 4) & 1) * 16;
    const u32 bW1 = W1S_ + ((k & 7) + ((k >> 3) & 1) * 8) * 272 + (nt * 32 + ((k >> 4) & 1) * 8) * 2;
    const u32 aH0 = HHS + (mt * 16 + (k & 7) + ((k >> 3) & 1) * 8) * 272 + ((k >> 4) & 1) * 16;
    const u32 bW2 = W2S_ + ((k & 7) + ((k >> 3) & 1) * 8) * 144 + (nt * 16 + ((k >> 4) & 1) * 8) * 2;

    // rebalanced task-B assignment
    const int dpB = (wid >= 10 && wid < 15) ? (6 + wid) : ((wid < 4) ? (21 + wid) : -1);

    int* smi = (int*)sm;
    const int stride2 = gridDim.x * 2;

    __syncthreads();

    // ================= PROLOGUE: fill par=0 buffers =================
    {
        int nb0 = blockIdx.x * 2;
        if (tid < 64) {
            int bb = tid >> 5, kk = tid & 31;
            int n = nb0 + bb;
            int nb = nbrs[n * KC + kk];
            int j = nb < 0 ? 0 : nb;
            float valid = (nb != -1) ? 1.0f : 0.0f;
            smi[OFF_SJ + bb * 32 + kk] = j;
            int dr = resi[j] - resi[n];
            dr = dr < -32 ? -32 : (dr > 32 ? 32 : dr);
            smi[OFF_SREL + bb * 32 + kk] = dr + 32;
            float same = (chain[j] == chain[n] && batch[j] == batch[n]) ? 1.0f : 0.0f;
            sm[OFF_SSAME + bb * 32 + kk] = same;
            float pm = maskp[n] * maskp[j] * valid;
            sm[OFF_SPM + bb * 32 + kk] = pm;
            outMask[n * KC + kk] = pm;
        } else if (tid < 66) {
            int bb = tid - 64;
            float e1[3], e2[3], e3[3], t[3], prow[9];
#pragma unroll
            for (int i = 0; i < 9; ++i) prow[i] = pos[(nb0 + bb) * 15 + i];
            frames_from(prow, e1, e2, e3, t);
#pragma unroll
            for (int r = 0; r < 3; ++r) {
                sm[OFF_RN + bb * 12 + r * 3 + 0] = e1[r];
                sm[OFF_RN + bb * 12 + r * 3 + 1] = e2[r];
                sm[OFF_RN + bb * 12 + r * 3 + 2] = e3[r];
            }
            sm[OFF_RN + bb * 12 + 9 + 0] = t[0];
            sm[OFF_RN + bb * 12 + 9 + 1] = t[1];
            sm[OFF_RN + bb * 12 + 9 + 2] = t[2];
        } else if (tid >= 96 && tid < 126) {
            int bb = (tid - 96) / 15, e = (tid - 96) % 15;
            sm[OFF_POSN + bb * 16 + e] = pos[(nb0 + bb) * 15 + e];
        }
        __syncthreads();
        for (int i = tid; i < 960; i += THREADS) {
            int bb = i / 480, r2 = i - bb * 480;
            int kk = r2 / 15, e = r2 - kk * 15;
            int j = smi[OFF_SJ + bb * 32 + kk];
            sm[OFF_PJ + bb * 544 + kk * 17 + e] = pos[j * 15 + e];
        }
        if (tid < 64) {
            int bb = tid >> 5;
            int j = smi[OFF_SJ + tid];
            sm[OFF_DM + tid] = __ldg(&dmap[(long)(nb0 + bb) * Ntot + j]);
        }
        __syncthreads();
    }

    int iter = 0;
    for (int n0 = blockIdx.x * 2; n0 < Ntot; n0 += stride2, ++iter) {
        const int par  = iter & 1;
        const int parn = par ^ 1;
        const int nN   = n0 + stride2;
        const bool hasNext = (nN < Ntot);

        // ---------- P3: build features into F^T ----------
        for (int bb = 0; bb < 2; ++bb) {
            __half* fT = FT + (bb * 32 + k);
            const float* pn = sm + OFF_POSN + par * 32 + bb * 16;
            const float* pj = sm + OFF_PJ + par * 1088 + bb * 544 + k * 17;
            const float* rn = sm + OFF_RN + par * 24 + bb * 12;
            {
                int a = wid / 5, c5 = wid - a * 5;
                float dx = pn[a * 3 + 0] - pj[c5 * 3 + 0];
                float dy = pn[a * 3 + 1] - pj[c5 * 3 + 1];
                float dz = pn[a * 3 + 2] - pj[c5 * 3 + 2];
                float d = sqrtf(dx * dx + dy * dy + dz * dz);
                rbf16s(d, fT + (wid * 16) * S72);
            }
            if (dpB >= 0) {
                int a = dpB / 5, c5 = dpB - a * 5;
                float dx = pn[a * 3 + 0] - pj[c5 * 3 + 0];
                float dy = pn[a * 3 + 1] - pj[c5 * 3 + 1];
                float dz = pn[a * 3 + 2] - pj[c5 * 3 + 2];
                float d = sqrtf(dx * dx + dy * dy + dz * dz);
                rbf16s(d, fT + (dpB * 16) * S72);
            }
            if (wid == 9) {
                float pm = sm[OFF_SPM + par * 64 + bb * 32 + k];
                float dval = sm[OFF_DM + par * 64 + bb * 32 + k];
                if (pm > 0.0f) {
                    rbf16s(dval, fT + 400 * S72);
                } else {
                    __half z = __float2half(0.0f);
#pragma unroll
                    for (int i = 0; i < 16; ++i) fT[(400 + i) * S72] = z;
                }
            } else if (wid >= 10 && wid < 15) {
                int a = wid - 10;
                float v0 = pj[a * 3 + 0] - rn[9 + 0];
                float v1 = pj[a * 3 + 1] - rn[9 + 1];
                float v2 = pj[a * 3 + 2] - rn[9 + 2];
                float rv[3];
#pragma unroll
                for (int i = 0; i < 3; ++i)
                    rv[i] = rn[0 + i] * v0 + rn[3 + i] * v1 + rn[6 + i] * v2;
                float nr = sqrtf(rv[0] * rv[0] + rv[1] * rv[1] + rv[2] * rv[2]);
                float inv = 1.0f / (nr + 1e-6f);
#pragma unroll
                for (int i = 0; i < 3; ++i) {
                    fT[(416 + a * 3 + i) * S72] = __float2half(rv[i] * inv);
                    fT[(431 + a * 3 + i) * S72] = __float2half(rv[i] * 0.1f);
                }
            } else if (wid == 15) {
                float e1j[3], e2j[3], e3j[3], tj[3];
                frames_from(pj, e1j, e2j, e3j, tj);
#pragma unroll
                for (int i = 0; i < 3; ++i) {
                    float r0 = rn[0 + i], r1 = rn[3 + i], r2 = rn[6 + i];
                    fT[(446 + i * 3 + 0) * S72] = __float2half(r0 * e1j[0] + r1 * e1j[1] + r2 * e1j[2]);
                    fT[(446 + i * 3 + 1) * S72] = __float2half(r0 * e2j[0] + r1 * e2j[1] + r2 * e2j[2]);
                    fT[(446 + i * 3 + 2) * S72] = __float2half(r0 * e3j[0] + r1 * e3j[1] + r2 * e3j[2]);
                }
            }
        }
        __syncthreads();

        // ---------- P4: Wrel prefetch + first-level prefetch (cp.async posn) + GEMM ----------
        float4 wrA, wrC;
        {
            int relA = smi[OFF_SREL + par * 64 + lkk];
            int relC = smi[OFF_SREL + par * 64 + 32 + lkk];
            wrA = __ldg(reinterpret_cast<const float4*>(Wrel) + relA * 16 + ls);
            wrC = __ldg(reinterpret_cast<const float4*>(Wrel) + relC * 16 + ls);
        }
        int nbv = -1;
        if (hasNext) {
            if (tid < 64) {
                int bb = tid >> 5, kk = tid & 31;
                nbv = nbrs[(nN + bb) * KC + kk];
            } else if (tid >= 96 && tid < 126) {
                int bb = (tid - 96) / 15, e = (tid - 96) % 15;
                CPA4(SMB + (OFF_POSN + parn * 32 + bb * 16 + e) * 4,
                     pos + (long)(nN + bb) * 15 + e);
            }
            CPA_COMMIT();
        }
        {
            float d0 = 0.f, d1 = 0.f, d2 = 0.f, d3 = 0.f;
            float d4 = 0.f, d5 = 0.f, d6 = 0.f, d7 = 0.f;
            u32 aA = aAddr0, bA = bAddr0;
            u32 xa0, xa1, xa2, xa3, xb0, xb1, xb2, xb3;
            u32 ya0, ya1, ya2, ya3, yb0, yb1, yb2, yb3;
            LDSM4T(xa0, xa1, xa2, xa3, aA);
            LDSM4T(xb0, xb1, xb2, xb3, bA);
#pragma unroll 1
            for (int s = 0; s < 14; ++s) {
                aA += 2304; bA += 2304;
                LDSM4T(ya0, ya1, ya2, ya3, aA);
                LDSM4T(yb0, yb1, yb2, yb3, bA);
                MMA16816(d0, d1, d2, d3, xa0, xa1, xa2, xa3, xb0, xb1);
                MMA16816(d4, d5, d6, d7, xa0, xa1, xa2, xa3, xb2, xb3);
                aA += 2304; bA += 2304;
                LDSM4T(xa0, xa1, xa2, xa3, aA);
                LDSM4T(xb0, xb1, xb2, xb3, bA);
                MMA16816(d0, d1, d2, d3, ya0, ya1, ya2, ya3, yb0, yb1);
                MMA16816(d4, d5, d6, d7, ya0, ya1, ya2, ya3, yb2, yb3);
            }
            MMA16816(d0, d1, d2, d3, xa0, xa1, xa2, xa3, xb0, xb1);
            MMA16816(d4, d5, d6, d7, xa0, xa1, xa2, xa3, xb2, xb3);

            float* P = sm + ((mt >> 1) ? OFF_P1 : OFF_P0);
            int kk1 = (mt & 1) * 16 + (k >> 2);
            int kk2 = kk1 + 8;
            int col = nt * 16 + (k & 3) * 2;
            *reinterpret_cast<float2*>(P + kk1 * 66 + col)     = make_float2(d0, d1);
            *reinterpret_cast<float2*>(P + kk2 * 66 + col)     = make_float2(d2, d3);
            *reinterpret_cast<float2*>(P + kk1 * 66 + col + 8) = make_float2(d4, d5);
            *reinterpret_cast<float2*>(P + kk2 * 66 + col + 8) = make_float2(d6, d7);
        }
        if (hasNext) {
            if (tid < 64) {
                int bb = tid >> 5, kk = tid & 31;
                int j = nbv < 0 ? 0 : nbv;
                smi[OFF_SJ + parn * 64 + bb * 32 + kk] = j;
            }
            CPA_WAIT0();
        }
        __syncthreads();

        // ---------- P5: + Wrel, LayerNorm -> Ph ; frames for nN from POSN[parn] ----------
        if (hasNext && tid < 2) {
            int bb = tid;
            float e1[3], e2[3], e3[3], t[3];
            frames_from(sm + OFF_POSN + parn * 32 + bb * 16, e1, e2, e3, t);
#pragma unroll
            for (int r = 0; r < 3; ++r) {
                sm[OFF_RN + parn * 24 + bb * 12 + r * 3 + 0] = e1[r];
                sm[OFF_RN + parn * 24 + bb * 12 + r * 3 + 1] = e2[r];
                sm[OFF_RN + parn * 24 + bb * 12 + r * 3 + 2] = e3[r];
            }
            sm[OFF_RN + parn * 24 + bb * 12 + 9 + 0] = t[0];
            sm[OFF_RN + parn * 24 + bb * 12 + 9 + 1] = t[1];
            sm[OFF_RN + parn * 24 + bb * 12 + 9 + 2] = t[2];
        }
        {
            float a0 = sm[OFF_P0 + lkk * 66 + ls * 4 + 0];
            float a1 = sm[OFF_P0 + lkk * 66 + ls * 4 + 1];
            float a2 = sm[OFF_P0 + lkk * 66 + ls * 4 + 2];
            float a3 = sm[OFF_P0 + lkk * 66 + ls * 4 + 3];
            float c0 = sm[OFF_P1 + lkk * 66 + ls * 4 + 0];
            float c1 = sm[OFF_P1 + lkk * 66 + ls * 4 + 1];
            float c2 = sm[OFF_P1 + lkk * 66 + ls * 4 + 2];
            float c3 = sm[OFF_P1 + lkk * 66 + ls * 4 + 3];
            {
                float same = sm[OFF_SSAME + par * 64 + lkk];
                a0 = fmaf(same, wrA.x, a0); a1 = fmaf(same, wrA.y, a1);
                a2 = fmaf(same, wrA.z, a2); a3 = fmaf(same, wrA.w, a3);
            }
            {
                float same = sm[OFF_SSAME + par * 64 + 32 + lkk];
                c0 = fmaf(same, wrC.x, c0); c1 = fmaf(same, wrC.y, c1);
                c2 = fmaf(same, wrC.z, c2); c3 = fmaf(same, wrC.w, c3);
            }
            __half2* ph2 = (__half2*)(sm + OFF_PH);
            {
                float ssum = a0 + a1 + a2 + a3;
                ssum += __shfl_xor_sync(0xffffffffu, ssum, 8);
                ssum += __shfl_xor_sync(0xffffffffu, ssum, 4);
                ssum += __shfl_xor_sync(0xffffffffu, ssum, 2);
                ssum += __shfl_xor_sync(0xffffffffu, ssum, 1);
                float mu = ssum * 0.015625f;
                float e0 = a0 - mu, e1 = a1 - mu, e2 = a2 - mu, e3 = a3 - mu;
                float sq = e0 * e0 + e1 * e1 + e2 * e2 + e3 * e3;
                sq += __shfl_xor_sync(0xffffffffu, sq, 8);
                sq += __shfl_xor_sync(0xffffffffu, sq, 4);
                sq += __shfl_xor_sync(0xffffffffu, sq, 2);
                sq += __shfl_xor_sync(0xffffffffu, sq, 1);
                float inv = rsqrtf(sq * 0.015625f + 1e-5f);
                ph2[lkk * 36 + ls * 2 + 0] = __floats2half2_rn(lgr[0] * e0 * inv + lbr[0],
                                                               lgr[1] * e1 * inv + lbr[1]);
                ph2[lkk * 36 + ls * 2 + 1] = __floats2half2_rn(lgr[2] * e2 * inv + lbr[2],
                                                               lgr[3] * e3 * inv + lbr[3]);
            }
            {
                float ssum = c0 + c1 + c2 + c3;
                ssum += __shfl_xor_sync(0xffffffffu, ssum, 8);
                ssum += __shfl_xor_sync(0xffffffffu, ssum, 4);
                ssum += __shfl_xor_sync(0xffffffffu, ssum, 2);
                ssum += __shfl_xor_sync(0xffffffffu, ssum, 1);
                float mu = ssum * 0.015625f;
                float e0 = c0 - mu, e1 = c1 - mu, e2 = c2 - mu, e3 = c3 - mu;
                float sq = e0 * e0 + e1 * e1 + e2 * e2 + e3 * e3;
                sq += __shfl_xor_sync(0xffffffffu, sq, 8);
                sq += __shfl_xor_sync(0xffffffffu, sq, 4);
                sq += __shfl_xor_sync(0xffffffffu, sq, 2);
                sq += __shfl_xor_sync(0xffffffffu, sq, 1);
                float inv = rsqrtf(sq * 0.015625f + 1e-5f);
                ph2[(32 + lkk) * 36 + ls * 2 + 0] = __floats2half2_rn(lgr[0] * e0 * inv + lbr[0],
                                                                      lgr[1] * e1 * inv + lbr[1]);
                ph2[(32 + lkk) * 36 + ls * 2 + 1] = __floats2half2_rn(lgr[2] * e2 * inv + lbr[2],
                                                                      lgr[3] * e3 * inv + lbr[3]);
            }
        }
        __syncthreads();

        // ---------- P6: MLP1 mma + second-level prefetch via cp.async ----------
        int rjv = 0, rnv = 0, cjv = 0, cnv = 0, bjv = 0, bnv = 0;
        float mjv = 0.0f, mnv = 0.0f;
        if (hasNext) {
            {   // PJ gather item 0 (pure copy -> cp.async)
                int bb = tid / 480, r2 = tid - bb * 480;
                int kk = r2 / 15, e = r2 - kk * 15;
                int j = smi[OFF_SJ + parn * 64 + bb * 32 + kk];
                CPA4(SMB + (OFF_PJ + parn * 1088 + bb * 544 + kk * 17 + e) * 4,
                     pos + (long)j * 15 + e);
            }
            if (tid < 448) {   // PJ gather item 1
                int i1 = tid + 512;
                int bb = i1 / 480, r2 = i1 - bb * 480;
                int kk = r2 / 15, e = r2 - kk * 15;
                int j = smi[OFF_SJ + parn * 64 + bb * 32 + kk];
                CPA4(SMB + (OFF_PJ + parn * 1088 + bb * 544 + kk * 17 + e) * 4,
                     pos + (long)j * 15 + e);
            }
            if (tid < 64) {
                int bb = tid >> 5;
                int nn = nN + bb;
                int j = smi[OFF_SJ + parn * 64 + tid];
                CPA4(SMB + (OFF_DM + parn * 64 + tid) * 4,
                     dmap + (long)nn * Ntot + j);
                rjv = resi[j]; rnv = resi[nn];
                cjv = chain[j]; cnv = chain[nn];
                bjv = batch[j]; bnv = batch[nn];
                mjv = maskp[j]; mnv = maskp[nn];
            }
            CPA_COMMIT();
        }
        {
            float c[16];
#pragma unroll
            for (int j = 0; j < 16; ++j) c[j] = 0.0f;
            u32 aA = aP0, bA = bW1;
#pragma unroll
            for (int s = 0; s < 4; ++s) {
                u32 ra0, ra1, ra2, ra3, rb0, rb1, rb2, rb3, rc0, rc1, rc2, rc3;
                LDSM4(ra0, ra1, ra2, ra3, aA);
                LDSM4T(rb0, rb1, rb2, rb3, bA);
                LDSM4T(rc0, rc1, rc2, rc3, bA + 32);
                aA += 32;
                bA += 4352;
                MMA16816(c[0],  c[1],  c[2],  c[3],  ra0, ra1, ra2, ra3, rb0, rb1);
                MMA16816(c[4],  c[5],  c[6],  c[7],  ra0, ra1, ra2, ra3, rb2, rb3);
                MMA16816(c[8],  c[9],  c[10], c[11], ra0, ra1, ra2, ra3, rc0, rc1);
                MMA16816(c[12], c[13], c[14], c[15], ra0, ra1, ra2, ra3, rc2, rc3);
            }
            __half2* hh2 = (__half2*)(sm + OFF_HH);
            int r1 = mt * 16 + (k >> 2), r2 = r1 + 8;
#pragma unroll
            for (int t = 0; t < 4; ++t) {
                float g0 = gelu_f(c[4 * t + 0] + b1r[2 * t + 0]);
                float g1 = gelu_f(c[4 * t + 1] + b1r[2 * t + 1]);
                float g2 = gelu_f(c[4 * t + 2] + b1r[2 * t + 0]);
                float g3 = gelu_f(c[4 * t + 3] + b1r[2 * t + 1]);
                int cw = nt * 16 + t * 4 + (k & 3);
                hh2[r1 * 68 + cw] = __floats2half2_rn(g0, g1);
                hh2[r2 * 68 + cw] = __floats2half2_rn(g2, g3);
            }
        }
        if (hasNext) {
            if (tid < 64) {
                int bb = tid >> 5, kk = tid & 31;
                int dr = rjv - rnv;
                dr = dr < -32 ? -32 : (dr > 32 ? 32 : dr);
                smi[OFF_SREL + parn * 64 + tid] = dr + 32;
                float same = (cjv == cnv && bjv == bnv) ? 1.0f : 0.0f;
                sm[OFF_SSAME + parn * 64 + tid] = same;
                float valid = (nbv != -1) ? 1.0f : 0.0f;
                float pm = mnv * mjv * valid;
                sm[OFF_SPM + parn * 64 + tid] = pm;
                outMask[(nN + bb) * KC + kk] = pm;
            }
            CPA_WAIT0();
        }
        __syncthreads();

        // ---------- P7: MLP2 mma + gmem write (no trailing barrier) ----------
        {
            float d0 = 0.f, d1 = 0.f, d2 = 0.f, d3 = 0.f;
            float d4 = 0.f, d5 = 0.f, d6 = 0.f, d7 = 0.f;
            u32 aA = aH0, bA = bW2;
#pragma unroll
            for (int s = 0; s < 8; ++s) {
                u32 ra0, ra1, ra2, ra3, rb0, rb1, rb2, rb3;
                LDSM4(ra0, ra1, ra2, ra3, aA);
                LDSM4T(rb0, rb1, rb2, rb3, bA);
                aA += 32;
                bA += 2304;
                MMA16816(d0, d1, d2, d3, ra0, ra1, ra2, ra3, rb0, rb1);
                MMA16816(d4, d5, d6, d7, ra0, ra1, ra2, ra3, rb2, rb3);
            }
            d0 += b2r[0]; d1 += b2r[1]; d2 += b2r[0]; d3 += b2r[1];
            d4 += b2r[2]; d5 += b2r[3]; d6 += b2r[2]; d7 += b2r[3];
            int r1 = mt * 16 + (k >> 2), r2 = r1 + 8;
            int col = nt * 16 + (k & 3) * 2;
            long i1 = ((long)(n0 + (r1 >> 5)) * 32 + (r1 & 31)) * 64;
            long i2 = ((long)(n0 + (r2 >> 5)) * 32 + (r2 & 31)) * 64;
            *reinterpret_cast<float2*>(outPair + i1 + col)     = make_float2(d0, d1);
            *reinterpret_cast<float2*>(outPair + i2 + col)     = make_float2(d2, d3);
            *reinterpret_cast<float2*>(outPair + i1 + col + 8) = make_float2(d4, d5);
            *reinterpret_cast<float2*>(outPair + i2 + col + 8) = make_float2(d6, d7);
        }
        // no trailing barrier: next P3 writes FT / reads prefetch buffers sealed above
    }
}

extern "C" void kernel_launch(void* const* d_in, const int* in_sizes, int n_in,
                              void* d_out, int out_size) {
    const float* pos   = (const float*)d_in[0];
    const float* dmap  = (const float*)d_in[1];
    const int*   nbrs  = (const int*)d_in[2];
    const int*   resi  = (const int*)d_in[3];
    const int*   chain = (const int*)d_in[4];
    const int*   batch = (const int*)d_in[5];
    const float* maskp = (const float*)d_in[6];
    const float* Wrel  = (const float*)d_in[7];
    const float* Wdmap = (const float*)d_in[8];
    const float* Wdist = (const float*)d_in[9];
    const float* Wdir  = (const float*)d_in[10];
    const float* Wrot  = (const float*)d_in[11];
    const float* Wvec  = (const float*)d_in[12];
    const float* lng   = (const float*)d_in[13];
    const float* lnb   = (const float*)d_in[14];
    const float* W1    = (const float*)d_in[15];
    const float* b1    = (const float*)d_in[16];
    const float* W2    = (const float*)d_in[17];
    const float* b2    = (const float*)d_in[18];

    float* outPair = (float*)d_out;
    float* outMask = outPair + (long)Ntot * KC * PC;

    cudaFuncSetAttribute(dsd_kernel, cudaFuncAttributeMaxDynamicSharedMemorySize, SMEMF * 4);
    int sms = 148;
    cudaDeviceGetAttribute(&sms, cudaDevAttrMultiProcessorCount, 0);

    dsd_kernel<<<sms, THREADS, SMEMF * 4>>>(
        pos, dmap, nbrs, resi, chain, batch, maskp,
        Wrel, Wdmap, Wdist, Wdir, Wrot, Wvec, lng, lnb, W1, b1, W2, b2,
        outPair, outMask);
}

// round 16
// speedup vs baseline: 5.6763x; 1.1090x over previous
#include <cuda_runtime.h>
#include <cuda_fp16.h>
#include <cstdint>
#include <math.h>

typedef unsigned long long ull;
typedef unsigned int u32;

#define Ntot 8192
#define KC   32
#define PC   64
#define KPAD  464            // 29 * 16
#define THREADS 512

// ---- shared weights (float offsets) ----
#define OFF_WDH   0                        // half[464][72]  = 16704 fl
#define OFF_W1H   16704                    // half[64][136]  = 4352 fl
#define OFF_W2H   21056                    // half[128][72]  = 4608 fl
#define OFF_HALF0 25664
#define HALF_FL   16184
// per-half relative offsets (floats)
#define R_FT    0        // F^T half[464][40] = 9280 fl
#define R_HH    9280     // Hh half[32][136] = 2176 fl
#define R_P     11456    // fp32 [32][66] = 2112 fl
#define R_PH    13568    // pair half[32][72] = 1152 fl
#define R_PJ    14720    // [par][32][17] = 1088 fl
#define R_POSN  15808    // [par][16] = 32
#define R_RN    15840    // [par][12] = 24
#define R_SJ    15864    // [par][32] ints = 64
#define R_SREL  15928    // 64
#define R_SSAME 15992    // 64
#define R_SPM   16056    // 64
#define R_DM    16120    // 64 -> 16184
#define SMEMF   (OFF_HALF0 + 2 * HALF_FL)   // 58032 fl = 232128 B

// ---- tensor-core helpers ----
#define LDSM4(q0, q1, q2, q3, addr) \
    asm volatile("ldmatrix.sync.aligned.m8n8.x4.shared.b16 {%0,%1,%2,%3}, [%4];" \
                 : "=r"(q0), "=r"(q1), "=r"(q2), "=r"(q3) : "r"(addr))
#define LDSM4T(q0, q1, q2, q3, addr) \
    asm volatile("ldmatrix.sync.aligned.m8n8.x4.trans.shared.b16 {%0,%1,%2,%3}, [%4];" \
                 : "=r"(q0), "=r"(q1), "=r"(q2), "=r"(q3) : "r"(addr))
#define MMA16816(d0, d1, d2, d3, q0, q1, q2, q3, p0, p1) \
    asm volatile("mma.sync.aligned.m16n8k16.row.col.f32.f16.f16.f32 " \
                 "{%0,%1,%2,%3}, {%4,%5,%6,%7}, {%8,%9}, {%0,%1,%2,%3};" \
                 : "+f"(d0), "+f"(d1), "+f"(d2), "+f"(d3) \
                 : "r"(q0), "r"(q1), "r"(q2), "r"(q3), "r"(p0), "r"(p1))

// ---- cp.async helpers ----
#define CPA4(dst, src) \
    asm volatile("cp.async.ca.shared.global [%0], [%1], 4;" :: "r"(dst), "l"(src) : "memory")
#define CPA_COMMIT() asm volatile("cp.async.commit_group;" ::: "memory")
#define CPA_WAIT0()  asm volatile("cp.async.wait_group 0;" ::: "memory")

// named barrier for this half (id 1 or 2), 256 threads
#define BARH() asm volatile("bar.sync %0, 256;" :: "r"(1 + h) : "memory")

// ---------------- RBF: peak + ±5-step walk, fp16-exact, stride 40 ----------------
__device__ __forceinline__ void rbf16s(float d, __half* out) {
    const float SI = 0.72727272727f;
    const float G  = 1.06666666667f;
    const float Q  = 0.10273954f;
    float g = d * SI;
    int m = __float2int_rn(g * 0.9375f);
    m = m < 0 ? 0 : (m > 15 ? 15 : m);
    float u = g - (float)m * G;
    float peak = __expf(-u * u);
    float r = __expf(G * (2.0f * u - G));
    float s = __expf(-G * (2.0f * u + G));
    {
        __half z = __float2half(0.0f);
        __half* q = out;
#pragma unroll
        for (int i = 0; i < 16; ++i) { *q = z; q += 40; }
    }
    out[m * 40] = __float2half(peak);
    float v = peak;
#pragma unroll
    for (int st = 1; st <= 5; ++st) {
        v *= r; r *= Q;
        int i = m + st;
        if (i <= 15) out[i * 40] = __float2half(v);
    }
    v = peak;
#pragma unroll
    for (int st = 1; st <= 5; ++st) {
        v *= s; s *= Q;
        int i = m - st;
        if (i >= 0) out[i * 40] = __float2half(v);
    }
}

__device__ __forceinline__ void frames_from(const float* p,
                                            float e1[3], float e2[3], float e3[3], float t[3]) {
    t[0] = p[3]; t[1] = p[4]; t[2] = p[5];
    float v1x = p[6] - t[0], v1y = p[7] - t[1], v1z = p[8] - t[2];
    float v2x = p[0] - t[0], v2y = p[1] - t[1], v2z = p[2] - t[2];
    float n1 = sqrtf(v1x * v1x + v1y * v1y + v1z * v1z) + 1e-6f;
    e1[0] = v1x / n1; e1[1] = v1y / n1; e1[2] = v1z / n1;
    float dt = v2x * e1[0] + v2y * e1[1] + v2z * e1[2];
    float ux = v2x - dt * e1[0], uy = v2y - dt * e1[1], uz = v2z - dt * e1[2];
    float n2 = sqrtf(ux * ux + uy * uy + uz * uz) + 1e-6f;
    e2[0] = ux / n2; e2[1] = uy / n2; e2[2] = uz / n2;
    e3[0] = e1[1] * e2[2] - e1[2] * e2[1];
    e3[1] = e1[2] * e2[0] - e1[0] * e2[2];
    e3[2] = e1[0] * e2[1] - e1[1] * e2[0];
}

__device__ __forceinline__ float gelu_f(float x) {
    float c = 0.7978845608028654f * (x + 0.044715f * x * x * x);
    float t;
    asm("tanh.approx.f32 %0, %1;" : "=f"(t) : "f"(c));
    return 0.5f * x * (1.0f + t);
}

__global__ void __launch_bounds__(THREADS, 1)
dsd_kernel(const float* __restrict__ pos, const float* __restrict__ dmap,
           const int* __restrict__ nbrs, const int* __restrict__ resi,
           const int* __restrict__ chain, const int* __restrict__ batch,
           const float* __restrict__ maskp,
           const float* __restrict__ Wrel, const float* __restrict__ Wdmap,
           const float* __restrict__ Wdist, const float* __restrict__ Wdir,
           const float* __restrict__ Wrot, const float* __restrict__ Wvec,
           const float* __restrict__ lng, const float* __restrict__ lnb,
           const float* __restrict__ W1, const float* __restrict__ bias1,
           const float* __restrict__ W2, const float* __restrict__ bias2,
           float* __restrict__ outPair, float* __restrict__ outMask)
{
    extern __shared__ float sm[];
    const int tid = threadIdx.x;
    const int h   = tid >> 8;           // half id 0/1
    const int t   = tid & 255;          // thread within half
    const int w   = t >> 5;             // warp within half (0..7)
    const int k   = t & 31;
    const int mt  = w & 1;              // m-tile (16 rows of 32)
    const int nt  = w >> 1;             // n-tile (0..3)
    const int lkk = t >> 3;             // LN row 0..31
    const int l8  = t & 7;              // LN col-group (8 cols)

    __half* WDh = (__half*)(sm + OFF_WDH);
    __half* W1h = (__half*)(sm + OFF_W1H);
    __half* W2h = (__half*)(sm + OFF_W2H);

    float* Hf = sm + OFF_HALF0 + h * HALF_FL;
    int*   Hi = (int*)Hf;
    __half* FTh = (__half*)(Hf + R_FT);

    // ---- stage constant weights once (full block) ----
    for (int i = tid; i < KPAD * 64; i += THREADS) {
        int f = i >> 6, c = i & 63;
        float v;
        if (f < 400)      v = Wdist[f * 64 + c];
        else if (f < 416) v = Wdmap[(f - 400) * 64 + c];
        else if (f < 431) v = Wdir[(f - 416) * 64 + c];
        else if (f < 446) v = Wvec[(f - 431) * 64 + c];
        else if (f < 455) v = Wrot[(f - 446) * 64 + c];
        else              v = 0.0f;
        WDh[f * 72 + c] = __float2half(v);
    }
    for (int i = tid; i < 64 * 128; i += THREADS) {
        int p = i >> 7, hh = i & 127;
        W1h[p * 136 + hh] = __float2half(W1[i]);
    }
    for (int i = tid; i < 128 * 64; i += THREADS) {
        int j = i >> 6, c = i & 63;
        W2h[j * 72 + c] = __float2half(W2[i]);
    }
    // zero K-pad rows of both halves' FT (455..463, cols 0..31)
    {
        __half z = __float2half(0.0f);
        for (int i = tid; i < 2 * 9 * 32; i += THREADS) {
            int hh = i / 288, r2 = i - hh * 288;
            int r = 455 + r2 / 32, c = r2 & 31;
            ((__half*)(sm + OFF_HALF0 + hh * HALF_FL + R_FT))[r * 40 + c] = z;
        }
    }

    float lgr[8], lbr[8], b1r[8], b2r[4];
#pragma unroll
    for (int i = 0; i < 8; ++i) {
        lgr[i] = lng[l8 * 8 + i];
        lbr[i] = lnb[l8 * 8 + i];
    }
#pragma unroll
    for (int tq = 0; tq < 4; ++tq) {
        b1r[2 * tq + 0] = bias1[nt * 32 + tq * 8 + (k & 3) * 2 + 0];
        b1r[2 * tq + 1] = bias1[nt * 32 + tq * 8 + (k & 3) * 2 + 1];
    }
#pragma unroll
    for (int tq = 0; tq < 2; ++tq) {
        b2r[2 * tq + 0] = bias2[nt * 16 + tq * 8 + (k & 3) * 2 + 0];
        b2r[2 * tq + 1] = bias2[nt * 16 + tq * 8 + (k & 3) * 2 + 1];
    }

    // mma base addresses
    const u32 FTS  = (u32)__cvta_generic_to_shared(FTh);
    const u32 WDS  = (u32)__cvta_generic_to_shared(WDh);
    const u32 W1S_ = (u32)__cvta_generic_to_shared(W1h);
    const u32 W2S_ = (u32)__cvta_generic_to_shared(W2h);
    const u32 PhS  = (u32)__cvta_generic_to_shared(Hf + R_PH);
    const u32 HHS  = (u32)__cvta_generic_to_shared(Hf + R_HH);
    const u32 SMB  = (u32)__cvta_generic_to_shared(sm);
    // stage-4: A = F^T[K][32] stride 80B trans; B = WD stride 144B trans
    const u32 aAddr0 = FTS + ((k & 7) + ((k >> 4) & 1) * 8) * 80 + (mt * 16 + ((k >> 3) & 1) * 8) * 2;
    const u32 bAddr0 = WDS + ((k & 7) + ((k >> 3) & 1) * 8) * 144 + (nt * 16 + ((k >> 4) & 1) * 8) * 2;
    // MLP1: A = Ph[32][72] non-trans; B = W1 stride 272B trans, 32-col group
    const u32 aP0 = PhS + (mt * 16 + (k & 7) + ((k >> 3) & 1) * 8) * 144 + ((k >> 4) & 1) * 16;
    const u32 bW1 = W1S_ + ((k & 7) + ((k >> 3) & 1) * 8) * 272 + (nt * 32 + ((k >> 4) & 1) * 8) * 2;
    // MLP2: A = Hh[32][136] non-trans; B = W2 stride 144B trans
    const u32 aH0 = HHS + (mt * 16 + (k & 7) + ((k >> 3) & 1) * 8) * 272 + ((k >> 4) & 1) * 16;
    const u32 bW2 = W2S_ + ((k & 7) + ((k >> 3) & 1) * 8) * 144 + (nt * 16 + ((k >> 4) & 1) * 8) * 2;

    const int stride2 = gridDim.x * 2;
    const int nBase = blockIdx.x * 2 + h;

    __syncthreads();   // weights + pad ready for both halves

    // ================= PROLOGUE (per half): fill par=0 buffers for n = nBase =================
    {
        int n = nBase;
        if (t < 32) {
            int nb = nbrs[n * KC + t];
            int j = nb < 0 ? 0 : nb;
            float valid = (nb != -1) ? 1.0f : 0.0f;
            Hi[R_SJ + t] = j;
            int dr = resi[j] - resi[n];
            dr = dr < -32 ? -32 : (dr > 32 ? 32 : dr);
            Hi[R_SREL + t] = dr + 32;
            float same = (chain[j] == chain[n] && batch[j] == batch[n]) ? 1.0f : 0.0f;
            Hf[R_SSAME + t] = same;
            float pm = maskp[n] * maskp[j] * valid;
            Hf[R_SPM + t] = pm;
            outMask[n * KC + t] = pm;
        } else if (t == 32) {
            float e1[3], e2[3], e3[3], tt[3], prow[9];
#pragma unroll
            for (int i = 0; i < 9; ++i) prow[i] = pos[n * 15 + i];
            frames_from(prow, e1, e2, e3, tt);
#pragma unroll
            for (int r = 0; r < 3; ++r) {
                Hf[R_RN + r * 3 + 0] = e1[r];
                Hf[R_RN + r * 3 + 1] = e2[r];
                Hf[R_RN + r * 3 + 2] = e3[r];
            }
            Hf[R_RN + 9 + 0] = tt[0]; Hf[R_RN + 9 + 1] = tt[1]; Hf[R_RN + 9 + 2] = tt[2];
        } else if (t >= 48 && t < 63) {
            Hf[R_POSN + (t - 48)] = pos[n * 15 + (t - 48)];
        }
        BARH();
        for (int i = t; i < 480; i += 256) {
            int kk = i / 15, e = i - kk * 15;
            int j = Hi[R_SJ + kk];
            Hf[R_PJ + kk * 17 + e] = pos[(long)j * 15 + e];
        }
        if (t < 32) {
            int j = Hi[R_SJ + t];
            Hf[R_DM + t] = __ldg(&dmap[(long)n * Ntot + j]);
        }
        BARH();
    }

    int iter = 0;
    for (int n0 = nBase; n0 < Ntot; n0 += stride2, ++iter) {
        const int par  = iter & 1;
        const int parn = par ^ 1;
        const int nN   = n0 + stride2;
        const bool hasNext = (nN < Ntot);

        // ---------- P3: build features into F^T[464][32] ----------
        {
            __half* fT = FTh + k;
            const float* pn = Hf + R_POSN + par * 16;
            const float* pj = Hf + R_PJ + par * 544 + k * 17;
            const float* rn = Hf + R_RN + par * 12;
            // 3 rbf per warp: dp = w, 8+w, 16+w
#pragma unroll
            for (int q = 0; q < 3; ++q) {
                int dp = q * 8 + w;
                int a = dp / 5, c5 = dp - a * 5;
                float dx = pn[a * 3 + 0] - pj[c5 * 3 + 0];
                float dy = pn[a * 3 + 1] - pj[c5 * 3 + 1];
                float dz = pn[a * 3 + 2] - pj[c5 * 3 + 2];
                float d = sqrtf(dx * dx + dy * dy + dz * dz);
                rbf16s(d, fT + (dp * 16) * 40);
            }
            if (w == 0) {   // dp 24
                float dx = pn[12] - pj[12];
                float dy = pn[13] - pj[13];
                float dz = pn[14] - pj[14];
                float d = sqrtf(dx * dx + dy * dy + dz * dz);
                rbf16s(d, fT + (24 * 16) * 40);
            } else if (w == 1) {   // dmap rbf, masked
                float pm = Hf[R_SPM + par * 32 + k];
                float dval = Hf[R_DM + par * 32 + k];
                if (pm > 0.0f) {
                    rbf16s(dval, fT + 400 * 40);
                } else {
                    __half z = __float2half(0.0f);
#pragma unroll
                    for (int i = 0; i < 16; ++i) fT[(400 + i) * 40] = z;
                }
            } else if (w < 7) {   // dirs + vec, atom a = w-2
                int a = w - 2;
                float v0 = pj[a * 3 + 0] - rn[9 + 0];
                float v1 = pj[a * 3 + 1] - rn[9 + 1];
                float v2 = pj[a * 3 + 2] - rn[9 + 2];
                float rv[3];
#pragma unroll
                for (int i = 0; i < 3; ++i)
                    rv[i] = rn[0 + i] * v0 + rn[3 + i] * v1 + rn[6 + i] * v2;
                float nr = sqrtf(rv[0] * rv[0] + rv[1] * rv[1] + rv[2] * rv[2]);
                float inv = 1.0f / (nr + 1e-6f);
#pragma unroll
                for (int i = 0; i < 3; ++i) {
                    fT[(416 + a * 3 + i) * 40] = __float2half(rv[i] * inv);
                    fT[(431 + a * 3 + i) * 40] = __float2half(rv[i] * 0.1f);
                }
            } else {   // w == 7: rotation features
                float e1j[3], e2j[3], e3j[3], tj[3];
                frames_from(pj, e1j, e2j, e3j, tj);
#pragma unroll
                for (int i = 0; i < 3; ++i) {
                    float r0 = rn[0 + i], r1 = rn[3 + i], r2 = rn[6 + i];
                    fT[(446 + i * 3 + 0) * 40] = __float2half(r0 * e1j[0] + r1 * e1j[1] + r2 * e1j[2]);
                    fT[(446 + i * 3 + 1) * 40] = __float2half(r0 * e2j[0] + r1 * e2j[1] + r2 * e2j[2]);
                    fT[(446 + i * 3 + 2) * 40] = __float2half(r0 * e3j[0] + r1 * e3j[1] + r2 * e3j[2]);
                }
            }
        }
        BARH();

        // ---------- P4: Wrel prefetch + first-level prefetch + pipelined GEMM ----------
        float4 wrA0, wrA1;
        {
            int rel = Hi[R_SREL + par * 32 + lkk];
            wrA0 = __ldg(reinterpret_cast<const float4*>(Wrel) + rel * 16 + l8 * 2);
            wrA1 = __ldg(reinterpret_cast<const float4*>(Wrel) + rel * 16 + l8 * 2 + 1);
        }
        int nbv = -1;
        if (hasNext) {
            if (t < 32) {
                nbv = nbrs[(long)nN * KC + t];
            } else if (t >= 48 && t < 63) {
                CPA4(SMB + (u32)(Hf - sm + R_POSN + parn * 16 + (t - 48)) * 4,
                     pos + (long)nN * 15 + (t - 48));
            }
            CPA_COMMIT();
        }
        {
            float d0 = 0.f, d1 = 0.f, d2 = 0.f, d3 = 0.f;
            float d4 = 0.f, d5 = 0.f, d6 = 0.f, d7 = 0.f;
            u32 aA = aAddr0, bA = bAddr0;
            u32 xa0, xa1, xa2, xa3, xb0, xb1, xb2, xb3;
            u32 ya0, ya1, ya2, ya3, yb0, yb1, yb2, yb3;
            LDSM4T(xa0, xa1, xa2, xa3, aA);
            LDSM4T(xb0, xb1, xb2, xb3, bA);
#pragma unroll 1
            for (int s = 0; s < 14; ++s) {
                aA += 1280; bA += 2304;
                LDSM4T(ya0, ya1, ya2, ya3, aA);
                LDSM4T(yb0, yb1, yb2, yb3, bA);
                MMA16816(d0, d1, d2, d3, xa0, xa1, xa2, xa3, xb0, xb1);
                MMA16816(d4, d5, d6, d7, xa0, xa1, xa2, xa3, xb2, xb3);
                aA += 1280; bA += 2304;
                LDSM4T(xa0, xa1, xa2, xa3, aA);
                LDSM4T(xb0, xb1, xb2, xb3, bA);
                MMA16816(d0, d1, d2, d3, ya0, ya1, ya2, ya3, yb0, yb1);
                MMA16816(d4, d5, d6, d7, ya0, ya1, ya2, ya3, yb2, yb3);
            }
            MMA16816(d0, d1, d2, d3, xa0, xa1, xa2, xa3, xb0, xb1);
            MMA16816(d4, d5, d6, d7, xa0, xa1, xa2, xa3, xb2, xb3);

            float* P = Hf + R_P;
            int kk1 = mt * 16 + (k >> 2);
            int kk2 = kk1 + 8;
            int col = nt * 16 + (k & 3) * 2;
            *reinterpret_cast<float2*>(P + kk1 * 66 + col)     = make_float2(d0, d1);
            *reinterpret_cast<float2*>(P + kk2 * 66 + col)     = make_float2(d2, d3);
            *reinterpret_cast<float2*>(P + kk1 * 66 + col + 8) = make_float2(d4, d5);
            *reinterpret_cast<float2*>(P + kk2 * 66 + col + 8) = make_float2(d6, d7);
        }
        if (hasNext) {
            if (t < 32) {
                int j = nbv < 0 ? 0 : nbv;
                Hi[R_SJ + parn * 32 + t] = j;
            }
            CPA_WAIT0();
        }
        BARH();

        // ---------- P5: + Wrel, LayerNorm -> Ph ; frames for nN ----------
        if (hasNext && t == 0) {
            float e1[3], e2[3], e3[3], tt[3];
            frames_from(Hf + R_POSN + parn * 16, e1, e2, e3, tt);
#pragma unroll
            for (int r = 0; r < 3; ++r) {
                Hf[R_RN + parn * 12 + r * 3 + 0] = e1[r];
                Hf[R_RN + parn * 12 + r * 3 + 1] = e2[r];
                Hf[R_RN + parn * 12 + r * 3 + 2] = e3[r];
            }
            Hf[R_RN + parn * 12 + 9 + 0] = tt[0];
            Hf[R_RN + parn * 12 + 9 + 1] = tt[1];
            Hf[R_RN + parn * 12 + 9 + 2] = tt[2];
        }
        {
            const float* P = Hf + R_P + lkk * 66 + l8 * 8;
            float a0 = P[0], a1 = P[1], a2 = P[2], a3 = P[3];
            float a4 = P[4], a5 = P[5], a6 = P[6], a7 = P[7];
            {
                float same = Hf[R_SSAME + par * 32 + lkk];
                a0 = fmaf(same, wrA0.x, a0); a1 = fmaf(same, wrA0.y, a1);
                a2 = fmaf(same, wrA0.z, a2); a3 = fmaf(same, wrA0.w, a3);
                a4 = fmaf(same, wrA1.x, a4); a5 = fmaf(same, wrA1.y, a5);
                a6 = fmaf(same, wrA1.z, a6); a7 = fmaf(same, wrA1.w, a7);
            }
            float ssum = a0 + a1 + a2 + a3 + a4 + a5 + a6 + a7;
            ssum += __shfl_xor_sync(0xffffffffu, ssum, 4);
            ssum += __shfl_xor_sync(0xffffffffu, ssum, 2);
            ssum += __shfl_xor_sync(0xffffffffu, ssum, 1);
            float mu = ssum * 0.015625f;
            float e0 = a0 - mu, e1 = a1 - mu, e2 = a2 - mu, e3 = a3 - mu;
            float e4 = a4 - mu, e5 = a5 - mu, e6 = a6 - mu, e7 = a7 - mu;
            float sq = e0 * e0 + e1 * e1 + e2 * e2 + e3 * e3 + e4 * e4 + e5 * e5 + e6 * e6 + e7 * e7;
            sq += __shfl_xor_sync(0xffffffffu, sq, 4);
            sq += __shfl_xor_sync(0xffffffffu, sq, 2);
            sq += __shfl_xor_sync(0xffffffffu, sq, 1);
            float inv = rsqrtf(sq * 0.015625f + 1e-5f);
            __half2* ph2 = (__half2*)(Hf + R_PH);
            ph2[lkk * 36 + l8 * 4 + 0] = __floats2half2_rn(lgr[0] * e0 * inv + lbr[0],
                                                           lgr[1] * e1 * inv + lbr[1]);
            ph2[lkk * 36 + l8 * 4 + 1] = __floats2half2_rn(lgr[2] * e2 * inv + lbr[2],
                                                           lgr[3] * e3 * inv + lbr[3]);
            ph2[lkk * 36 + l8 * 4 + 2] = __floats2half2_rn(lgr[4] * e4 * inv + lbr[4],
                                                           lgr[5] * e5 * inv + lbr[5]);
            ph2[lkk * 36 + l8 * 4 + 3] = __floats2half2_rn(lgr[6] * e6 * inv + lbr[6],
                                                           lgr[7] * e7 * inv + lbr[7]);
        }
        BARH();

        // ---------- P6: MLP1 mma + second-level prefetch via cp.async ----------
        int rjv = 0, rnv = 0, cjv = 0, cnv = 0, bjv = 0, bnv = 0;
        float mjv = 0.0f, mnv = 0.0f;
        if (hasNext) {
            {   // PJ gather item 0
                int kk = t / 15, e = t - kk * 15;
                if (kk < 32) {
                    int j = Hi[R_SJ + parn * 32 + kk];
                    CPA4(SMB + (u32)(Hf - sm + R_PJ + parn * 544 + kk * 17 + e) * 4,
                         pos + (long)j * 15 + e);
                }
            }
            if (t < 224) {   // PJ gather item 1
                int i1 = t + 256;
                int kk = i1 / 15, e = i1 - kk * 15;
                int j = Hi[R_SJ + parn * 32 + kk];
                CPA4(SMB + (u32)(Hf - sm + R_PJ + parn * 544 + kk * 17 + e) * 4,
                     pos + (long)j * 15 + e);
            }
            if (t < 32) {
                int j = Hi[R_SJ + parn * 32 + t];
                CPA4(SMB + (u32)(Hf - sm + R_DM + parn * 32 + t) * 4,
                     dmap + (long)nN * Ntot + j);
                rjv = resi[j]; rnv = resi[nN];
                cjv = chain[j]; cnv = chain[nN];
                bjv = batch[j]; bnv = batch[nN];
                mjv = maskp[j]; mnv = maskp[nN];
            }
            CPA_COMMIT();
        }
        {
            float c[16];
#pragma unroll
            for (int j = 0; j < 16; ++j) c[j] = 0.0f;
            u32 aA = aP0, bA = bW1;
#pragma unroll
            for (int s = 0; s < 4; ++s) {
                u32 ra0, ra1, ra2, ra3, rb0, rb1, rb2, rb3, rc0, rc1, rc2, rc3;
                LDSM4(ra0, ra1, ra2, ra3, aA);
                LDSM4T(rb0, rb1, rb2, rb3, bA);
                LDSM4T(rc0, rc1, rc2, rc3, bA + 32);
                aA += 32;
                bA += 4352;
                MMA16816(c[0],  c[1],  c[2],  c[3],  ra0, ra1, ra2, ra3, rb0, rb1);
                MMA16816(c[4],  c[5],  c[6],  c[7],  ra0, ra1, ra2, ra3, rb2, rb3);
                MMA16816(c[8],  c[9],  c[10], c[11], ra0, ra1, ra2, ra3, rc0, rc1);
                MMA16816(c[12], c[13], c[14], c[15], ra0, ra1, ra2, ra3, rc2, rc3);
            }
            __half2* hh2 = (__half2*)(Hf + R_HH);
            int r1 = mt * 16 + (k >> 2), r2 = r1 + 8;
#pragma unroll
            for (int tq = 0; tq < 4; ++tq) {
                float g0 = gelu_f(c[4 * tq + 0] + b1r[2 * tq + 0]);
                float g1 = gelu_f(c[4 * tq + 1] + b1r[2 * tq + 1]);
                float g2 = gelu_f(c[4 * tq + 2] + b1r[2 * tq + 0]);
                float g3 = gelu_f(c[4 * tq + 3] + b1r[2 * tq + 1]);
                int cw = nt * 16 + tq * 4 + (k & 3);
                hh2[r1 * 68 + cw] = __floats2half2_rn(g0, g1);
                hh2[r2 * 68 + cw] = __floats2half2_rn(g2, g3);
            }
        }
        if (hasNext) {
            if (t < 32) {
                int dr = rjv - rnv;
                dr = dr < -32 ? -32 : (dr > 32 ? 32 : dr);
                Hi[R_SREL + parn * 32 + t] = dr + 32;
                float same = (cjv == cnv && bjv == bnv) ? 1.0f : 0.0f;
                Hf[R_SSAME + parn * 32 + t] = same;
                float valid = (nbv != -1) ? 1.0f : 0.0f;
                float pm = mnv * mjv * valid;
                Hf[R_SPM + parn * 32 + t] = pm;
                outMask[(long)nN * KC + t] = pm;
            }
            CPA_WAIT0();
        }
        BARH();

        // ---------- P7: MLP2 mma + gmem write (no trailing barrier) ----------
        {
            float d0 = 0.f, d1 = 0.f, d2 = 0.f, d3 = 0.f;
            float d4 = 0.f, d5 = 0.f, d6 = 0.f, d7 = 0.f;
            u32 aA = aH0, bA = bW2;
#pragma unroll
            for (int s = 0; s < 8; ++s) {
                u32 ra0, ra1, ra2, ra3, rb0, rb1, rb2, rb3;
                LDSM4(ra0, ra1, ra2, ra3, aA);
                LDSM4T(rb0, rb1, rb2, rb3, bA);
                aA += 32;
                bA += 2304;
                MMA16816(d0, d1, d2, d3, ra0, ra1, ra2, ra3, rb0, rb1);
                MMA16816(d4, d5, d6, d7, ra0, ra1, ra2, ra3, rb2, rb3);
            }
            d0 += b2r[0]; d1 += b2r[1]; d2 += b2r[0]; d3 += b2r[1];
            d4 += b2r[2]; d5 += b2r[3]; d6 += b2r[2]; d7 += b2r[3];
            int r1 = mt * 16 + (k >> 2), r2 = r1 + 8;
            int col = nt * 16 + (k & 3) * 2;
            long i1 = ((long)n0 * KC + r1) * 64;
            long i2 = ((long)n0 * KC + r2) * 64;
            *reinterpret_cast<float2*>(outPair + i1 + col)     = make_float2(d0, d1);
            *reinterpret_cast<float2*>(outPair + i2 + col)     = make_float2(d2, d3);
            *reinterpret_cast<float2*>(outPair + i1 + col + 8) = make_float2(d4, d5);
            *reinterpret_cast<float2*>(outPair + i2 + col + 8) = make_float2(d6, d7);
        }
        // no trailing barrier: next P3 writes FT (not touched by P7);
        // prefetch buffers sealed by the post-P6 barrier.
    }
}

extern "C" void kernel_launch(void* const* d_in, const int* in_sizes, int n_in,
                              void* d_out, int out_size) {
    const float* pos   = (const float*)d_in[0];
    const float* dmap  = (const float*)d_in[1];
    const int*   nbrs  = (const int*)d_in[2];
    const int*   resi  = (const int*)d_in[3];
    const int*   chain = (const int*)d_in[4];
    const int*   batch = (const int*)d_in[5];
    const float* maskp = (const float*)d_in[6];
    const float* Wrel  = (const float*)d_in[7];
    const float* Wdmap = (const float*)d_in[8];
    const float* Wdist = (const float*)d_in[9];
    const float* Wdir  = (const float*)d_in[10];
    const float* Wrot  = (const float*)d_in[11];
    const float* Wvec  = (const float*)d_in[12];
    const float* lng   = (const float*)d_in[13];
    const float* lnb   = (const float*)d_in[14];
    const float* W1    = (const float*)d_in[15];
    const float* b1    = (const float*)d_in[16];
    const float* W2    = (const float*)d_in[17];
    const float* b2    = (const float*)d_in[18];

    float* outPair = (float*)d_out;
    float* outMask = outPair + (long)Ntot * KC * PC;

    cudaFuncSetAttribute(dsd_kernel, cudaFuncAttributeMaxDynamicSharedMemorySize, SMEMF * 4);
    int sms = 148;
    cudaDeviceGetAttribute(&sms, cudaDevAttrMultiProcessorCount, 0);

    dsd_kernel<<<sms, THREADS, SMEMF * 4>>>(
        pos, dmap, nbrs, resi, chain, batch, maskp,
        Wrel, Wdmap, Wdist, Wdir, Wrot, Wvec, lng, lnb, W1, b1, W2, b2,
        outPair, outMask);
}

// round 17
// speedup vs baseline: 5.7369x; 1.0107x over previous
#include <cuda_runtime.h>
#include <cuda_fp16.h>
#include <cstdint>
#include <math.h>

typedef unsigned long long ull;
typedef unsigned int u32;

#define Ntot 8192
#define KC   32
#define PC   64
#define KPAD  464            // 29 * 16
#define THREADS 512

// ---- shared weights (float offsets) ----
#define OFF_WDH   0                        // half[464][72]  = 16704 fl
#define OFF_W1H   16704                    // half[64][136]  = 4352 fl
#define OFF_W2H   21056                    // half[128][72]  = 4608 fl
#define OFF_HALF0 25664
#define HALF_FL   16184
// per-half relative offsets (floats)
#define R_FT    0        // F^T half[464][40] = 9280 fl
#define R_HH    9280     // Hh half[32][136] = 2176 fl
#define R_P     11456    // fp32 [32][66] = 2112 fl
#define R_PH    13568    // pair half[32][72] = 1152 fl
#define R_PJ    14720    // [par][32][17] = 1088 fl
#define R_POSN  15808    // [par][16] = 32
#define R_RN    15840    // [par][12] = 24
#define R_SJ    15864    // [par][32] ints = 64
#define R_SREL  15928    // 64
#define R_SSAME 15992    // 64
#define R_SPM   16056    // 64
#define R_DM    16120    // 64 -> 16184
#define SMEMF   (OFF_HALF0 + 2 * HALF_FL)   // 58032 fl = 232128 B

// ---- tensor-core helpers ----
#define LDSM4(q0, q1, q2, q3, addr) \
    asm volatile("ldmatrix.sync.aligned.m8n8.x4.shared.b16 {%0,%1,%2,%3}, [%4];" \
                 : "=r"(q0), "=r"(q1), "=r"(q2), "=r"(q3) : "r"(addr))
#define LDSM4T(q0, q1, q2, q3, addr) \
    asm volatile("ldmatrix.sync.aligned.m8n8.x4.trans.shared.b16 {%0,%1,%2,%3}, [%4];" \
                 : "=r"(q0), "=r"(q1), "=r"(q2), "=r"(q3) : "r"(addr))
#define MMA16816(d0, d1, d2, d3, q0, q1, q2, q3, p0, p1) \
    asm volatile("mma.sync.aligned.m16n8k16.row.col.f32.f16.f16.f32 " \
                 "{%0,%1,%2,%3}, {%4,%5,%6,%7}, {%8,%9}, {%0,%1,%2,%3};" \
                 : "+f"(d0), "+f"(d1), "+f"(d2), "+f"(d3) \
                 : "r"(q0), "r"(q1), "r"(q2), "r"(q3), "r"(p0), "r"(p1))

// ---- cp.async helpers ----
#define CPA4(dst, src) \
    asm volatile("cp.async.ca.shared.global [%0], [%1], 4;" :: "r"(dst), "l"(src) : "memory")
#define CPA_COMMIT() asm volatile("cp.async.commit_group;" ::: "memory")
#define CPA_WAIT0()  asm volatile("cp.async.wait_group 0;" ::: "memory")

// named barrier for this half (id 1 or 2), 256 threads
#define BARH() asm volatile("bar.sync %0, 256;" :: "r"(1 + h) : "memory")

// ---------------- RBF: peak + ±5-step walk into PRE-ZEROED bins (fp16-exact) ----------------
__device__ __forceinline__ void rbf16s(float d, __half* out) {
    const float SI = 0.72727272727f;
    const float G  = 1.06666666667f;
    const float Q  = 0.10273954f;
    float g = d * SI;
    int m = __float2int_rn(g * 0.9375f);
    m = m < 0 ? 0 : (m > 15 ? 15 : m);
    float u = g - (float)m * G;
    float peak = __expf(-u * u);
    float r = __expf(G * (2.0f * u - G));
    float s = __expf(-G * (2.0f * u + G));
    out[m * 40] = __float2half(peak);
    float v = peak;
#pragma unroll
    for (int st = 1; st <= 5; ++st) {
        v *= r; r *= Q;
        int i = m + st;
        if (i <= 15) out[i * 40] = __float2half(v);
    }
    v = peak;
#pragma unroll
    for (int st = 1; st <= 5; ++st) {
        v *= s; s *= Q;
        int i = m - st;
        if (i >= 0) out[i * 40] = __float2half(v);
    }
}

__device__ __forceinline__ void frames_from(const float* p,
                                            float e1[3], float e2[3], float e3[3], float t[3]) {
    t[0] = p[3]; t[1] = p[4]; t[2] = p[5];
    float v1x = p[6] - t[0], v1y = p[7] - t[1], v1z = p[8] - t[2];
    float v2x = p[0] - t[0], v2y = p[1] - t[1], v2z = p[2] - t[2];
    float n1 = sqrtf(v1x * v1x + v1y * v1y + v1z * v1z) + 1e-6f;
    e1[0] = v1x / n1; e1[1] = v1y / n1; e1[2] = v1z / n1;
    float dt = v2x * e1[0] + v2y * e1[1] + v2z * e1[2];
    float ux = v2x - dt * e1[0], uy = v2y - dt * e1[1], uz = v2z - dt * e1[2];
    float n2 = sqrtf(ux * ux + uy * uy + uz * uz) + 1e-6f;
    e2[0] = ux / n2; e2[1] = uy / n2; e2[2] = uz / n2;
    e3[0] = e1[1] * e2[2] - e1[2] * e2[1];
    e3[1] = e1[2] * e2[0] - e1[0] * e2[2];
    e3[2] = e1[0] * e2[1] - e1[1] * e2[0];
}

__device__ __forceinline__ float gelu_f(float x) {
    float c = 0.7978845608028654f * (x + 0.044715f * x * x * x);
    float t;
    asm("tanh.approx.f32 %0, %1;" : "=f"(t) : "f"(c));
    return 0.5f * x * (1.0f + t);
}

__global__ void __launch_bounds__(THREADS, 1)
dsd_kernel(const float* __restrict__ pos, const float* __restrict__ dmap,
           const int* __restrict__ nbrs, const int* __restrict__ resi,
           const int* __restrict__ chain, const int* __restrict__ batch,
           const float* __restrict__ maskp,
           const float* __restrict__ Wrel, const float* __restrict__ Wdmap,
           const float* __restrict__ Wdist, const float* __restrict__ Wdir,
           const float* __restrict__ Wrot, const float* __restrict__ Wvec,
           const float* __restrict__ lng, const float* __restrict__ lnb,
           const float* __restrict__ W1, const float* __restrict__ bias1,
           const float* __restrict__ W2, const float* __restrict__ bias2,
           float* __restrict__ outPair, float* __restrict__ outMask)
{
    extern __shared__ float sm[];
    const int tid = threadIdx.x;
    const int h   = tid >> 8;           // half id 0/1
    const int t   = tid & 255;          // thread within half
    const int w   = t >> 5;             // warp within half (0..7)
    const int k   = t & 31;
    const int mt  = w & 1;
    const int nt  = w >> 1;
    const int lkk = t >> 3;
    const int l8  = t & 7;

    __half* WDh = (__half*)(sm + OFF_WDH);
    __half* W1h = (__half*)(sm + OFF_W1H);
    __half* W2h = (__half*)(sm + OFF_W2H);

    float* Hf = sm + OFF_HALF0 + h * HALF_FL;
    int*   Hi = (int*)Hf;
    __half* FTh = (__half*)(Hf + R_FT);

    // ---- stage constant weights once (full block) ----
    for (int i = tid; i < KPAD * 64; i += THREADS) {
        int f = i >> 6, c = i & 63;
        float v;
        if (f < 400)      v = Wdist[f * 64 + c];
        else if (f < 416) v = Wdmap[(f - 400) * 64 + c];
        else if (f < 431) v = Wdir[(f - 416) * 64 + c];
        else if (f < 446) v = Wvec[(f - 431) * 64 + c];
        else if (f < 455) v = Wrot[(f - 446) * 64 + c];
        else              v = 0.0f;
        WDh[f * 72 + c] = __float2half(v);
    }
    for (int i = tid; i < 64 * 128; i += THREADS) {
        int p = i >> 7, hh = i & 127;
        W1h[p * 136 + hh] = __float2half(W1[i]);
    }
    for (int i = tid; i < 128 * 64; i += THREADS) {
        int j = i >> 6, c = i & 63;
        W2h[j * 72 + c] = __float2half(W2[i]);
    }
    // one-time zero of ALL 464 FT rows (cols 0..31) for both halves
    for (int i = tid; i < 2 * 464 * 4; i += THREADS) {
        int hh = i / 1856, r2 = i - hh * 1856;
        int r = r2 >> 2, q = r2 & 3;
        float* base = sm + OFF_HALF0 + hh * HALF_FL + R_FT;
        reinterpret_cast<float4*>(base + r * 20)[q] = make_float4(0.f, 0.f, 0.f, 0.f);
    }

    float lgr[8], lbr[8], b1r[8], b2r[4];
#pragma unroll
    for (int i = 0; i < 8; ++i) {
        lgr[i] = lng[l8 * 8 + i];
        lbr[i] = lnb[l8 * 8 + i];
    }
#pragma unroll
    for (int tq = 0; tq < 4; ++tq) {
        b1r[2 * tq + 0] = bias1[nt * 32 + tq * 8 + (k & 3) * 2 + 0];
        b1r[2 * tq + 1] = bias1[nt * 32 + tq * 8 + (k & 3) * 2 + 1];
    }
#pragma unroll
    for (int tq = 0; tq < 2; ++tq) {
        b2r[2 * tq + 0] = bias2[nt * 16 + tq * 8 + (k & 3) * 2 + 0];
        b2r[2 * tq + 1] = bias2[nt * 16 + tq * 8 + (k & 3) * 2 + 1];
    }

    // mma base addresses
    const u32 FTS  = (u32)__cvta_generic_to_shared(FTh);
    const u32 WDS  = (u32)__cvta_generic_to_shared(WDh);
    const u32 W1S_ = (u32)__cvta_generic_to_shared(W1h);
    const u32 W2S_ = (u32)__cvta_generic_to_shared(W2h);
    const u32 PhS  = (u32)__cvta_generic_to_shared(Hf + R_PH);
    const u32 HHS  = (u32)__cvta_generic_to_shared(Hf + R_HH);
    const u32 SMB  = (u32)__cvta_generic_to_shared(sm);
    const u32 aAddr0 = FTS + ((k & 7) + ((k >> 4) & 1) * 8) * 80 + (mt * 16 + ((k >> 3) & 1) * 8) * 2;
    const u32 bAddr0 = WDS + ((k & 7) + ((k >> 3) & 1) * 8) * 144 + (nt * 16 + ((k >> 4) & 1) * 8) * 2;
    const u32 aP0 = PhS + (mt * 16 + (k & 7) + ((k >> 3) & 1) * 8) * 144 + ((k >> 4) & 1) * 16;
    const u32 bW1 = W1S_ + ((k & 7) + ((k >> 3) & 1) * 8) * 272 + (nt * 32 + ((k >> 4) & 1) * 8) * 2;
    const u32 aH0 = HHS + (mt * 16 + (k & 7) + ((k >> 3) & 1) * 8) * 272 + ((k >> 4) & 1) * 16;
    const u32 bW2 = W2S_ + ((k & 7) + ((k >> 3) & 1) * 8) * 144 + (nt * 16 + ((k >> 4) & 1) * 8) * 2;

    const int stride2 = gridDim.x * 2;
    const int nBase = blockIdx.x * 2 + h;

    __syncthreads();   // weights + zeroed FT ready

    // ================= PROLOGUE (per half) =================
    {
        int n = nBase;
        if (t < 32) {
            int nb = nbrs[n * KC + t];
            int j = nb < 0 ? 0 : nb;
            float valid = (nb != -1) ? 1.0f : 0.0f;
            Hi[R_SJ + t] = j;
            int dr = resi[j] - resi[n];
            dr = dr < -32 ? -32 : (dr > 32 ? 32 : dr);
            Hi[R_SREL + t] = dr + 32;
            float same = (chain[j] == chain[n] && batch[j] == batch[n]) ? 1.0f : 0.0f;
            Hf[R_SSAME + t] = same;
            float pm = maskp[n] * maskp[j] * valid;
            Hf[R_SPM + t] = pm;
            outMask[n * KC + t] = pm;
        } else if (t == 32) {
            float e1[3], e2[3], e3[3], tt[3], prow[9];
#pragma unroll
            for (int i = 0; i < 9; ++i) prow[i] = pos[n * 15 + i];
            frames_from(prow, e1, e2, e3, tt);
#pragma unroll
            for (int r = 0; r < 3; ++r) {
                Hf[R_RN + r * 3 + 0] = e1[r];
                Hf[R_RN + r * 3 + 1] = e2[r];
                Hf[R_RN + r * 3 + 2] = e3[r];
            }
            Hf[R_RN + 9 + 0] = tt[0]; Hf[R_RN + 9 + 1] = tt[1]; Hf[R_RN + 9 + 2] = tt[2];
        } else if (t >= 48 && t < 63) {
            Hf[R_POSN + (t - 48)] = pos[n * 15 + (t - 48)];
        }
        BARH();
        for (int i = t; i < 480; i += 256) {
            int kk = i / 15, e = i - kk * 15;
            int j = Hi[R_SJ + kk];
            Hf[R_PJ + kk * 17 + e] = pos[(long)j * 15 + e];
        }
        if (t < 32) {
            int j = Hi[R_SJ + t];
            Hf[R_DM + t] = __ldg(&dmap[(long)n * Ntot + j]);
        }
        BARH();
    }

    int iter = 0;
    for (int n0 = nBase; n0 < Ntot; n0 += stride2, ++iter) {
        const int par  = iter & 1;
        const int parn = par ^ 1;
        const int nN   = n0 + stride2;
        const bool hasNext = (nN < Ntot);

        // ---------- P3: write nonzero features into pre-zeroed F^T ----------
        {
            __half* fT = FTh + k;
            const float* pn = Hf + R_POSN + par * 16;
            const float* pj = Hf + R_PJ + par * 544 + k * 17;
            const float* rn = Hf + R_RN + par * 12;
#pragma unroll
            for (int q = 0; q < 3; ++q) {
                int dp = q * 8 + w;
                int a = dp / 5, c5 = dp - a * 5;
                float dx = pn[a * 3 + 0] - pj[c5 * 3 + 0];
                float dy = pn[a * 3 + 1] - pj[c5 * 3 + 1];
                float dz = pn[a * 3 + 2] - pj[c5 * 3 + 2];
                float d = sqrtf(dx * dx + dy * dy + dz * dz);
                rbf16s(d, fT + (dp * 16) * 40);
            }
            if (w == 0) {   // dp 24
                float dx = pn[12] - pj[12];
                float dy = pn[13] - pj[13];
                float dz = pn[14] - pj[14];
                float d = sqrtf(dx * dx + dy * dy + dz * dz);
                rbf16s(d, fT + (24 * 16) * 40);
            } else if (w == 1) {   // dmap rbf; pm==0 -> bins stay zero
                float pm = Hf[R_SPM + par * 32 + k];
                if (pm > 0.0f) {
                    float dval = Hf[R_DM + par * 32 + k];
                    rbf16s(dval, fT + 400 * 40);
                }
            } else if (w < 7) {
                int a = w - 2;
                float v0 = pj[a * 3 + 0] - rn[9 + 0];
                float v1 = pj[a * 3 + 1] - rn[9 + 1];
                float v2 = pj[a * 3 + 2] - rn[9 + 2];
                float rv[3];
#pragma unroll
                for (int i = 0; i < 3; ++i)
                    rv[i] = rn[0 + i] * v0 + rn[3 + i] * v1 + rn[6 + i] * v2;
                float nr = sqrtf(rv[0] * rv[0] + rv[1] * rv[1] + rv[2] * rv[2]);
                float inv = 1.0f / (nr + 1e-6f);
#pragma unroll
                for (int i = 0; i < 3; ++i) {
                    fT[(416 + a * 3 + i) * 40] = __float2half(rv[i] * inv);
                    fT[(431 + a * 3 + i) * 40] = __float2half(rv[i] * 0.1f);
                }
            } else {
                float e1j[3], e2j[3], e3j[3], tj[3];
                frames_from(pj, e1j, e2j, e3j, tj);
#pragma unroll
                for (int i = 0; i < 3; ++i) {
                    float r0 = rn[0 + i], r1 = rn[3 + i], r2 = rn[6 + i];
                    fT[(446 + i * 3 + 0) * 40] = __float2half(r0 * e1j[0] + r1 * e1j[1] + r2 * e1j[2]);
                    fT[(446 + i * 3 + 1) * 40] = __float2half(r0 * e2j[0] + r1 * e2j[1] + r2 * e2j[2]);
                    fT[(446 + i * 3 + 2) * 40] = __float2half(r0 * e3j[0] + r1 * e3j[1] + r2 * e3j[2]);
                }
            }
        }
        BARH();

        // ---------- P4: Wrel prefetch + first-level prefetch + pipelined GEMM ----------
        float4 wrA0, wrA1;
        {
            int rel = Hi[R_SREL + par * 32 + lkk];
            wrA0 = __ldg(reinterpret_cast<const float4*>(Wrel) + rel * 16 + l8 * 2);
            wrA1 = __ldg(reinterpret_cast<const float4*>(Wrel) + rel * 16 + l8 * 2 + 1);
        }
        int nbv = -1;
        if (hasNext) {
            if (t < 32) {
                nbv = nbrs[(long)nN * KC + t];
            } else if (t >= 48 && t < 63) {
                CPA4(SMB + (u32)(Hf - sm + R_POSN + parn * 16 + (t - 48)) * 4,
                     pos + (long)nN * 15 + (t - 48));
            }
            CPA_COMMIT();
        }
        {
            float d0 = 0.f, d1 = 0.f, d2 = 0.f, d3 = 0.f;
            float d4 = 0.f, d5 = 0.f, d6 = 0.f, d7 = 0.f;
            u32 aA = aAddr0, bA = bAddr0;
            u32 xa0, xa1, xa2, xa3, xb0, xb1, xb2, xb3;
            u32 ya0, ya1, ya2, ya3, yb0, yb1, yb2, yb3;
            LDSM4T(xa0, xa1, xa2, xa3, aA);
            LDSM4T(xb0, xb1, xb2, xb3, bA);
#pragma unroll 1
            for (int s = 0; s < 14; ++s) {
                aA += 1280; bA += 2304;
                LDSM4T(ya0, ya1, ya2, ya3, aA);
                LDSM4T(yb0, yb1, yb2, yb3, bA);
                MMA16816(d0, d1, d2, d3, xa0, xa1, xa2, xa3, xb0, xb1);
                MMA16816(d4, d5, d6, d7, xa0, xa1, xa2, xa3, xb2, xb3);
                aA += 1280; bA += 2304;
                LDSM4T(xa0, xa1, xa2, xa3, aA);
                LDSM4T(xb0, xb1, xb2, xb3, bA);
                MMA16816(d0, d1, d2, d3, ya0, ya1, ya2, ya3, yb0, yb1);
                MMA16816(d4, d5, d6, d7, ya0, ya1, ya2, ya3, yb2, yb3);
            }
            MMA16816(d0, d1, d2, d3, xa0, xa1, xa2, xa3, xb0, xb1);
            MMA16816(d4, d5, d6, d7, xa0, xa1, xa2, xa3, xb2, xb3);

            float* P = Hf + R_P;
            int kk1 = mt * 16 + (k >> 2);
            int kk2 = kk1 + 8;
            int col = nt * 16 + (k & 3) * 2;
            *reinterpret_cast<float2*>(P + kk1 * 66 + col)     = make_float2(d0, d1);
            *reinterpret_cast<float2*>(P + kk2 * 66 + col)     = make_float2(d2, d3);
            *reinterpret_cast<float2*>(P + kk1 * 66 + col + 8) = make_float2(d4, d5);
            *reinterpret_cast<float2*>(P + kk2 * 66 + col + 8) = make_float2(d6, d7);
        }
        if (hasNext) {
            if (t < 32) {
                int j = nbv < 0 ? 0 : nbv;
                Hi[R_SJ + parn * 32 + t] = j;
            }
            CPA_WAIT0();
        }
        BARH();

        // ---------- P5: + Wrel, LayerNorm -> Ph ; frames for nN ----------
        if (hasNext && t == 0) {
            float e1[3], e2[3], e3[3], tt[3];
            frames_from(Hf + R_POSN + parn * 16, e1, e2, e3, tt);
#pragma unroll
            for (int r = 0; r < 3; ++r) {
                Hf[R_RN + parn * 12 + r * 3 + 0] = e1[r];
                Hf[R_RN + parn * 12 + r * 3 + 1] = e2[r];
                Hf[R_RN + parn * 12 + r * 3 + 2] = e3[r];
            }
            Hf[R_RN + parn * 12 + 9 + 0] = tt[0];
            Hf[R_RN + parn * 12 + 9 + 1] = tt[1];
            Hf[R_RN + parn * 12 + 9 + 2] = tt[2];
        }
        {
            const float* P = Hf + R_P + lkk * 66 + l8 * 8;
            float a0 = P[0], a1 = P[1], a2 = P[2], a3 = P[3];
            float a4 = P[4], a5 = P[5], a6 = P[6], a7 = P[7];
            {
                float same = Hf[R_SSAME + par * 32 + lkk];
                a0 = fmaf(same, wrA0.x, a0); a1 = fmaf(same, wrA0.y, a1);
                a2 = fmaf(same, wrA0.z, a2); a3 = fmaf(same, wrA0.w, a3);
                a4 = fmaf(same, wrA1.x, a4); a5 = fmaf(same, wrA1.y, a5);
                a6 = fmaf(same, wrA1.z, a6); a7 = fmaf(same, wrA1.w, a7);
            }
            float ssum = a0 + a1 + a2 + a3 + a4 + a5 + a6 + a7;
            ssum += __shfl_xor_sync(0xffffffffu, ssum, 4);
            ssum += __shfl_xor_sync(0xffffffffu, ssum, 2);
            ssum += __shfl_xor_sync(0xffffffffu, ssum, 1);
            float mu = ssum * 0.015625f;
            float e0 = a0 - mu, e1 = a1 - mu, e2 = a2 - mu, e3 = a3 - mu;
            float e4 = a4 - mu, e5 = a5 - mu, e6 = a6 - mu, e7 = a7 - mu;
            float sq = e0 * e0 + e1 * e1 + e2 * e2 + e3 * e3 + e4 * e4 + e5 * e5 + e6 * e6 + e7 * e7;
            sq += __shfl_xor_sync(0xffffffffu, sq, 4);
            sq += __shfl_xor_sync(0xffffffffu, sq, 2);
            sq += __shfl_xor_sync(0xffffffffu, sq, 1);
            float inv = rsqrtf(sq * 0.015625f + 1e-5f);
            __half2 q0 = __floats2half2_rn(lgr[0] * e0 * inv + lbr[0], lgr[1] * e1 * inv + lbr[1]);
            __half2 q1 = __floats2half2_rn(lgr[2] * e2 * inv + lbr[2], lgr[3] * e3 * inv + lbr[3]);
            __half2 q2 = __floats2half2_rn(lgr[4] * e4 * inv + lbr[4], lgr[5] * e5 * inv + lbr[5]);
            __half2 q3 = __floats2half2_rn(lgr[6] * e6 * inv + lbr[6], lgr[7] * e7 * inv + lbr[7]);
            uint4 pk;
            pk.x = *(u32*)&q0; pk.y = *(u32*)&q1; pk.z = *(u32*)&q2; pk.w = *(u32*)&q3;
            *reinterpret_cast<uint4*>((__half2*)(Hf + R_PH) + lkk * 36 + l8 * 4) = pk;
        }
        BARH();

        // ---------- P6: MLP1 mma + prefetch + FT re-zero (FT dead after P4) ----------
        int rjv = 0, rnv = 0, cjv = 0, cnv = 0, bjv = 0, bnv = 0;
        float mjv = 0.0f, mnv = 0.0f;
        if (hasNext) {
            {
                int kk = t / 15, e = t - kk * 15;
                if (kk < 32) {
                    int j = Hi[R_SJ + parn * 32 + kk];
                    CPA4(SMB + (u32)(Hf - sm + R_PJ + parn * 544 + kk * 17 + e) * 4,
                         pos + (long)j * 15 + e);
                }
            }
            if (t < 224) {
                int i1 = t + 256;
                int kk = i1 / 15, e = i1 - kk * 15;
                int j = Hi[R_SJ + parn * 32 + kk];
                CPA4(SMB + (u32)(Hf - sm + R_PJ + parn * 544 + kk * 17 + e) * 4,
                     pos + (long)j * 15 + e);
            }
            if (t < 32) {
                int j = Hi[R_SJ + parn * 32 + t];
                CPA4(SMB + (u32)(Hf - sm + R_DM + parn * 32 + t) * 4,
                     dmap + (long)nN * Ntot + j);
                rjv = resi[j]; rnv = resi[nN];
                cjv = chain[j]; cnv = chain[nN];
                bjv = batch[j]; bnv = batch[nN];
                mjv = maskp[j]; mnv = maskp[nN];
            }
            CPA_COMMIT();
        }
        // re-zero RBF region rows 0..415 cols 0..31 (coalesced st.128)
        if (hasNext) {
            for (int i = t; i < 416 * 4; i += 256) {
                int r = i >> 2, q = i & 3;
                reinterpret_cast<float4*>(Hf + R_FT + r * 20)[q] = make_float4(0.f, 0.f, 0.f, 0.f);
            }
        }
        {
            float c[16];
#pragma unroll
            for (int j = 0; j < 16; ++j) c[j] = 0.0f;
            u32 aA = aP0, bA = bW1;
#pragma unroll
            for (int s = 0; s < 4; ++s) {
                u32 ra0, ra1, ra2, ra3, rb0, rb1, rb2, rb3, rc0, rc1, rc2, rc3;
                LDSM4(ra0, ra1, ra2, ra3, aA);
                LDSM4T(rb0, rb1, rb2, rb3, bA);
                LDSM4T(rc0, rc1, rc2, rc3, bA + 32);
                aA += 32;
                bA += 4352;
                MMA16816(c[0],  c[1],  c[2],  c[3],  ra0, ra1, ra2, ra3, rb0, rb1);
                MMA16816(c[4],  c[5],  c[6],  c[7],  ra0, ra1, ra2, ra3, rb2, rb3);
                MMA16816(c[8],  c[9],  c[10], c[11], ra0, ra1, ra2, ra3, rc0, rc1);
                MMA16816(c[12], c[13], c[14], c[15], ra0, ra1, ra2, ra3, rc2, rc3);
            }
            __half2* hh2 = (__half2*)(Hf + R_HH);
            int r1 = mt * 16 + (k >> 2), r2 = r1 + 8;
#pragma unroll
            for (int tq = 0; tq < 4; ++tq) {
                float g0 = gelu_f(c[4 * tq + 0] + b1r[2 * tq + 0]);
                float g1 = gelu_f(c[4 * tq + 1] + b1r[2 * tq + 1]);
                float g2 = gelu_f(c[4 * tq + 2] + b1r[2 * tq + 0]);
                float g3 = gelu_f(c[4 * tq + 3] + b1r[2 * tq + 1]);
                int cw = nt * 16 + tq * 4 + (k & 3);
                hh2[r1 * 68 + cw] = __floats2half2_rn(g0, g1);
                hh2[r2 * 68 + cw] = __floats2half2_rn(g2, g3);
            }
        }
        if (hasNext) {
            if (t < 32) {
                int dr = rjv - rnv;
                dr = dr < -32 ? -32 : (dr > 32 ? 32 : dr);
                Hi[R_SREL + parn * 32 + t] = dr + 32;
                float same = (cjv == cnv && bjv == bnv) ? 1.0f : 0.0f;
                Hf[R_SSAME + parn * 32 + t] = same;
                float valid = (nbv != -1) ? 1.0f : 0.0f;
                float pm = mnv * mjv * valid;
                Hf[R_SPM + parn * 32 + t] = pm;
                outMask[(long)nN * KC + t] = pm;
            }
            CPA_WAIT0();
        }
        BARH();

        // ---------- P7: MLP2 mma + gmem write (no trailing barrier) ----------
        {
            float d0 = 0.f, d1 = 0.f, d2 = 0.f, d3 = 0.f;
            float d4 = 0.f, d5 = 0.f, d6 = 0.f, d7 = 0.f;
            u32 aA = aH0, bA = bW2;
#pragma unroll
            for (int s = 0; s < 8; ++s) {
                u32 ra0, ra1, ra2, ra3, rb0, rb1, rb2, rb3;
                LDSM4(ra0, ra1, ra2, ra3, aA);
                LDSM4T(rb0, rb1, rb2, rb3, bA);
                aA += 32;
                bA += 2304;
                MMA16816(d0, d1, d2, d3, ra0, ra1, ra2, ra3, rb0, rb1);
                MMA16816(d4, d5, d6, d7, ra0, ra1, ra2, ra3, rb2, rb3);
            }
            d0 += b2r[0]; d1 += b2r[1]; d2 += b2r[0]; d3 += b2r[1];
            d4 += b2r[2]; d5 += b2r[3]; d6 += b2r[2]; d7 += b2r[3];
            int r1 = mt * 16 + (k >> 2), r2 = r1 + 8;
            int col = nt * 16 + (k & 3) * 2;
            long i1 = ((long)n0 * KC + r1) * 64;
            long i2 = ((long)n0 * KC + r2) * 64;
            *reinterpret_cast<float2*>(outPair + i1 + col)     = make_float2(d0, d1);
            *reinterpret_cast<float2*>(outPair + i2 + col)     = make_float2(d2, d3);
            *reinterpret_cast<float2*>(outPair + i1 + col + 8) = make_float2(d4, d5);
            *reinterpret_cast<float2*>(outPair + i2 + col + 8) = make_float2(d6, d7);
        }
        // no trailing barrier: next P3 writes FT nonzero bins (sealed by post-P6 barrier)
    }
}

extern "C" void kernel_launch(void* const* d_in, const int* in_sizes, int n_in,
                              void* d_out, int out_size) {
    const float* pos   = (const float*)d_in[0];
    const float* dmap  = (const float*)d_in[1];
    const int*   nbrs  = (const int*)d_in[2];
    const int*   resi  = (const int*)d_in[3];
    const int*   chain = (const int*)d_in[4];
    const int*   batch = (const int*)d_in[5];
    const float* maskp = (const float*)d_in[6];
    const float* Wrel  = (const float*)d_in[7];
    const float* Wdmap = (const float*)d_in[8];
    const float* Wdist = (const float*)d_in[9];
    const float* Wdir  = (const float*)d_in[10];
    const float* Wrot  = (const float*)d_in[11];
    const float* Wvec  = (const float*)d_in[12];
    const float* lng   = (const float*)d_in[13];
    const float* lnb   = (const float*)d_in[14];
    const float* W1    = (const float*)d_in[15];
    const float* b1    = (const float*)d_in[16];
    const float* W2    = (const float*)d_in[17];
    const float* b2    = (const float*)d_in[18];

    float* outPair = (float*)d_out;
    float* outMask = outPair + (long)Ntot * KC * PC;

    cudaFuncSetAttribute(dsd_kernel, cudaFuncAttributeMaxDynamicSharedMemorySize, SMEMF * 4);
    int sms = 148;
    cudaDeviceGetAttribute(&sms, cudaDevAttrMultiProcessorCount, 0);

    dsd_kernel<<<sms, THREADS, SMEMF * 4>>>(
        pos, dmap, nbrs, resi, chain, batch, maskp,
        Wrel, Wdmap, Wdist, Wdir, Wrot, Wvec, lng, lnb, W1, b1, W2, b2,
        outPair, outMask);
}